// round 2
// baseline (speedup 1.0000x reference)
#include <cuda_runtime.h>
#include <math.h>

// ---- fixed problem shapes ----
#define NTOK 4096      // B*T
#define TSEQ 2048
#define NB   2
#define CDIM 1024
#define NH   16
#define HD   64
#define FF   4096
#define NE   8
#define EPS  1e-5f
#define SCALE 0.03125f // C^-0.5 = 1/32

// ---- scratch (device globals: allocation-free) ----
__device__ float g_qkv[3 * NH * NTOK * HD];   // [mat][head][tok][d]
__device__ float g_attn[NTOK * CDIM];         // head-concat attention out
__device__ float g_proj[NTOK * CDIM];
__device__ float g_x1[NTOK * CDIM];
__device__ float g_h[2 * NTOK * FF];          // 8192 expert-slot rows x FF
__device__ float g_eo[2 * NTOK * CDIM];       // 8192 expert-slot rows x C
__device__ int   g_counts[NE];
__device__ int   g_base[NE];
__device__ int   g_list[NE * NTOK];           // list-local -> token
__device__ float g_gate[NE * NTOK];
__device__ int   g_slot[NTOK * 2];            // token -> e*NTOK + list-local

// ============================================================
// reset expert counters
// ============================================================
__global__ void k_zero() {
    if (threadIdx.x < NE) g_counts[threadIdx.x] = 0;
}

// ============================================================
// QKV projection: per (mat,head) GEMM  x[4096,1024] @ W[1024,64]
// grid (64, 1, 48), block 256
// ============================================================
__global__ void k_qkv(const float* __restrict__ x,
                      const float* __restrict__ Wq,
                      const float* __restrict__ Wk,
                      const float* __restrict__ Wv) {
    __shared__ __align__(16) float As[16][68];
    __shared__ __align__(16) float Bs[16][68];
    int z = blockIdx.z;
    int mat = z / NH, head = z % NH;
    const float* W = (mat == 0 ? Wq : (mat == 1 ? Wk : Wv)) + head * CDIM * HD;
    float* out = g_qkv + z * NTOK * HD;
    int m0 = blockIdx.x * 64;
    int tid = threadIdx.x, tx = tid & 15, ty = tid >> 4;
    float acc[4][4] = {};
    for (int k0 = 0; k0 < CDIM; k0 += 16) {
        #pragma unroll
        for (int r = 0; r < 4; r++) {
            int idx = tid + r * 256;
            int kk = idx & 15, m = idx >> 4;
            As[kk][m] = x[(m0 + m) * CDIM + k0 + kk];
        }
        #pragma unroll
        for (int r = 0; r < 4; r++) {
            int idx = tid + r * 256;
            int n = idx & 63, kk = idx >> 6;
            Bs[kk][n] = W[(k0 + kk) * HD + n];
        }
        __syncthreads();
        #pragma unroll
        for (int kk = 0; kk < 16; kk++) {
            float4 a = *(const float4*)&As[kk][ty * 4];
            float4 b = *(const float4*)&Bs[kk][tx * 4];
            float av[4] = {a.x, a.y, a.z, a.w};
            float bv[4] = {b.x, b.y, b.z, b.w};
            #pragma unroll
            for (int i = 0; i < 4; i++)
                #pragma unroll
                for (int j = 0; j < 4; j++) acc[i][j] += av[i] * bv[j];
        }
        __syncthreads();
    }
    #pragma unroll
    for (int i = 0; i < 4; i++)
        #pragma unroll
        for (int j = 0; j < 4; j++)
            out[(m0 + ty * 4 + i) * HD + tx * 4 + j] = acc[i][j];
}

// ============================================================
// causal flash attention: 1 thread = 1 query row
// grid (16, 32), block 128
// ============================================================
__global__ void k_attn() {
    int bh = blockIdx.y;
    int b = bh / NH, h = bh % NH;
    const float* Q = g_qkv + (0 * NH + h) * NTOK * HD;
    const float* K = g_qkv + (1 * NH + h) * NTOK * HD;
    const float* V = g_qkv + (2 * NH + h) * NTOK * HD;
    int tl = blockIdx.x * 128 + threadIdx.x;   // local seq position
    int tok = b * TSEQ + tl;

    float q[HD];
    #pragma unroll
    for (int d = 0; d < HD; d++) q[d] = Q[tok * HD + d] * SCALE;
    float o[HD];
    #pragma unroll
    for (int d = 0; d < HD; d++) o[d] = 0.f;
    float m = -1e30f, l = 0.f;

    __shared__ __align__(16) float Ks[32][HD];
    __shared__ __align__(16) float Vs[32][HD];

    int kmax = blockIdx.x * 128 + 127;
    for (int kb = 0; kb <= kmax; kb += 32) {
        for (int i = threadIdx.x; i < 32 * 16; i += 128) {
            int s = i >> 4, dv = i & 15;
            ((float4*)&Ks[s][0])[dv] = ((const float4*)&K[(b * TSEQ + kb + s) * HD])[dv];
            ((float4*)&Vs[s][0])[dv] = ((const float4*)&V[(b * TSEQ + kb + s) * HD])[dv];
        }
        __syncthreads();
        float sc[32];
        #pragma unroll
        for (int s = 0; s < 32; s++) {
            float d0 = 0.f;
            #pragma unroll
            for (int d = 0; d < HD; d++) d0 += q[d] * Ks[s][d];
            sc[s] = (kb + s <= tl) ? d0 : -1e30f;
        }
        float mn = m;
        #pragma unroll
        for (int s = 0; s < 32; s++) mn = fmaxf(mn, sc[s]);
        float corr = __expf(m - mn);
        l *= corr;
        #pragma unroll
        for (int d = 0; d < HD; d++) o[d] *= corr;
        #pragma unroll
        for (int s = 0; s < 32; s++) {
            float p = __expf(sc[s] - mn);
            l += p;
            #pragma unroll
            for (int d = 0; d < HD; d++) o[d] += p * Vs[s][d];
        }
        m = mn;
        __syncthreads();
    }
    float inv = 1.f / l;
    #pragma unroll
    for (int d = 0; d < HD; d++)
        g_attn[tok * CDIM + h * HD + d] = o[d] * inv;
}

// ============================================================
// output projection: g_attn[4096,1024] @ Wo[1024,1024] + bo
// grid (64, 16), block 256
// ============================================================
__global__ void k_proj(const float* __restrict__ Wo, const float* __restrict__ bo) {
    __shared__ __align__(16) float As[16][68];
    __shared__ __align__(16) float Bs[16][68];
    int m0 = blockIdx.x * 64, n0 = blockIdx.y * 64;
    int tid = threadIdx.x, tx = tid & 15, ty = tid >> 4;
    float acc[4][4] = {};
    for (int k0 = 0; k0 < CDIM; k0 += 16) {
        #pragma unroll
        for (int r = 0; r < 4; r++) {
            int idx = tid + r * 256;
            int kk = idx & 15, m = idx >> 4;
            As[kk][m] = g_attn[(m0 + m) * CDIM + k0 + kk];
        }
        #pragma unroll
        for (int r = 0; r < 4; r++) {
            int idx = tid + r * 256;
            int n = idx & 63, kk = idx >> 6;
            Bs[kk][n] = Wo[(k0 + kk) * CDIM + n0 + n];
        }
        __syncthreads();
        #pragma unroll
        for (int kk = 0; kk < 16; kk++) {
            float4 a = *(const float4*)&As[kk][ty * 4];
            float4 b = *(const float4*)&Bs[kk][tx * 4];
            float av[4] = {a.x, a.y, a.z, a.w};
            float bv[4] = {b.x, b.y, b.z, b.w};
            #pragma unroll
            for (int i = 0; i < 4; i++)
                #pragma unroll
                for (int j = 0; j < 4; j++) acc[i][j] += av[i] * bv[j];
        }
        __syncthreads();
    }
    #pragma unroll
    for (int i = 0; i < 4; i++)
        #pragma unroll
        for (int j = 0; j < 4; j++)
            g_proj[(m0 + ty * 4 + i) * CDIM + n0 + tx * 4 + j] =
                acc[i][j] + bo[n0 + tx * 4 + j];
}

// ============================================================
// LN1 + residual: x1 = x + ln(proj)
// grid 4096, block 256
// ============================================================
__global__ void k_ln1(const float* __restrict__ x,
                      const float* __restrict__ g, const float* __restrict__ bsh) {
    int t = blockIdx.x, tid = threadIdx.x;
    __shared__ float rs[256], rss[256];
    float s = 0.f, ss = 0.f;
    for (int c = tid; c < CDIM; c += 256) {
        float v = g_proj[t * CDIM + c];
        s += v; ss += v * v;
    }
    rs[tid] = s; rss[tid] = ss;
    __syncthreads();
    for (int off = 128; off > 0; off >>= 1) {
        if (tid < off) { rs[tid] += rs[tid + off]; rss[tid] += rss[tid + off]; }
        __syncthreads();
    }
    float mean = rs[0] * (1.f / CDIM);
    float var = rss[0] * (1.f / CDIM) - mean * mean;
    float rstd = rsqrtf(var + EPS);
    for (int c = tid; c < CDIM; c += 256) {
        float v = (g_proj[t * CDIM + c] - mean) * rstd * g[c] + bsh[c];
        g_x1[t * CDIM + c] = x[t * CDIM + c] + v;
    }
}

// ============================================================
// noisy top-2 router + expert-list build
// grid 4096, block 128
// ============================================================
__global__ void k_router(const float* __restrict__ Wr, const float* __restrict__ br,
                         const float* __restrict__ Wn, const float* __restrict__ bn,
                         const float* __restrict__ noise) {
    int t = blockIdx.x, tid = threadIdx.x;
    float ar[NE], an[NE];
    #pragma unroll
    for (int e = 0; e < NE; e++) { ar[e] = 0.f; an[e] = 0.f; }
    for (int c = tid; c < CDIM; c += 128) {
        float xv = g_x1[t * CDIM + c];
        const float4* wr4 = (const float4*)&Wr[c * NE];
        const float4* wn4 = (const float4*)&Wn[c * NE];
        float4 r0 = wr4[0], r1 = wr4[1];
        float4 n0 = wn4[0], n1 = wn4[1];
        ar[0] += xv * r0.x; ar[1] += xv * r0.y; ar[2] += xv * r0.z; ar[3] += xv * r0.w;
        ar[4] += xv * r1.x; ar[5] += xv * r1.y; ar[6] += xv * r1.z; ar[7] += xv * r1.w;
        an[0] += xv * n0.x; an[1] += xv * n0.y; an[2] += xv * n0.z; an[3] += xv * n0.w;
        an[4] += xv * n1.x; an[5] += xv * n1.y; an[6] += xv * n1.z; an[7] += xv * n1.w;
    }
    __shared__ float red[16 * 128];
    #pragma unroll
    for (int e = 0; e < NE; e++) {
        red[e * 128 + tid] = ar[e];
        red[(e + 8) * 128 + tid] = an[e];
    }
    __syncthreads();
    __shared__ float res[16];
    if (tid < 16) {
        float s = 0.f;
        for (int i = 0; i < 128; i++) s += red[tid * 128 + i];
        res[tid] = s;
    }
    __syncthreads();
    if (tid == 0) {
        float noisy[NE];
        #pragma unroll
        for (int e = 0; e < NE; e++) {
            float lg = res[e] + br[e];
            float nl = res[e + 8] + bn[e];
            // softplus with overflow guard
            float sp = (nl > 20.f) ? nl : log1pf(expf(nl));
            noisy[e] = lg + noise[t * NE + e] * sp;
        }
        int i0 = 0; float v0 = noisy[0];
        #pragma unroll
        for (int e = 1; e < NE; e++) if (noisy[e] > v0) { v0 = noisy[e]; i0 = e; }
        int i1 = -1; float v1 = -1e30f;
        #pragma unroll
        for (int e = 0; e < NE; e++)
            if (e != i0 && noisy[e] > v1) { v1 = noisy[e]; i1 = e; }
        float e1 = expf(v1 - v0);
        float denom = 1.f + e1;
        float gate0 = 1.f / denom, gate1 = e1 / denom;
        int s0 = atomicAdd(&g_counts[i0], 1);
        g_list[i0 * NTOK + s0] = t; g_gate[i0 * NTOK + s0] = gate0;
        g_slot[t * 2 + 0] = i0 * NTOK + s0;
        int s1 = atomicAdd(&g_counts[i1], 1);
        g_list[i1 * NTOK + s1] = t; g_gate[i1 * NTOK + s1] = gate1;
        g_slot[t * 2 + 1] = i1 * NTOK + s1;
    }
}

__global__ void k_prefix() {
    if (threadIdx.x == 0 && blockIdx.x == 0) {
        int s = 0;
        for (int e = 0; e < NE; e++) { g_base[e] = s; s += g_counts[e]; }
    }
}

// ============================================================
// MoE GEMM1 + bias + exact GELU: h = gelu(x1_gathered @ W1[e] + b1[e])
// grid (64, 64, 8), block 256
// ============================================================
__global__ void k_moe1(const float* __restrict__ W1, const float* __restrict__ b1) {
    int e = blockIdx.z;
    int cnt = g_counts[e];
    int m0 = blockIdx.x * 64;
    if (m0 >= cnt) return;
    int n0 = blockIdx.y * 64;
    const float* B = W1 + (size_t)e * CDIM * FF;
    const float* bias = b1 + e * FF;
    int base = g_base[e];

    __shared__ __align__(16) float As[16][68];
    __shared__ __align__(16) float Bs[16][68];
    __shared__ int rows[64];
    int tid = threadIdx.x, tx = tid & 15, ty = tid >> 4;
    if (tid < 64) {
        int r = m0 + tid; if (r >= cnt) r = cnt - 1;
        rows[tid] = g_list[e * NTOK + r];
    }
    __syncthreads();
    float acc[4][4] = {};
    for (int k0 = 0; k0 < CDIM; k0 += 16) {
        #pragma unroll
        for (int r = 0; r < 4; r++) {
            int idx = tid + r * 256;
            int kk = idx & 15, m = idx >> 4;
            As[kk][m] = g_x1[rows[m] * CDIM + k0 + kk];
        }
        #pragma unroll
        for (int r = 0; r < 4; r++) {
            int idx = tid + r * 256;
            int n = idx & 63, kk = idx >> 6;
            Bs[kk][n] = B[(size_t)(k0 + kk) * FF + n0 + n];
        }
        __syncthreads();
        #pragma unroll
        for (int kk = 0; kk < 16; kk++) {
            float4 a = *(const float4*)&As[kk][ty * 4];
            float4 b = *(const float4*)&Bs[kk][tx * 4];
            float av[4] = {a.x, a.y, a.z, a.w};
            float bv[4] = {b.x, b.y, b.z, b.w};
            #pragma unroll
            for (int i = 0; i < 4; i++)
                #pragma unroll
                for (int j = 0; j < 4; j++) acc[i][j] += av[i] * bv[j];
        }
        __syncthreads();
    }
    #pragma unroll
    for (int i = 0; i < 4; i++) {
        int r = m0 + ty * 4 + i;
        if (r < cnt) {
            #pragma unroll
            for (int j = 0; j < 4; j++) {
                int n = n0 + tx * 4 + j;
                float v = acc[i][j] + bias[n];
                v = 0.5f * v * (1.0f + erff(v * 0.70710678118654752f));
                g_h[(size_t)(base + r) * FF + n] = v;
            }
        }
    }
}

// ============================================================
// MoE GEMM2 + bias + gate-scale: g_eo[base+r] = gate*(h @ W2[e] + b2[e])
// grid (64, 16, 8), block 256  — no atomics, slot-indexed
// ============================================================
__global__ void k_moe2(const float* __restrict__ W2, const float* __restrict__ b2) {
    int e = blockIdx.z;
    int cnt = g_counts[e];
    int m0 = blockIdx.x * 64;
    if (m0 >= cnt) return;
    int n0 = blockIdx.y * 64;
    const float* B = W2 + (size_t)e * FF * CDIM;
    const float* bias = b2 + e * CDIM;
    int base = g_base[e];

    __shared__ __align__(16) float As[16][68];
    __shared__ __align__(16) float Bs[16][68];
    int tid = threadIdx.x, tx = tid & 15, ty = tid >> 4;
    float acc[4][4] = {};
    for (int k0 = 0; k0 < FF; k0 += 16) {
        #pragma unroll
        for (int r = 0; r < 4; r++) {
            int idx = tid + r * 256;
            int kk = idx & 15, m = idx >> 4;
            int rr = m0 + m; if (rr >= cnt) rr = cnt - 1;
            As[kk][m] = g_h[(size_t)(base + rr) * FF + k0 + kk];
        }
        #pragma unroll
        for (int r = 0; r < 4; r++) {
            int idx = tid + r * 256;
            int n = idx & 63, kk = idx >> 6;
            Bs[kk][n] = B[(size_t)(k0 + kk) * CDIM + n0 + n];
        }
        __syncthreads();
        #pragma unroll
        for (int kk = 0; kk < 16; kk++) {
            float4 a = *(const float4*)&As[kk][ty * 4];
            float4 b = *(const float4*)&Bs[kk][tx * 4];
            float av[4] = {a.x, a.y, a.z, a.w};
            float bv[4] = {b.x, b.y, b.z, b.w};
            #pragma unroll
            for (int i = 0; i < 4; i++)
                #pragma unroll
                for (int j = 0; j < 4; j++) acc[i][j] += av[i] * bv[j];
        }
        __syncthreads();
    }
    #pragma unroll
    for (int i = 0; i < 4; i++) {
        int r = m0 + ty * 4 + i;
        if (r < cnt) {
            float gate = g_gate[e * NTOK + r];
            #pragma unroll
            for (int j = 0; j < 4; j++) {
                int n = n0 + tx * 4 + j;
                g_eo[(size_t)(base + r) * CDIM + n] = (acc[i][j] + bias[n]) * gate;
            }
        }
    }
}

// ============================================================
// combine 2 expert rows + LN2 + residual: out = x1 + ln(eo0 + eo1)
// grid 4096, block 256
// ============================================================
__global__ void k_out(const float* __restrict__ g, const float* __restrict__ bsh,
                      float* __restrict__ out) {
    int t = blockIdx.x, tid = threadIdx.x;
    __shared__ int srow[2];
    if (tid < 2) {
        int slot = g_slot[t * 2 + tid];
        int e = slot / NTOK, r = slot % NTOK;
        srow[tid] = g_base[e] + r;
    }
    __syncthreads();
    const float* eo0 = g_eo + (size_t)srow[0] * CDIM;
    const float* eo1 = g_eo + (size_t)srow[1] * CDIM;

    __shared__ float rs[256], rss[256];
    float s = 0.f, ss = 0.f;
    for (int c = tid; c < CDIM; c += 256) {
        float v = eo0[c] + eo1[c];
        s += v; ss += v * v;
    }
    rs[tid] = s; rss[tid] = ss;
    __syncthreads();
    for (int off = 128; off > 0; off >>= 1) {
        if (tid < off) { rs[tid] += rs[tid + off]; rss[tid] += rss[tid + off]; }
        __syncthreads();
    }
    float mean = rs[0] * (1.f / CDIM);
    float var = rss[0] * (1.f / CDIM) - mean * mean;
    float rstd = rsqrtf(var + EPS);
    for (int c = tid; c < CDIM; c += 256) {
        float v = ((eo0[c] + eo1[c]) - mean) * rstd * g[c] + bsh[c];
        out[t * CDIM + c] = g_x1[t * CDIM + c] + v;
    }
}

// ============================================================
extern "C" void kernel_launch(void* const* d_in, const int* in_sizes, int n_in,
                              void* d_out, int out_size) {
    const float* x     = (const float*)d_in[0];
    const float* Wq    = (const float*)d_in[1];
    const float* Wk    = (const float*)d_in[2];
    const float* Wv    = (const float*)d_in[3];
    const float* Wo    = (const float*)d_in[4];
    const float* bo    = (const float*)d_in[5];
    const float* ln1_g = (const float*)d_in[6];
    const float* ln1_b = (const float*)d_in[7];
    const float* Wr    = (const float*)d_in[8];
    const float* br    = (const float*)d_in[9];
    const float* Wn    = (const float*)d_in[10];
    const float* bn    = (const float*)d_in[11];
    const float* W1    = (const float*)d_in[12];
    const float* b1    = (const float*)d_in[13];
    const float* W2    = (const float*)d_in[14];
    const float* b2    = (const float*)d_in[15];
    const float* ln2_g = (const float*)d_in[16];
    const float* ln2_b = (const float*)d_in[17];
    const float* noise = (const float*)d_in[18];
    float* out = (float*)d_out;

    k_zero<<<1, 32>>>();
    k_qkv<<<dim3(NTOK / 64, 1, 48), 256>>>(x, Wq, Wk, Wv);
    k_attn<<<dim3(TSEQ / 128, NB * NH), 128>>>();
    k_proj<<<dim3(NTOK / 64, CDIM / 64), 256>>>(Wo, bo);
    k_ln1<<<NTOK, 256>>>(x, ln1_g, ln1_b);
    k_router<<<NTOK, 128>>>(Wr, br, Wn, bn, noise);
    k_prefix<<<1, 1>>>();
    k_moe1<<<dim3(NTOK / 64, FF / 64, NE), 256>>>(W1, b1);
    k_moe2<<<dim3(NTOK / 64, CDIM / 64, NE), 256>>>(W2, b2);
    k_out<<<NTOK, 256>>>(ln2_g, ln2_b, out);
}

// round 8
// speedup vs baseline: 1.3078x; 1.3078x over previous
#include <cuda_runtime.h>
#include <cuda_bf16.h>
#include <math.h>
#include <stdint.h>

// ---- fixed problem shapes ----
#define NTOK 4096      // B*T
#define TSEQ 2048
#define NB   2
#define CDIM 1024
#define NH   16
#define HD   64
#define FF   4096
#define NE   8
#define EPS  1e-5f
#define SCALE 0.03125f // C^-0.5 = 1/32

// ============================================================
// scratch (device globals: allocation-free)
// ============================================================
__device__ __align__(128) float g_qkv[3 * NH * NTOK * HD];   // fp32 for attention
__device__ __align__(128) float g_proj[NTOK * CDIM];
__device__ __align__(128) float g_x1[NTOK * CDIM];
__device__ __align__(128) float g_eo[2 * NTOK * CDIM];
__device__ int   g_counts[NE];
__device__ int   g_base[NE];
__device__ int   g_list[NE * NTOK];
__device__ float g_gate[NE * NTOK];
__device__ int   g_slot[NTOK * 2];

// bf16 hi/lo activation scratch (K-major rows)
__device__ __align__(128) __nv_bfloat16 g_xh[NTOK * CDIM];
__device__ __align__(128) __nv_bfloat16 g_xl[NTOK * CDIM];
__device__ __align__(128) __nv_bfloat16 g_attnh[NTOK * CDIM];
__device__ __align__(128) __nv_bfloat16 g_attnl[NTOK * CDIM];
__device__ __align__(128) __nv_bfloat16 g_x1h[NTOK * CDIM];
__device__ __align__(128) __nv_bfloat16 g_x1l[NTOK * CDIM];
__device__ __align__(128) __nv_bfloat16 g_hh[2 * NTOK * FF];
__device__ __align__(128) __nv_bfloat16 g_hl[2 * NTOK * FF];

// bf16 hi/lo transposed weights (B^T: [N rows][K cols], K-major)
__device__ __align__(128) __nv_bfloat16 g_Wqkvh[3 * CDIM * CDIM];  // [3072][1024]
__device__ __align__(128) __nv_bfloat16 g_Wqkvl[3 * CDIM * CDIM];
__device__ __align__(128) __nv_bfloat16 g_Woh[CDIM * CDIM];        // [1024][1024]
__device__ __align__(128) __nv_bfloat16 g_Wol[CDIM * CDIM];
__device__ __align__(128) __nv_bfloat16 g_W1h[NE * FF * CDIM];     // [e][4096][1024]
__device__ __align__(128) __nv_bfloat16 g_W1l[NE * FF * CDIM];
__device__ __align__(128) __nv_bfloat16 g_W2h[NE * CDIM * FF];     // [e][1024][4096]
__device__ __align__(128) __nv_bfloat16 g_W2l[NE * CDIM * FF];

// ============================================================
// small kernels
// ============================================================
__global__ void k_zero() {
    if (threadIdx.x < NE) g_counts[threadIdx.x] = 0;
}

// x -> hi/lo bf16 split (elementwise)
__global__ void k_splitx(const float* __restrict__ x) {
    int n = NTOK * CDIM;
    for (int i = blockIdx.x * blockDim.x + threadIdx.x; i < n;
         i += gridDim.x * blockDim.x) {
        float v = x[i];
        __nv_bfloat16 hi = __float2bfloat16(v);
        g_xh[i] = hi;
        g_xl[i] = __float2bfloat16(v - __bfloat162float(hi));
    }
}

// transpose + split: src [z][K][N] fp32 -> dst [z][N][K] bf16 hi/lo
// block (32,8), grid (K/32, N/32, z)
__global__ void k_split_t(const float* __restrict__ src, int K, int N,
                          long long szs, long long dzs, int sel) {
    __nv_bfloat16 *dh, *dl;
    switch (sel) {
        case 0: dh = g_Wqkvh;                 dl = g_Wqkvl;                 break;
        case 1: dh = g_Wqkvh + CDIM * CDIM;   dl = g_Wqkvl + CDIM * CDIM;   break;
        case 2: dh = g_Wqkvh + 2 * CDIM * CDIM; dl = g_Wqkvl + 2 * CDIM * CDIM; break;
        case 3: dh = g_Woh;                   dl = g_Wol;                   break;
        case 4: dh = g_W1h;                   dl = g_W1l;                   break;
        default: dh = g_W2h;                  dl = g_W2l;                   break;
    }
    long long z = blockIdx.z;
    src += z * szs; dh += z * dzs; dl += z * dzs;
    __shared__ float t[32][33];
    int k0 = blockIdx.x * 32, n0 = blockIdx.y * 32;
    int tx = threadIdx.x, ty = threadIdx.y;
    #pragma unroll
    for (int r = 0; r < 4; r++) {
        int k = k0 + ty + r * 8;
        t[ty + r * 8][tx] = src[(size_t)k * N + n0 + tx];
    }
    __syncthreads();
    #pragma unroll
    for (int r = 0; r < 4; r++) {
        int nl = ty + r * 8;
        float v = t[tx][nl];
        __nv_bfloat16 hi = __float2bfloat16(v);
        size_t o = (size_t)(n0 + nl) * K + k0 + tx;
        dh[o] = hi;
        dl[o] = __float2bfloat16(v - __bfloat162float(hi));
    }
}

// ============================================================
// unified bf16 split-GEMM via mma.sync (m16n8k16, HMMA path)
// block tile 128x128, BK=64, 8 warps (2x4), warp tile 64x32
// 3-term hi/lo expansion accumulated in fp32 registers
// mode 0: qkv    A=g_xh/l    B=Wqkvt  K=1024  out: g_qkv (scatter)
// mode 1: proj   A=g_attnh/l B=Wot    K=1024  out: g_proj (+bo)
// mode 2: moe1   A=x1h/l (gather) B=W1t[e] K=1024  out: g_hh/g_hl (gelu)
// mode 3: moe2   A=g_hh/l    B=W2t[e] K=4096  out: g_eo (gate)
// ============================================================
#define SMSTR 72   // bf16 elements per smem row (64 + 8 pad)

__device__ __forceinline__ void mma16816(float* c, const uint32_t* a, const uint32_t* b) {
    asm volatile(
        "mma.sync.aligned.m16n8k16.row.col.f32.bf16.bf16.f32 "
        "{%0,%1,%2,%3}, {%4,%5,%6,%7}, {%8,%9}, {%0,%1,%2,%3};"
        : "+f"(c[0]), "+f"(c[1]), "+f"(c[2]), "+f"(c[3])
        : "r"(a[0]), "r"(a[1]), "r"(a[2]), "r"(a[3]), "r"(b[0]), "r"(b[1]));
}

__global__ void __launch_bounds__(256, 1)
k_gemm(int mode, const float* __restrict__ bias) {
    __shared__ __align__(16) __nv_bfloat16 As[128 * SMSTR];
    __shared__ __align__(16) __nv_bfloat16 Bs[128 * SMSTR];
    __shared__ int rows[128];

    int tid = threadIdx.x;
    int lane = tid & 31, wid = tid >> 5;
    int wm = (wid >> 2) * 64;       // warp m offset within tile
    int wn = (wid & 3) * 32;        // warp n offset
    int qr = lane >> 2;             // 0..7
    int qc = (lane & 3) * 2;        // 0,2,4,6
    int e = blockIdx.z;
    int m0 = blockIdx.x * 128, n0 = blockIdx.y * 128;

    // per-mode config
    const __nv_bfloat16 *Ahp, *Alp, *Bhp, *Blp;
    int lda, K;
    int cnt = 0, base = 0;
    if (mode == 0) {
        Ahp = g_xh; Alp = g_xl; Bhp = g_Wqkvh; Blp = g_Wqkvl;
        lda = CDIM; K = CDIM;
    } else if (mode == 1) {
        Ahp = g_attnh; Alp = g_attnl; Bhp = g_Woh; Blp = g_Wol;
        lda = CDIM; K = CDIM;
    } else if (mode == 2) {
        cnt = g_counts[e]; base = g_base[e];
        if (m0 >= cnt) return;
        Ahp = g_x1h; Alp = g_x1l;
        Bhp = g_W1h + (size_t)e * FF * CDIM; Blp = g_W1l + (size_t)e * FF * CDIM;
        lda = CDIM; K = CDIM;
    } else {
        cnt = g_counts[e]; base = g_base[e];
        if (m0 >= cnt) return;
        Ahp = g_hh; Alp = g_hl;
        Bhp = g_W2h + (size_t)e * CDIM * FF; Blp = g_W2l + (size_t)e * CDIM * FF;
        lda = FF; K = FF;
    }

    // A row map
    if (tid < 128) {
        if (mode == 2) {
            int r = m0 + tid; if (r >= cnt) r = cnt - 1;
            rows[tid] = g_list[e * NTOK + r];
        } else if (mode == 3) {
            int r = m0 + tid; if (r >= cnt) r = cnt - 1;
            rows[tid] = base + r;
        } else {
            rows[tid] = m0 + tid;
        }
    }
    __syncthreads();

    float acc[4][4][4];
    #pragma unroll
    for (int im = 0; im < 4; im++)
        #pragma unroll
        for (int in_ = 0; in_ < 4; in_++)
            #pragma unroll
            for (int q = 0; q < 4; q++) acc[im][in_][q] = 0.f;

    const int KSTEPS = K >> 6;          // BK=64 tiles per term
    const int NST = 3 * KSTEPS;
    int lr = tid >> 1, lh = (tid & 1) * 32;   // gmem->smem: 2 threads/row, 32 bf16 each

    for (int kc = 0; kc < NST; kc++) {
        int t = kc >= KSTEPS ? (kc >= 2 * KSTEPS ? 2 : 1) : 0;
        int k0 = (kc - t * KSTEPS) << 6;
        const __nv_bfloat16* Asrc = (t == 2) ? Alp : Ahp;
        const __nv_bfloat16* Bsrc = (t == 1) ? Blp : Bhp;

        // load A tile: 128 rows x 64 bf16
        {
            const float4* ga = (const float4*)(Asrc + (size_t)rows[lr] * lda + k0 + lh);
            float4 a0 = ga[0], a1 = ga[1], a2 = ga[2], a3 = ga[3];
            float4* sa = (float4*)&As[lr * SMSTR + lh];
            sa[0] = a0; sa[1] = a1; sa[2] = a2; sa[3] = a3;
            const float4* gb = (const float4*)(Bsrc + (size_t)(n0 + lr) * lda + k0 + lh);
            float4 b0 = gb[0], b1 = gb[1], b2 = gb[2], b3 = gb[3];
            float4* sb = (float4*)&Bs[lr * SMSTR + lh];
            sb[0] = b0; sb[1] = b1; sb[2] = b2; sb[3] = b3;
        }
        __syncthreads();

        #pragma unroll
        for (int ks = 0; ks < 4; ks++) {
            int kb = ks * 16;
            uint32_t af[4][4], bf[4][2];
            #pragma unroll
            for (int im = 0; im < 4; im++) {
                const __nv_bfloat16* ap = &As[(wm + im * 16 + qr) * SMSTR + kb + qc];
                af[im][0] = *(const uint32_t*)ap;
                af[im][1] = *(const uint32_t*)(ap + 8 * SMSTR);
                af[im][2] = *(const uint32_t*)(ap + 8);
                af[im][3] = *(const uint32_t*)(ap + 8 * SMSTR + 8);
            }
            #pragma unroll
            for (int in_ = 0; in_ < 4; in_++) {
                const __nv_bfloat16* bp = &Bs[(wn + in_ * 8 + qr) * SMSTR + kb + qc];
                bf[in_][0] = *(const uint32_t*)bp;
                bf[in_][1] = *(const uint32_t*)(bp + 8);
            }
            #pragma unroll
            for (int im = 0; im < 4; im++)
                #pragma unroll
                for (int in_ = 0; in_ < 4; in_++)
                    mma16816(acc[im][in_], af[im], bf[in_]);
        }
        __syncthreads();
    }

    // epilogue
    #pragma unroll
    for (int im = 0; im < 4; im++) {
        #pragma unroll
        for (int in_ = 0; in_ < 4; in_++) {
            #pragma unroll
            for (int q = 0; q < 4; q++) {
                int ml = wm + im * 16 + qr + (q >> 1) * 8;
                int nl = wn + in_ * 8 + qc + (q & 1);
                float v = acc[im][in_][q];
                if (mode == 0) {
                    int tok = m0 + ml;
                    int col = n0 + nl;
                    int mat = col >> 10, rem = col & 1023;
                    int head = rem >> 6, d = rem & 63;
                    g_qkv[((size_t)(mat * NH + head) * NTOK + tok) * HD + d] = v;
                } else if (mode == 1) {
                    int tok = m0 + ml;
                    int col = n0 + nl;
                    g_proj[(size_t)tok * CDIM + col] = v + bias[col];
                } else if (mode == 2) {
                    int r = m0 + ml;
                    if (r < cnt) {
                        int col = n0 + nl;
                        float u = v + bias[(size_t)e * FF + col];
                        u = 0.5f * u * (1.0f + erff(u * 0.70710678118654752f));
                        __nv_bfloat16 hi = __float2bfloat16(u);
                        size_t o = (size_t)(base + r) * FF + col;
                        g_hh[o] = hi;
                        g_hl[o] = __float2bfloat16(u - __bfloat162float(hi));
                    }
                } else {
                    int r = m0 + ml;
                    if (r < cnt) {
                        int col = n0 + nl;
                        float gate = g_gate[e * NTOK + r];
                        g_eo[(size_t)(base + r) * CDIM + col] =
                            (v + bias[(size_t)e * CDIM + col]) * gate;
                    }
                }
            }
        }
    }
}

// ============================================================
// causal flash attention (fp32 SIMT): 1 thread = 1 query row
// writes bf16 hi/lo head-concat output
// ============================================================
__global__ void k_attn() {
    int bh = blockIdx.y;
    int b = bh / NH, h = bh % NH;
    const float* Q = g_qkv + (size_t)(0 * NH + h) * NTOK * HD;
    const float* K = g_qkv + (size_t)(1 * NH + h) * NTOK * HD;
    const float* V = g_qkv + (size_t)(2 * NH + h) * NTOK * HD;
    int tl = blockIdx.x * 128 + threadIdx.x;
    int tok = b * TSEQ + tl;

    float q[HD];
    #pragma unroll
    for (int d = 0; d < HD; d++) q[d] = Q[(size_t)tok * HD + d] * SCALE;
    float o[HD];
    #pragma unroll
    for (int d = 0; d < HD; d++) o[d] = 0.f;
    float m = -1e30f, l = 0.f;

    __shared__ __align__(16) float Ks[32][HD];
    __shared__ __align__(16) float Vs[32][HD];

    int kmax = blockIdx.x * 128 + 127;
    for (int kb = 0; kb <= kmax; kb += 32) {
        for (int i = threadIdx.x; i < 32 * 16; i += 128) {
            int s = i >> 4, dv = i & 15;
            ((float4*)&Ks[s][0])[dv] = ((const float4*)&K[(size_t)(b * TSEQ + kb + s) * HD])[dv];
            ((float4*)&Vs[s][0])[dv] = ((const float4*)&V[(size_t)(b * TSEQ + kb + s) * HD])[dv];
        }
        __syncthreads();
        float sc[32];
        #pragma unroll
        for (int s = 0; s < 32; s++) {
            float d0 = 0.f;
            #pragma unroll
            for (int d = 0; d < HD; d++) d0 += q[d] * Ks[s][d];
            sc[s] = (kb + s <= tl) ? d0 : -1e30f;
        }
        float mn = m;
        #pragma unroll
        for (int s = 0; s < 32; s++) mn = fmaxf(mn, sc[s]);
        float corr = __expf(m - mn);
        l *= corr;
        #pragma unroll
        for (int d = 0; d < HD; d++) o[d] *= corr;
        #pragma unroll
        for (int s = 0; s < 32; s++) {
            float p = __expf(sc[s] - mn);
            l += p;
            #pragma unroll
            for (int d = 0; d < HD; d++) o[d] += p * Vs[s][d];
        }
        m = mn;
        __syncthreads();
    }
    float inv = 1.f / l;
    #pragma unroll
    for (int d = 0; d < HD; d++) {
        float v = o[d] * inv;
        __nv_bfloat16 hi = __float2bfloat16(v);
        size_t idx = (size_t)tok * CDIM + h * HD + d;
        g_attnh[idx] = hi;
        g_attnl[idx] = __float2bfloat16(v - __bfloat162float(hi));
    }
}

// ============================================================
// LN1 + residual: x1 = x + ln(proj); also emit x1 hi/lo bf16
// ============================================================
__global__ void k_ln1(const float* __restrict__ x,
                      const float* __restrict__ g, const float* __restrict__ bsh) {
    int t = blockIdx.x, tid = threadIdx.x;
    __shared__ float rs[256], rss[256];
    float s = 0.f, ss = 0.f;
    for (int c = tid; c < CDIM; c += 256) {
        float v = g_proj[(size_t)t * CDIM + c];
        s += v; ss += v * v;
    }
    rs[tid] = s; rss[tid] = ss;
    __syncthreads();
    for (int off = 128; off > 0; off >>= 1) {
        if (tid < off) { rs[tid] += rs[tid + off]; rss[tid] += rss[tid + off]; }
        __syncthreads();
    }
    float mean = rs[0] * (1.f / CDIM);
    float var = rss[0] * (1.f / CDIM) - mean * mean;
    float rstd = rsqrtf(var + EPS);
    for (int c = tid; c < CDIM; c += 256) {
        float v = (g_proj[(size_t)t * CDIM + c] - mean) * rstd * g[c] + bsh[c];
        float x1 = x[(size_t)t * CDIM + c] + v;
        g_x1[(size_t)t * CDIM + c] = x1;
        __nv_bfloat16 hi = __float2bfloat16(x1);
        g_x1h[(size_t)t * CDIM + c] = hi;
        g_x1l[(size_t)t * CDIM + c] = __float2bfloat16(x1 - __bfloat162float(hi));
    }
}

// ============================================================
// noisy top-2 router
// ============================================================
__global__ void k_router(const float* __restrict__ Wr, const float* __restrict__ br,
                         const float* __restrict__ Wn, const float* __restrict__ bn,
                         const float* __restrict__ noise) {
    int t = blockIdx.x, tid = threadIdx.x;
    float ar[NE], an[NE];
    #pragma unroll
    for (int e = 0; e < NE; e++) { ar[e] = 0.f; an[e] = 0.f; }
    for (int c = tid; c < CDIM; c += 128) {
        float xv = g_x1[(size_t)t * CDIM + c];
        const float4* wr4 = (const float4*)&Wr[c * NE];
        const float4* wn4 = (const float4*)&Wn[c * NE];
        float4 r0 = wr4[0], r1 = wr4[1];
        float4 n0 = wn4[0], n1 = wn4[1];
        ar[0] += xv * r0.x; ar[1] += xv * r0.y; ar[2] += xv * r0.z; ar[3] += xv * r0.w;
        ar[4] += xv * r1.x; ar[5] += xv * r1.y; ar[6] += xv * r1.z; ar[7] += xv * r1.w;
        an[0] += xv * n0.x; an[1] += xv * n0.y; an[2] += xv * n0.z; an[3] += xv * n0.w;
        an[4] += xv * n1.x; an[5] += xv * n1.y; an[6] += xv * n1.z; an[7] += xv * n1.w;
    }
    __shared__ float red[16 * 128];
    #pragma unroll
    for (int e = 0; e < NE; e++) {
        red[e * 128 + tid] = ar[e];
        red[(e + 8) * 128 + tid] = an[e];
    }
    __syncthreads();
    __shared__ float res[16];
    if (tid < 16) {
        float s = 0.f;
        for (int i = 0; i < 128; i++) s += red[tid * 128 + i];
        res[tid] = s;
    }
    __syncthreads();
    if (tid == 0) {
        float noisy[NE];
        #pragma unroll
        for (int e = 0; e < NE; e++) {
            float lg = res[e] + br[e];
            float nl = res[e + 8] + bn[e];
            float sp = (nl > 20.f) ? nl : log1pf(expf(nl));
            noisy[e] = lg + noise[t * NE + e] * sp;
        }
        int i0 = 0; float v0 = noisy[0];
        #pragma unroll
        for (int e = 1; e < NE; e++) if (noisy[e] > v0) { v0 = noisy[e]; i0 = e; }
        int i1 = -1; float v1 = -1e30f;
        #pragma unroll
        for (int e = 0; e < NE; e++)
            if (e != i0 && noisy[e] > v1) { v1 = noisy[e]; i1 = e; }
        float e1 = expf(v1 - v0);
        float denom = 1.f + e1;
        float gate0 = 1.f / denom, gate1 = e1 / denom;
        int s0 = atomicAdd(&g_counts[i0], 1);
        g_list[i0 * NTOK + s0] = t; g_gate[i0 * NTOK + s0] = gate0;
        g_slot[t * 2 + 0] = i0 * NTOK + s0;
        int s1 = atomicAdd(&g_counts[i1], 1);
        g_list[i1 * NTOK + s1] = t; g_gate[i1 * NTOK + s1] = gate1;
        g_slot[t * 2 + 1] = i1 * NTOK + s1;
    }
}

__global__ void k_prefix() {
    if (threadIdx.x == 0 && blockIdx.x == 0) {
        int s = 0;
        for (int e = 0; e < NE; e++) { g_base[e] = s; s += g_counts[e]; }
    }
}

// ============================================================
// combine 2 expert rows + LN2 + residual
// ============================================================
__global__ void k_out(const float* __restrict__ g, const float* __restrict__ bsh,
                      float* __restrict__ out) {
    int t = blockIdx.x, tid = threadIdx.x;
    __shared__ int srow[2];
    if (tid < 2) {
        int slot = g_slot[t * 2 + tid];
        int e = slot / NTOK, r = slot % NTOK;
        srow[tid] = g_base[e] + r;
    }
    __syncthreads();
    const float* eo0 = g_eo + (size_t)srow[0] * CDIM;
    const float* eo1 = g_eo + (size_t)srow[1] * CDIM;

    __shared__ float rs[256], rss[256];
    float s = 0.f, ss = 0.f;
    for (int c = tid; c < CDIM; c += 256) {
        float v = eo0[c] + eo1[c];
        s += v; ss += v * v;
    }
    rs[tid] = s; rss[tid] = ss;
    __syncthreads();
    for (int off = 128; off > 0; off >>= 1) {
        if (tid < off) { rs[tid] += rs[tid + off]; rss[tid] += rss[tid + off]; }
        __syncthreads();
    }
    float mean = rs[0] * (1.f / CDIM);
    float var = rss[0] * (1.f / CDIM) - mean * mean;
    float rstd = rsqrtf(var + EPS);
    for (int c = tid; c < CDIM; c += 256) {
        float v = ((eo0[c] + eo1[c]) - mean) * rstd * g[c] + bsh[c];
        out[(size_t)t * CDIM + c] = g_x1[(size_t)t * CDIM + c] + v;
    }
}

// ============================================================
extern "C" void kernel_launch(void* const* d_in, const int* in_sizes, int n_in,
                              void* d_out, int out_size) {
    const float* x     = (const float*)d_in[0];
    const float* Wq    = (const float*)d_in[1];
    const float* Wk    = (const float*)d_in[2];
    const float* Wv    = (const float*)d_in[3];
    const float* Wo    = (const float*)d_in[4];
    const float* bo    = (const float*)d_in[5];
    const float* ln1_g = (const float*)d_in[6];
    const float* ln1_b = (const float*)d_in[7];
    const float* Wr    = (const float*)d_in[8];
    const float* br    = (const float*)d_in[9];
    const float* Wn    = (const float*)d_in[10];
    const float* bn    = (const float*)d_in[11];
    const float* W1    = (const float*)d_in[12];
    const float* b1    = (const float*)d_in[13];
    const float* W2    = (const float*)d_in[14];
    const float* b2    = (const float*)d_in[15];
    const float* ln2_g = (const float*)d_in[16];
    const float* ln2_b = (const float*)d_in[17];
    const float* noise = (const float*)d_in[18];
    float* out = (float*)d_out;

    dim3 tb(32, 8);

    k_zero<<<1, 32>>>();
    k_splitx<<<1024, 256>>>(x);
    // weight transpose+split: src [z][K][N] -> [z][N][K]
    k_split_t<<<dim3(32, 2, 16), tb>>>(Wq, CDIM, HD, (long long)CDIM * HD, (long long)HD * CDIM, 0);
    k_split_t<<<dim3(32, 2, 16), tb>>>(Wk, CDIM, HD, (long long)CDIM * HD, (long long)HD * CDIM, 1);
    k_split_t<<<dim3(32, 2, 16), tb>>>(Wv, CDIM, HD, (long long)CDIM * HD, (long long)HD * CDIM, 2);
    k_split_t<<<dim3(32, 32, 1), tb>>>(Wo, CDIM, CDIM, 0LL, 0LL, 3);
    k_split_t<<<dim3(32, 128, 8), tb>>>(W1, CDIM, FF, (long long)CDIM * FF, (long long)FF * CDIM, 4);
    k_split_t<<<dim3(128, 32, 8), tb>>>(W2, FF, CDIM, (long long)FF * CDIM, (long long)CDIM * FF, 5);

    k_gemm<<<dim3(32, 24, 1), 256>>>(0, nullptr);                 // qkv
    k_attn<<<dim3(TSEQ / 128, NB * NH), 128>>>();
    k_gemm<<<dim3(32, 8, 1), 256>>>(1, bo);                       // out-proj
    k_ln1<<<NTOK, 256>>>(x, ln1_g, ln1_b);
    k_router<<<NTOK, 128>>>(Wr, br, Wn, bn, noise);
    k_prefix<<<1, 1>>>();
    k_gemm<<<dim3(32, 32, NE), 256>>>(2, b1);                     // moe1 + gelu
    k_gemm<<<dim3(32, 8, NE), 256>>>(3, b2);                      // moe2 + gate
    k_out<<<NTOK, 256>>>(ln2_g, ln2_b, out);
}

// round 10
// speedup vs baseline: 2.0140x; 1.5400x over previous
#include <cuda_runtime.h>
#include <cuda_bf16.h>
#include <math.h>
#include <stdint.h>

// ---- fixed problem shapes ----
#define NTOK 4096      // B*T
#define TSEQ 2048
#define NB   2
#define CDIM 1024
#define NH   16
#define HD   64
#define FF   4096
#define NE   8
#define EPS  1e-5f
#define SCALE 0.03125f // C^-0.5 = 1/32

// ============================================================
// scratch (device globals: allocation-free)
// ============================================================
__device__ __align__(128) float g_qkv[3 * NH * NTOK * HD];   // fp32 for attention
__device__ __align__(128) float g_proj[NTOK * CDIM];
__device__ __align__(128) float g_x1[NTOK * CDIM];
__device__ __align__(128) float g_eo[2 * NTOK * CDIM];
__device__ int   g_counts[NE];
__device__ int   g_base[NE];
__device__ int   g_list[NE * NTOK];
__device__ float g_gate[NE * NTOK];
__device__ int   g_slot[NTOK * 2];

// bf16 hi/lo activation scratch (K-major rows)
__device__ __align__(128) __nv_bfloat16 g_xh[NTOK * CDIM];
__device__ __align__(128) __nv_bfloat16 g_xl[NTOK * CDIM];
__device__ __align__(128) __nv_bfloat16 g_attnh[NTOK * CDIM];
__device__ __align__(128) __nv_bfloat16 g_attnl[NTOK * CDIM];
__device__ __align__(128) __nv_bfloat16 g_x1h[NTOK * CDIM];
__device__ __align__(128) __nv_bfloat16 g_x1l[NTOK * CDIM];
__device__ __align__(128) __nv_bfloat16 g_hh[2 * NTOK * FF];
__device__ __align__(128) __nv_bfloat16 g_hl[2 * NTOK * FF];

// bf16 hi/lo transposed weights (B^T: [N rows][K cols], K-major)
__device__ __align__(128) __nv_bfloat16 g_Wqkvh[3 * CDIM * CDIM];  // [3072][1024]
__device__ __align__(128) __nv_bfloat16 g_Wqkvl[3 * CDIM * CDIM];
__device__ __align__(128) __nv_bfloat16 g_Woh[CDIM * CDIM];        // [1024][1024]
__device__ __align__(128) __nv_bfloat16 g_Wol[CDIM * CDIM];
__device__ __align__(128) __nv_bfloat16 g_W1h[NE * FF * CDIM];     // [e][4096][1024]
__device__ __align__(128) __nv_bfloat16 g_W1l[NE * FF * CDIM];
__device__ __align__(128) __nv_bfloat16 g_W2h[NE * CDIM * FF];     // [e][1024][4096]
__device__ __align__(128) __nv_bfloat16 g_W2l[NE * CDIM * FF];

// ============================================================
// small kernels
// ============================================================
__global__ void k_zero() {
    if (threadIdx.x < NE) g_counts[threadIdx.x] = 0;
}

// x -> hi/lo bf16 split (elementwise)
__global__ void k_splitx(const float* __restrict__ x) {
    int n = NTOK * CDIM;
    for (int i = blockIdx.x * blockDim.x + threadIdx.x; i < n;
         i += gridDim.x * blockDim.x) {
        float v = x[i];
        __nv_bfloat16 hi = __float2bfloat16(v);
        g_xh[i] = hi;
        g_xl[i] = __float2bfloat16(v - __bfloat162float(hi));
    }
}

// transpose + split: src [z][K][N] fp32 -> dst [z][N][K] bf16 hi/lo
// block (32,8), grid (K/32, N/32, z)
__global__ void k_split_t(const float* __restrict__ src, int K, int N,
                          long long szs, long long dzs, int sel) {
    __nv_bfloat16 *dh, *dl;
    switch (sel) {
        case 0: dh = g_Wqkvh;                 dl = g_Wqkvl;                 break;
        case 1: dh = g_Wqkvh + CDIM * CDIM;   dl = g_Wqkvl + CDIM * CDIM;   break;
        case 2: dh = g_Wqkvh + 2 * CDIM * CDIM; dl = g_Wqkvl + 2 * CDIM * CDIM; break;
        case 3: dh = g_Woh;                   dl = g_Wol;                   break;
        case 4: dh = g_W1h;                   dl = g_W1l;                   break;
        default: dh = g_W2h;                  dl = g_W2l;                   break;
    }
    long long z = blockIdx.z;
    src += z * szs; dh += z * dzs; dl += z * dzs;
    __shared__ float t[32][33];
    int k0 = blockIdx.x * 32, n0 = blockIdx.y * 32;
    int tx = threadIdx.x, ty = threadIdx.y;
    #pragma unroll
    for (int r = 0; r < 4; r++) {
        int k = k0 + ty + r * 8;
        t[ty + r * 8][tx] = src[(size_t)k * N + n0 + tx];
    }
    __syncthreads();
    #pragma unroll
    for (int r = 0; r < 4; r++) {
        int nl = ty + r * 8;
        float v = t[tx][nl];
        __nv_bfloat16 hi = __float2bfloat16(v);
        size_t o = (size_t)(n0 + nl) * K + k0 + tx;
        dh[o] = hi;
        dl[o] = __float2bfloat16(v - __bfloat162float(hi));
    }
}

// ============================================================
// unified bf16 split-GEMM via mma.sync + cp.async + ldmatrix
// block tile 128x128, BK=64, 8 warps (2x4), warp tile 64x32
// per k-chunk loads Ah,Al,Bh,Bl once, runs 3 split terms
// double-buffered cp.async pipeline
// smem element map per buffer: [0,TILE_E)=Ah [TILE_E,2T)=Al [2T,3T)=Bh [3T,4T)=Bl
// ============================================================
#define SMSTR 72                 // bf16 per smem row (64 + 8 pad); 144B: ldmatrix conflict-free
#define TILE_E (128 * SMSTR)     // 9216 elements per tile
#define BUF_E (4 * TILE_E)       // Ah,Al,Bh,Bl
#define SMEM_BYTES (2 * BUF_E * 2)

__device__ __forceinline__ void mma16816(float* c, const uint32_t* a, const uint32_t* b) {
    asm volatile(
        "mma.sync.aligned.m16n8k16.row.col.f32.bf16.bf16.f32 "
        "{%0,%1,%2,%3}, {%4,%5,%6,%7}, {%8,%9}, {%0,%1,%2,%3};"
        : "+f"(c[0]), "+f"(c[1]), "+f"(c[2]), "+f"(c[3])
        : "r"(a[0]), "r"(a[1]), "r"(a[2]), "r"(a[3]), "r"(b[0]), "r"(b[1]));
}
__device__ __forceinline__ void ldsm4(uint32_t* r, uint32_t saddr) {
    asm volatile("ldmatrix.sync.aligned.m8n8.x4.shared.b16 {%0,%1,%2,%3}, [%4];"
        : "=r"(r[0]), "=r"(r[1]), "=r"(r[2]), "=r"(r[3]) : "r"(saddr));
}
#define CPASYNC(dst, src) \
    asm volatile("cp.async.cg.shared.global [%0], [%1], 16;" :: "r"(dst), "l"(src))
#define CPCOMMIT() asm volatile("cp.async.commit_group;" ::: "memory")
#define CPWAIT1()  asm volatile("cp.async.wait_group 1;" ::: "memory")

__device__ __forceinline__ void stage_load(
    uint32_t sbase, int bufo,
    const __nv_bfloat16* __restrict__ Ah, const __nv_bfloat16* __restrict__ Al,
    const __nv_bfloat16* __restrict__ Bh, const __nv_bfloat16* __restrict__ Bl,
    const int* rows, int n0, int lda, int k0, int tid)
{
    #pragma unroll
    for (int i = 0; i < 4; i++) {
        int c = tid + i * 256;
        int r = c >> 3, col = (c & 7) * 8;
        uint32_t d = sbase + 2 * (bufo + r * SMSTR + col);
        size_t ao = (size_t)rows[r] * lda + k0 + col;
        size_t bo = (size_t)(n0 + r) * lda + k0 + col;
        CPASYNC(d,                Ah + ao);   // elem bufo + 0*TILE_E
        CPASYNC(d + 2 * TILE_E,   Al + ao);   // elem bufo + 1*TILE_E
        CPASYNC(d + 4 * TILE_E,   Bh + bo);   // elem bufo + 2*TILE_E
        CPASYNC(d + 6 * TILE_E,   Bl + bo);   // elem bufo + 3*TILE_E
    }
}

__global__ void __launch_bounds__(256, 1)
k_gemm(int mode, const float* __restrict__ bias) {
    extern __shared__ __align__(128) __nv_bfloat16 smem[];
    __shared__ int rows[128];

    int tid = threadIdx.x;
    int lane = tid & 31, wid = tid >> 5;
    int wm = (wid >> 2) * 64;       // warp m offset
    int wn = (wid & 3) * 32;        // warp n offset
    int qr = lane >> 2;
    int qc = (lane & 3) * 2;
    int e = blockIdx.z;
    int m0 = blockIdx.x * 128, n0 = blockIdx.y * 128;

    // per-mode config
    const __nv_bfloat16 *Ahp, *Alp, *Bhp, *Blp;
    int lda, K;
    int cnt = 0, base = 0;
    if (mode == 0) {
        Ahp = g_xh; Alp = g_xl; Bhp = g_Wqkvh; Blp = g_Wqkvl;
        lda = CDIM; K = CDIM;
    } else if (mode == 1) {
        Ahp = g_attnh; Alp = g_attnl; Bhp = g_Woh; Blp = g_Wol;
        lda = CDIM; K = CDIM;
    } else if (mode == 2) {
        cnt = g_counts[e]; base = g_base[e];
        if (m0 >= cnt) return;
        Ahp = g_x1h; Alp = g_x1l;
        Bhp = g_W1h + (size_t)e * FF * CDIM; Blp = g_W1l + (size_t)e * FF * CDIM;
        lda = CDIM; K = CDIM;
    } else {
        cnt = g_counts[e]; base = g_base[e];
        if (m0 >= cnt) return;
        Ahp = g_hh; Alp = g_hl;
        Bhp = g_W2h + (size_t)e * CDIM * FF; Blp = g_W2l + (size_t)e * CDIM * FF;
        lda = FF; K = FF;
    }

    if (tid < 128) {
        if (mode == 2) {
            int r = m0 + tid; if (r >= cnt) r = cnt - 1;
            rows[tid] = g_list[e * NTOK + r];
        } else if (mode == 3) {
            int r = m0 + tid; if (r >= cnt) r = cnt - 1;
            rows[tid] = base + r;
        } else {
            rows[tid] = m0 + tid;
        }
    }
    __syncthreads();

    float acc[4][4][4];
    #pragma unroll
    for (int im = 0; im < 4; im++)
        #pragma unroll
        for (int in_ = 0; in_ < 4; in_++)
            #pragma unroll
            for (int q = 0; q < 4; q++) acc[im][in_][q] = 0.f;

    uint32_t sbase;
    asm("{ .reg .u64 t; cvta.to.shared.u64 t, %1; cvt.u32.u64 %0, t; }"
        : "=r"(sbase) : "l"(smem));

    const int NST = K >> 6;

    // lane offsets for ldmatrix addressing
    int a_row = lane & 15, a_col = (lane >> 4) * 8;
    int b_row = (lane & 7) + ((lane >> 4) << 3);
    int b_col = ((lane >> 3) & 1) * 8;

    // prologue
    stage_load(sbase, 0, Ahp, Alp, Bhp, Blp, rows, n0, lda, 0, tid);
    CPCOMMIT();

    for (int kc = 0; kc < NST; kc++) {
        int cbuf = (kc & 1) * BUF_E;
        if (kc + 1 < NST)
            stage_load(sbase, ((kc + 1) & 1) * BUF_E, Ahp, Alp, Bhp, Blp,
                       rows, n0, lda, (kc + 1) << 6, tid);
        CPCOMMIT();
        CPWAIT1();
        __syncthreads();

        #pragma unroll
        for (int ks = 0; ks < 4; ks++) {
            int kb = ks * 16;
            uint32_t ah[4][4], al[4][4], bh[2][4], bl[2][4];
            #pragma unroll
            for (int im = 0; im < 4; im++) {
                uint32_t ad = sbase + 2 * (cbuf + (wm + im * 16 + a_row) * SMSTR + kb + a_col);
                ldsm4(ah[im], ad);
                ldsm4(al[im], ad + 2 * TILE_E);        // +TILE_E elements (Al)
            }
            #pragma unroll
            for (int ip = 0; ip < 2; ip++) {
                uint32_t bd = sbase + 2 * (cbuf + 2 * TILE_E + (wn + ip * 16 + b_row) * SMSTR + kb + b_col);
                ldsm4(bh[ip], bd);                      // Bh at elem cbuf+2*TILE_E
                ldsm4(bl[ip], bd + 2 * TILE_E);         // Bl at elem cbuf+3*TILE_E
            }
            #pragma unroll
            for (int im = 0; im < 4; im++) {
                #pragma unroll
                for (int in_ = 0; in_ < 4; in_++) {
                    uint32_t* bhp = &bh[in_ >> 1][(in_ & 1) * 2];
                    uint32_t* blp = &bl[in_ >> 1][(in_ & 1) * 2];
                    mma16816(acc[im][in_], ah[im], bhp);
                    mma16816(acc[im][in_], ah[im], blp);
                    mma16816(acc[im][in_], al[im], bhp);
                }
            }
        }
        __syncthreads();
    }

    // epilogue
    #pragma unroll
    for (int im = 0; im < 4; im++) {
        #pragma unroll
        for (int in_ = 0; in_ < 4; in_++) {
            #pragma unroll
            for (int q = 0; q < 4; q++) {
                int ml = wm + im * 16 + qr + (q >> 1) * 8;
                int nl = wn + in_ * 8 + qc + (q & 1);
                float v = acc[im][in_][q];
                if (mode == 0) {
                    int tok = m0 + ml;
                    int col = n0 + nl;
                    int mat = col >> 10, rem = col & 1023;
                    int head = rem >> 6, d = rem & 63;
                    g_qkv[((size_t)(mat * NH + head) * NTOK + tok) * HD + d] = v;
                } else if (mode == 1) {
                    int tok = m0 + ml;
                    int col = n0 + nl;
                    g_proj[(size_t)tok * CDIM + col] = v + bias[col];
                } else if (mode == 2) {
                    int r = m0 + ml;
                    if (r < cnt) {
                        int col = n0 + nl;
                        float u = v + bias[(size_t)e * FF + col];
                        u = 0.5f * u * (1.0f + erff(u * 0.70710678118654752f));
                        __nv_bfloat16 hi = __float2bfloat16(u);
                        size_t o = (size_t)(base + r) * FF + col;
                        g_hh[o] = hi;
                        g_hl[o] = __float2bfloat16(u - __bfloat162float(hi));
                    }
                } else {
                    int r = m0 + ml;
                    if (r < cnt) {
                        int col = n0 + nl;
                        float gate = g_gate[e * NTOK + r];
                        g_eo[(size_t)(base + r) * CDIM + col] =
                            (v + bias[(size_t)e * CDIM + col]) * gate;
                    }
                }
            }
        }
    }
}

// ============================================================
// causal flash attention (fp32 SIMT): 1 thread = 1 query row
// writes bf16 hi/lo head-concat output
// ============================================================
__global__ void k_attn() {
    int bh = blockIdx.y;
    int b = bh / NH, h = bh % NH;
    const float* Q = g_qkv + (size_t)(0 * NH + h) * NTOK * HD;
    const float* K = g_qkv + (size_t)(1 * NH + h) * NTOK * HD;
    const float* V = g_qkv + (size_t)(2 * NH + h) * NTOK * HD;
    int tl = blockIdx.x * 128 + threadIdx.x;
    int tok = b * TSEQ + tl;

    float q[HD];
    #pragma unroll
    for (int d = 0; d < HD; d++) q[d] = Q[(size_t)tok * HD + d] * SCALE;
    float o[HD];
    #pragma unroll
    for (int d = 0; d < HD; d++) o[d] = 0.f;
    float m = -1e30f, l = 0.f;

    __shared__ __align__(16) float Ks[32][HD];
    __shared__ __align__(16) float Vs[32][HD];

    int kmax = blockIdx.x * 128 + 127;
    for (int kb = 0; kb <= kmax; kb += 32) {
        for (int i = threadIdx.x; i < 32 * 16; i += 128) {
            int s = i >> 4, dv = i & 15;
            ((float4*)&Ks[s][0])[dv] = ((const float4*)&K[(size_t)(b * TSEQ + kb + s) * HD])[dv];
            ((float4*)&Vs[s][0])[dv] = ((const float4*)&V[(size_t)(b * TSEQ + kb + s) * HD])[dv];
        }
        __syncthreads();
        float sc[32];
        #pragma unroll
        for (int s = 0; s < 32; s++) {
            float d0 = 0.f;
            #pragma unroll
            for (int d = 0; d < HD; d++) d0 += q[d] * Ks[s][d];
            sc[s] = (kb + s <= tl) ? d0 : -1e30f;
        }
        float mn = m;
        #pragma unroll
        for (int s = 0; s < 32; s++) mn = fmaxf(mn, sc[s]);
        float corr = __expf(m - mn);
        l *= corr;
        #pragma unroll
        for (int d = 0; d < HD; d++) o[d] *= corr;
        #pragma unroll
        for (int s = 0; s < 32; s++) {
            float p = __expf(sc[s] - mn);
            l += p;
            #pragma unroll
            for (int d = 0; d < HD; d++) o[d] += p * Vs[s][d];
        }
        m = mn;
        __syncthreads();
    }
    float inv = 1.f / l;
    #pragma unroll
    for (int d = 0; d < HD; d++) {
        float v = o[d] * inv;
        __nv_bfloat16 hi = __float2bfloat16(v);
        size_t idx = (size_t)tok * CDIM + h * HD + d;
        g_attnh[idx] = hi;
        g_attnl[idx] = __float2bfloat16(v - __bfloat162float(hi));
    }
}

// ============================================================
// LN1 + residual: x1 = x + ln(proj); also emit x1 hi/lo bf16
// ============================================================
__global__ void k_ln1(const float* __restrict__ x,
                      const float* __restrict__ g, const float* __restrict__ bsh) {
    int t = blockIdx.x, tid = threadIdx.x;
    __shared__ float rs[256], rss[256];
    float s = 0.f, ss = 0.f;
    for (int c = tid; c < CDIM; c += 256) {
        float v = g_proj[(size_t)t * CDIM + c];
        s += v; ss += v * v;
    }
    rs[tid] = s; rss[tid] = ss;
    __syncthreads();
    for (int off = 128; off > 0; off >>= 1) {
        if (tid < off) { rs[tid] += rs[tid + off]; rss[tid] += rss[tid + off]; }
        __syncthreads();
    }
    float mean = rs[0] * (1.f / CDIM);
    float var = rss[0] * (1.f / CDIM) - mean * mean;
    float rstd = rsqrtf(var + EPS);
    for (int c = tid; c < CDIM; c += 256) {
        float v = (g_proj[(size_t)t * CDIM + c] - mean) * rstd * g[c] + bsh[c];
        float x1 = x[(size_t)t * CDIM + c] + v;
        g_x1[(size_t)t * CDIM + c] = x1;
        __nv_bfloat16 hi = __float2bfloat16(x1);
        g_x1h[(size_t)t * CDIM + c] = hi;
        g_x1l[(size_t)t * CDIM + c] = __float2bfloat16(x1 - __bfloat162float(hi));
    }
}

// ============================================================
// noisy top-2 router
// ============================================================
__global__ void k_router(const float* __restrict__ Wr, const float* __restrict__ br,
                         const float* __restrict__ Wn, const float* __restrict__ bn,
                         const float* __restrict__ noise) {
    int t = blockIdx.x, tid = threadIdx.x;
    float ar[NE], an[NE];
    #pragma unroll
    for (int e = 0; e < NE; e++) { ar[e] = 0.f; an[e] = 0.f; }
    for (int c = tid; c < CDIM; c += 128) {
        float xv = g_x1[(size_t)t * CDIM + c];
        const float4* wr4 = (const float4*)&Wr[c * NE];
        const float4* wn4 = (const float4*)&Wn[c * NE];
        float4 r0 = wr4[0], r1 = wr4[1];
        float4 n0 = wn4[0], n1 = wn4[1];
        ar[0] += xv * r0.x; ar[1] += xv * r0.y; ar[2] += xv * r0.z; ar[3] += xv * r0.w;
        ar[4] += xv * r1.x; ar[5] += xv * r1.y; ar[6] += xv * r1.z; ar[7] += xv * r1.w;
        an[0] += xv * n0.x; an[1] += xv * n0.y; an[2] += xv * n0.z; an[3] += xv * n0.w;
        an[4] += xv * n1.x; an[5] += xv * n1.y; an[6] += xv * n1.z; an[7] += xv * n1.w;
    }
    __shared__ float red[16 * 128];
    #pragma unroll
    for (int e = 0; e < NE; e++) {
        red[e * 128 + tid] = ar[e];
        red[(e + 8) * 128 + tid] = an[e];
    }
    __syncthreads();
    __shared__ float res[16];
    if (tid < 16) {
        float s = 0.f;
        for (int i = 0; i < 128; i++) s += red[tid * 128 + i];
        res[tid] = s;
    }
    __syncthreads();
    if (tid == 0) {
        float noisy[NE];
        #pragma unroll
        for (int e = 0; e < NE; e++) {
            float lg = res[e] + br[e];
            float nl = res[e + 8] + bn[e];
            float sp = (nl > 20.f) ? nl : log1pf(expf(nl));
            noisy[e] = lg + noise[t * NE + e] * sp;
        }
        int i0 = 0; float v0 = noisy[0];
        #pragma unroll
        for (int e = 1; e < NE; e++) if (noisy[e] > v0) { v0 = noisy[e]; i0 = e; }
        int i1 = -1; float v1 = -1e30f;
        #pragma unroll
        for (int e = 0; e < NE; e++)
            if (e != i0 && noisy[e] > v1) { v1 = noisy[e]; i1 = e; }
        float e1 = expf(v1 - v0);
        float denom = 1.f + e1;
        float gate0 = 1.f / denom, gate1 = e1 / denom;
        int s0 = atomicAdd(&g_counts[i0], 1);
        g_list[i0 * NTOK + s0] = t; g_gate[i0 * NTOK + s0] = gate0;
        g_slot[t * 2 + 0] = i0 * NTOK + s0;
        int s1 = atomicAdd(&g_counts[i1], 1);
        g_list[i1 * NTOK + s1] = t; g_gate[i1 * NTOK + s1] = gate1;
        g_slot[t * 2 + 1] = i1 * NTOK + s1;
    }
}

__global__ void k_prefix() {
    if (threadIdx.x == 0 && blockIdx.x == 0) {
        int s = 0;
        for (int e = 0; e < NE; e++) { g_base[e] = s; s += g_counts[e]; }
    }
}

// ============================================================
// combine 2 expert rows + LN2 + residual
// ============================================================
__global__ void k_out(const float* __restrict__ g, const float* __restrict__ bsh,
                      float* __restrict__ out) {
    int t = blockIdx.x, tid = threadIdx.x;
    __shared__ int srow[2];
    if (tid < 2) {
        int slot = g_slot[t * 2 + tid];
        int e = slot / NTOK, r = slot % NTOK;
        srow[tid] = g_base[e] + r;
    }
    __syncthreads();
    const float* eo0 = g_eo + (size_t)srow[0] * CDIM;
    const float* eo1 = g_eo + (size_t)srow[1] * CDIM;

    __shared__ float rs[256], rss[256];
    float s = 0.f, ss = 0.f;
    for (int c = tid; c < CDIM; c += 256) {
        float v = eo0[c] + eo1[c];
        s += v; ss += v * v;
    }
    rs[tid] = s; rss[tid] = ss;
    __syncthreads();
    for (int off = 128; off > 0; off >>= 1) {
        if (tid < off) { rs[tid] += rs[tid + off]; rss[tid] += rss[tid + off]; }
        __syncthreads();
    }
    float mean = rs[0] * (1.f / CDIM);
    float var = rss[0] * (1.f / CDIM) - mean * mean;
    float rstd = rsqrtf(var + EPS);
    for (int c = tid; c < CDIM; c += 256) {
        float v = ((eo0[c] + eo1[c]) - mean) * rstd * g[c] + bsh[c];
        out[(size_t)t * CDIM + c] = g_x1[(size_t)t * CDIM + c] + v;
    }
}

// ============================================================
extern "C" void kernel_launch(void* const* d_in, const int* in_sizes, int n_in,
                              void* d_out, int out_size) {
    const float* x     = (const float*)d_in[0];
    const float* Wq    = (const float*)d_in[1];
    const float* Wk    = (const float*)d_in[2];
    const float* Wv    = (const float*)d_in[3];
    const float* Wo    = (const float*)d_in[4];
    const float* bo    = (const float*)d_in[5];
    const float* ln1_g = (const float*)d_in[6];
    const float* ln1_b = (const float*)d_in[7];
    const float* Wr    = (const float*)d_in[8];
    const float* br    = (const float*)d_in[9];
    const float* Wn    = (const float*)d_in[10];
    const float* bn    = (const float*)d_in[11];
    const float* W1    = (const float*)d_in[12];
    const float* b1    = (const float*)d_in[13];
    const float* W2    = (const float*)d_in[14];
    const float* b2    = (const float*)d_in[15];
    const float* ln2_g = (const float*)d_in[16];
    const float* ln2_b = (const float*)d_in[17];
    const float* noise = (const float*)d_in[18];
    float* out = (float*)d_out;

    cudaFuncSetAttribute(k_gemm, cudaFuncAttributeMaxDynamicSharedMemorySize, SMEM_BYTES);

    dim3 tb(32, 8);

    k_zero<<<1, 32>>>();
    k_splitx<<<1024, 256>>>(x);
    // weight transpose+split: src [z][K][N] -> [z][N][K]
    k_split_t<<<dim3(32, 2, 16), tb>>>(Wq, CDIM, HD, (long long)CDIM * HD, (long long)HD * CDIM, 0);
    k_split_t<<<dim3(32, 2, 16), tb>>>(Wk, CDIM, HD, (long long)CDIM * HD, (long long)HD * CDIM, 1);
    k_split_t<<<dim3(32, 2, 16), tb>>>(Wv, CDIM, HD, (long long)CDIM * HD, (long long)HD * CDIM, 2);
    k_split_t<<<dim3(32, 32, 1), tb>>>(Wo, CDIM, CDIM, 0LL, 0LL, 3);
    k_split_t<<<dim3(32, 128, 8), tb>>>(W1, CDIM, FF, (long long)CDIM * FF, (long long)FF * CDIM, 4);
    k_split_t<<<dim3(128, 32, 8), tb>>>(W2, FF, CDIM, (long long)FF * CDIM, (long long)CDIM * FF, 5);

    k_gemm<<<dim3(32, 24, 1), 256, SMEM_BYTES>>>(0, nullptr);     // qkv
    k_attn<<<dim3(TSEQ / 128, NB * NH), 128>>>();
    k_gemm<<<dim3(32, 8, 1), 256, SMEM_BYTES>>>(1, bo);           // out-proj
    k_ln1<<<NTOK, 256>>>(x, ln1_g, ln1_b);
    k_router<<<NTOK, 128>>>(Wr, br, Wn, bn, noise);
    k_prefix<<<1, 1>>>();
    k_gemm<<<dim3(32, 32, NE), 256, SMEM_BYTES>>>(2, b1);         // moe1 + gelu
    k_gemm<<<dim3(32, 8, NE), 256, SMEM_BYTES>>>(3, b2);          // moe2 + gate
    k_out<<<NTOK, 256>>>(ln2_g, ln2_b, out);
}

// round 11
// speedup vs baseline: 2.0557x; 1.0207x over previous
#include <cuda_runtime.h>
#include <cuda_bf16.h>
#include <math.h>
#include <stdint.h>

// ---- fixed problem shapes ----
#define NTOK 4096      // B*T
#define TSEQ 2048
#define NB   2
#define CDIM 1024
#define NH   16
#define HD   64
#define FF   4096
#define NE   8
#define EPS  1e-5f
#define SCALE 0.03125f // C^-0.5 = 1/32

// ============================================================
// scratch (device globals: allocation-free)
// ============================================================
__device__ __align__(128) float g_qkv[3 * NH * NTOK * HD];   // fp32 for attention
__device__ __align__(128) float g_proj[NTOK * CDIM];
__device__ __align__(128) float g_x1[NTOK * CDIM];
__device__ __align__(128) float g_eo[2 * NTOK * CDIM];
__device__ int   g_counts[NE];
__device__ int   g_base[NE];
__device__ int   g_list[NE * NTOK];
__device__ float g_gate[NE * NTOK];
__device__ int   g_slot[NTOK * 2];

// bf16 hi/lo activation scratch (K-major rows)
__device__ __align__(128) __nv_bfloat16 g_xh[NTOK * CDIM];
__device__ __align__(128) __nv_bfloat16 g_xl[NTOK * CDIM];
__device__ __align__(128) __nv_bfloat16 g_attnh[NTOK * CDIM];
__device__ __align__(128) __nv_bfloat16 g_attnl[NTOK * CDIM];
__device__ __align__(128) __nv_bfloat16 g_x1h[NTOK * CDIM];
__device__ __align__(128) __nv_bfloat16 g_x1l[NTOK * CDIM];
__device__ __align__(128) __nv_bfloat16 g_hh[2 * NTOK * FF];
__device__ __align__(128) __nv_bfloat16 g_hl[2 * NTOK * FF];

// bf16 hi/lo transposed weights (B^T: [N rows][K cols], K-major)
__device__ __align__(128) __nv_bfloat16 g_Wqkvh[3 * CDIM * CDIM];  // [3072][1024]
__device__ __align__(128) __nv_bfloat16 g_Wqkvl[3 * CDIM * CDIM];
__device__ __align__(128) __nv_bfloat16 g_Woh[CDIM * CDIM];        // [1024][1024]
__device__ __align__(128) __nv_bfloat16 g_Wol[CDIM * CDIM];
__device__ __align__(128) __nv_bfloat16 g_W1h[NE * FF * CDIM];     // [e][4096][1024]
__device__ __align__(128) __nv_bfloat16 g_W1l[NE * FF * CDIM];
__device__ __align__(128) __nv_bfloat16 g_W2h[NE * CDIM * FF];     // [e][1024][4096]
__device__ __align__(128) __nv_bfloat16 g_W2l[NE * CDIM * FF];

__device__ __forceinline__ uint32_t pack2bf(float a, float b) {
    __nv_bfloat162 t;
    t.x = __float2bfloat16(a);
    t.y = __float2bfloat16(b);
    return *(uint32_t*)&t;
}

// ============================================================
// small kernels
// ============================================================
__global__ void k_zero() {
    if (threadIdx.x < NE) g_counts[threadIdx.x] = 0;
}

// x -> hi/lo bf16 split, vectorized (float4 in, bf16x4 out)
__global__ void k_splitx(const float* __restrict__ x) {
    int n4 = NTOK * CDIM / 4;
    for (int i = blockIdx.x * blockDim.x + threadIdx.x; i < n4;
         i += gridDim.x * blockDim.x) {
        float4 v = ((const float4*)x)[i];
        __nv_bfloat16 h0 = __float2bfloat16(v.x);
        __nv_bfloat16 h1 = __float2bfloat16(v.y);
        __nv_bfloat16 h2 = __float2bfloat16(v.z);
        __nv_bfloat16 h3 = __float2bfloat16(v.w);
        uint2 hi, lo;
        hi.x = pack2bf(v.x, v.y); hi.y = pack2bf(v.z, v.w);
        lo.x = pack2bf(v.x - __bfloat162float(h0), v.y - __bfloat162float(h1));
        lo.y = pack2bf(v.z - __bfloat162float(h2), v.w - __bfloat162float(h3));
        ((uint2*)g_xh)[i] = hi;
        ((uint2*)g_xl)[i] = lo;
    }
}

// transpose + split (vectorized): src [z][K][N] fp32 -> dst [z][N][K] bf16 hi/lo
// tile 64(k) x 64(n), block 256, grid (N/64, K/64, z)
__global__ void __launch_bounds__(256)
k_split_w(const float* __restrict__ src, int K, int N,
          long long szs, long long dzs, int sel) {
    __nv_bfloat16 *dh, *dl;
    switch (sel) {
        case 0: dh = g_Wqkvh;                   dl = g_Wqkvl;                   break;
        case 1: dh = g_Wqkvh + CDIM * CDIM;     dl = g_Wqkvl + CDIM * CDIM;     break;
        case 2: dh = g_Wqkvh + 2 * CDIM * CDIM; dl = g_Wqkvl + 2 * CDIM * CDIM; break;
        case 3: dh = g_Woh;                     dl = g_Wol;                     break;
        case 4: dh = g_W1h;                     dl = g_W1l;                     break;
        default: dh = g_W2h;                    dl = g_W2l;                     break;
    }
    long long z = blockIdx.z;
    src += z * szs; dh += z * dzs; dl += z * dzs;

    __shared__ float t[64][68];   // [n][k], padded
    int n0 = blockIdx.x * 64, k0 = blockIdx.y * 64;
    int tid = threadIdx.x;

    // load 64k x 64n, float4 along n; store transposed into smem
    int tk = tid >> 4;            // 0..15
    int tn4 = (tid & 15) * 4;     // n offset
    #pragma unroll
    for (int r = 0; r < 4; r++) {
        int k = r * 16 + tk;
        float4 v = *(const float4*)(src + (size_t)(k0 + k) * N + n0 + tn4);
        t[tn4 + 0][k] = v.x;
        t[tn4 + 1][k] = v.y;
        t[tn4 + 2][k] = v.z;
        t[tn4 + 3][k] = v.w;
    }
    __syncthreads();

    // store: each thread one n row, 16 consecutive k; 16B stores
    int sn = tid >> 2;            // 0..63
    int skg = (tid & 3) * 16;     // k group
    float v[16];
    #pragma unroll
    for (int i = 0; i < 16; i += 4) {
        float4 w = *(const float4*)&t[sn][skg + i];
        v[i] = w.x; v[i + 1] = w.y; v[i + 2] = w.z; v[i + 3] = w.w;
    }
    uint32_t hi[8], lo[8];
    #pragma unroll
    for (int j = 0; j < 8; j++) {
        float a = v[2 * j], b = v[2 * j + 1];
        __nv_bfloat16 ha = __float2bfloat16(a);
        __nv_bfloat16 hb = __float2bfloat16(b);
        hi[j] = pack2bf(a, b);
        lo[j] = pack2bf(a - __bfloat162float(ha), b - __bfloat162float(hb));
    }
    size_t off = (size_t)(n0 + sn) * K + k0 + skg;
    *(uint4*)(dh + off)     = make_uint4(hi[0], hi[1], hi[2], hi[3]);
    *(uint4*)(dh + off + 8) = make_uint4(hi[4], hi[5], hi[6], hi[7]);
    *(uint4*)(dl + off)     = make_uint4(lo[0], lo[1], lo[2], lo[3]);
    *(uint4*)(dl + off + 8) = make_uint4(lo[4], lo[5], lo[6], lo[7]);
}

// ============================================================
// unified bf16 split-GEMM via mma.sync + cp.async + ldmatrix
// block tile 128x128, BK=64, 8 warps (2x4), warp tile 64x32
// per k-chunk loads Ah,Al,Bh,Bl once, runs 3 split terms
// double-buffered cp.async pipeline
// smem element map per buffer: [0,T)=Ah [T,2T)=Al [2T,3T)=Bh [3T,4T)=Bl
// ============================================================
#define SMSTR 72                 // bf16 per smem row (64 + 8 pad)
#define TILE_E (128 * SMSTR)     // 9216 elements per tile
#define BUF_E (4 * TILE_E)
#define SMEM_BYTES (2 * BUF_E * 2)

__device__ __forceinline__ void mma16816(float* c, const uint32_t* a, const uint32_t* b) {
    asm volatile(
        "mma.sync.aligned.m16n8k16.row.col.f32.bf16.bf16.f32 "
        "{%0,%1,%2,%3}, {%4,%5,%6,%7}, {%8,%9}, {%0,%1,%2,%3};"
        : "+f"(c[0]), "+f"(c[1]), "+f"(c[2]), "+f"(c[3])
        : "r"(a[0]), "r"(a[1]), "r"(a[2]), "r"(a[3]), "r"(b[0]), "r"(b[1]));
}
__device__ __forceinline__ void ldsm4(uint32_t* r, uint32_t saddr) {
    asm volatile("ldmatrix.sync.aligned.m8n8.x4.shared.b16 {%0,%1,%2,%3}, [%4];"
        : "=r"(r[0]), "=r"(r[1]), "=r"(r[2]), "=r"(r[3]) : "r"(saddr));
}
#define CPASYNC(dst, src) \
    asm volatile("cp.async.cg.shared.global [%0], [%1], 16;" :: "r"(dst), "l"(src))
#define CPCOMMIT() asm volatile("cp.async.commit_group;" ::: "memory")
#define CPWAIT1()  asm volatile("cp.async.wait_group 1;" ::: "memory")

__device__ __forceinline__ void stage_load(
    uint32_t sbase, int bufo,
    const __nv_bfloat16* __restrict__ Ah, const __nv_bfloat16* __restrict__ Al,
    const __nv_bfloat16* __restrict__ Bh, const __nv_bfloat16* __restrict__ Bl,
    const int* rows, int n0, int lda, int k0, int tid)
{
    #pragma unroll
    for (int i = 0; i < 4; i++) {
        int c = tid + i * 256;
        int r = c >> 3, col = (c & 7) * 8;
        uint32_t d = sbase + 2 * (bufo + r * SMSTR + col);
        size_t ao = (size_t)rows[r] * lda + k0 + col;
        size_t bo = (size_t)(n0 + r) * lda + k0 + col;
        CPASYNC(d,                Ah + ao);
        CPASYNC(d + 2 * TILE_E,   Al + ao);
        CPASYNC(d + 4 * TILE_E,   Bh + bo);
        CPASYNC(d + 6 * TILE_E,   Bl + bo);
    }
}

__global__ void __launch_bounds__(256, 1)
k_gemm(int mode, const float* __restrict__ bias) {
    extern __shared__ __align__(128) __nv_bfloat16 smem[];
    __shared__ int rows[128];

    int tid = threadIdx.x;
    int lane = tid & 31, wid = tid >> 5;
    int wm = (wid >> 2) * 64;
    int wn = (wid & 3) * 32;
    int qr = lane >> 2;
    int qc = (lane & 3) * 2;
    int e = blockIdx.z;
    int m0 = blockIdx.x * 128, n0 = blockIdx.y * 128;

    const __nv_bfloat16 *Ahp, *Alp, *Bhp, *Blp;
    int lda, K;
    int cnt = 0, base = 0;
    if (mode == 0) {
        Ahp = g_xh; Alp = g_xl; Bhp = g_Wqkvh; Blp = g_Wqkvl;
        lda = CDIM; K = CDIM;
    } else if (mode == 1) {
        Ahp = g_attnh; Alp = g_attnl; Bhp = g_Woh; Blp = g_Wol;
        lda = CDIM; K = CDIM;
    } else if (mode == 2) {
        cnt = g_counts[e]; base = g_base[e];
        if (m0 >= cnt) return;
        Ahp = g_x1h; Alp = g_x1l;
        Bhp = g_W1h + (size_t)e * FF * CDIM; Blp = g_W1l + (size_t)e * FF * CDIM;
        lda = CDIM; K = CDIM;
    } else {
        cnt = g_counts[e]; base = g_base[e];
        if (m0 >= cnt) return;
        Ahp = g_hh; Alp = g_hl;
        Bhp = g_W2h + (size_t)e * CDIM * FF; Blp = g_W2l + (size_t)e * CDIM * FF;
        lda = FF; K = FF;
    }

    if (tid < 128) {
        if (mode == 2) {
            int r = m0 + tid; if (r >= cnt) r = cnt - 1;
            rows[tid] = g_list[e * NTOK + r];
        } else if (mode == 3) {
            int r = m0 + tid; if (r >= cnt) r = cnt - 1;
            rows[tid] = base + r;
        } else {
            rows[tid] = m0 + tid;
        }
    }
    __syncthreads();

    float acc[4][4][4];
    #pragma unroll
    for (int im = 0; im < 4; im++)
        #pragma unroll
        for (int in_ = 0; in_ < 4; in_++)
            #pragma unroll
            for (int q = 0; q < 4; q++) acc[im][in_][q] = 0.f;

    uint32_t sbase;
    asm("{ .reg .u64 t; cvta.to.shared.u64 t, %1; cvt.u32.u64 %0, t; }"
        : "=r"(sbase) : "l"(smem));

    const int NST = K >> 6;

    int a_row = lane & 15, a_col = (lane >> 4) * 8;
    int b_row = (lane & 7) + ((lane >> 4) << 3);
    int b_col = ((lane >> 3) & 1) * 8;

    stage_load(sbase, 0, Ahp, Alp, Bhp, Blp, rows, n0, lda, 0, tid);
    CPCOMMIT();

    for (int kc = 0; kc < NST; kc++) {
        int cbuf = (kc & 1) * BUF_E;
        if (kc + 1 < NST)
            stage_load(sbase, ((kc + 1) & 1) * BUF_E, Ahp, Alp, Bhp, Blp,
                       rows, n0, lda, (kc + 1) << 6, tid);
        CPCOMMIT();
        CPWAIT1();
        __syncthreads();

        #pragma unroll
        for (int ks = 0; ks < 4; ks++) {
            int kb = ks * 16;
            uint32_t ah[4][4], al[4][4], bh[2][4], bl[2][4];
            #pragma unroll
            for (int im = 0; im < 4; im++) {
                uint32_t ad = sbase + 2 * (cbuf + (wm + im * 16 + a_row) * SMSTR + kb + a_col);
                ldsm4(ah[im], ad);
                ldsm4(al[im], ad + 2 * TILE_E);
            }
            #pragma unroll
            for (int ip = 0; ip < 2; ip++) {
                uint32_t bd = sbase + 2 * (cbuf + 2 * TILE_E + (wn + ip * 16 + b_row) * SMSTR + kb + b_col);
                ldsm4(bh[ip], bd);
                ldsm4(bl[ip], bd + 2 * TILE_E);
            }
            #pragma unroll
            for (int im = 0; im < 4; im++) {
                #pragma unroll
                for (int in_ = 0; in_ < 4; in_++) {
                    uint32_t* bhp = &bh[in_ >> 1][(in_ & 1) * 2];
                    uint32_t* blp = &bl[in_ >> 1][(in_ & 1) * 2];
                    mma16816(acc[im][in_], ah[im], bhp);
                    mma16816(acc[im][in_], ah[im], blp);
                    mma16816(acc[im][in_], al[im], bhp);
                }
            }
        }
        __syncthreads();
    }

    // vectorized epilogue: quads (0,1)/(2,3) are column-adjacent
    #pragma unroll
    for (int im = 0; im < 4; im++) {
        #pragma unroll
        for (int in_ = 0; in_ < 4; in_++) {
            #pragma unroll
            for (int half = 0; half < 2; half++) {
                int ml = wm + im * 16 + qr + half * 8;
                int nl = wn + in_ * 8 + qc;
                float v0 = acc[im][in_][half * 2 + 0];
                float v1 = acc[im][in_][half * 2 + 1];
                if (mode == 0) {
                    int tok = m0 + ml;
                    int col = n0 + nl;
                    int mat = col >> 10, rem = col & 1023;
                    int head = rem >> 6, d = rem & 63;
                    float2* p = (float2*)&g_qkv[((size_t)(mat * NH + head) * NTOK + tok) * HD + d];
                    *p = make_float2(v0, v1);
                } else if (mode == 1) {
                    int tok = m0 + ml;
                    int col = n0 + nl;
                    *(float2*)&g_proj[(size_t)tok * CDIM + col] =
                        make_float2(v0 + bias[col], v1 + bias[col + 1]);
                } else if (mode == 2) {
                    int r = m0 + ml;
                    if (r < cnt) {
                        int col = n0 + nl;
                        float u0 = v0 + bias[(size_t)e * FF + col];
                        float u1 = v1 + bias[(size_t)e * FF + col + 1];
                        u0 = 0.5f * u0 * (1.0f + erff(u0 * 0.70710678118654752f));
                        u1 = 0.5f * u1 * (1.0f + erff(u1 * 0.70710678118654752f));
                        __nv_bfloat16 h0 = __float2bfloat16(u0);
                        __nv_bfloat16 h1 = __float2bfloat16(u1);
                        size_t o = (size_t)(base + r) * FF + col;
                        *(uint32_t*)&g_hh[o] = pack2bf(u0, u1);
                        *(uint32_t*)&g_hl[o] = pack2bf(u0 - __bfloat162float(h0),
                                                       u1 - __bfloat162float(h1));
                    }
                } else {
                    int r = m0 + ml;
                    if (r < cnt) {
                        int col = n0 + nl;
                        float gate = g_gate[e * NTOK + r];
                        *(float2*)&g_eo[(size_t)(base + r) * CDIM + col] =
                            make_float2((v0 + bias[(size_t)e * CDIM + col]) * gate,
                                        (v1 + bias[(size_t)e * CDIM + col + 1]) * gate);
                    }
                }
            }
        }
    }
}

// ============================================================
// causal flash attention (fp32 SIMT): 1 thread = 1 query row
// ============================================================
__global__ void k_attn() {
    int bh = blockIdx.y;
    int b = bh / NH, h = bh % NH;
    const float* Q = g_qkv + (size_t)(0 * NH + h) * NTOK * HD;
    const float* K = g_qkv + (size_t)(1 * NH + h) * NTOK * HD;
    const float* V = g_qkv + (size_t)(2 * NH + h) * NTOK * HD;
    int tl = blockIdx.x * 128 + threadIdx.x;
    int tok = b * TSEQ + tl;

    float q[HD];
    #pragma unroll
    for (int d = 0; d < HD; d++) q[d] = Q[(size_t)tok * HD + d] * SCALE;
    float o[HD];
    #pragma unroll
    for (int d = 0; d < HD; d++) o[d] = 0.f;
    float m = -1e30f, l = 0.f;

    __shared__ __align__(16) float Ks[32][HD];
    __shared__ __align__(16) float Vs[32][HD];

    int kmax = blockIdx.x * 128 + 127;
    for (int kb = 0; kb <= kmax; kb += 32) {
        for (int i = threadIdx.x; i < 32 * 16; i += 128) {
            int s = i >> 4, dv = i & 15;
            ((float4*)&Ks[s][0])[dv] = ((const float4*)&K[(size_t)(b * TSEQ + kb + s) * HD])[dv];
            ((float4*)&Vs[s][0])[dv] = ((const float4*)&V[(size_t)(b * TSEQ + kb + s) * HD])[dv];
        }
        __syncthreads();
        float sc[32];
        #pragma unroll
        for (int s = 0; s < 32; s++) {
            float d0 = 0.f;
            #pragma unroll
            for (int d = 0; d < HD; d++) d0 += q[d] * Ks[s][d];
            sc[s] = (kb + s <= tl) ? d0 : -1e30f;
        }
        float mn = m;
        #pragma unroll
        for (int s = 0; s < 32; s++) mn = fmaxf(mn, sc[s]);
        float corr = __expf(m - mn);
        l *= corr;
        #pragma unroll
        for (int d = 0; d < HD; d++) o[d] *= corr;
        #pragma unroll
        for (int s = 0; s < 32; s++) {
            float p = __expf(sc[s] - mn);
            l += p;
            #pragma unroll
            for (int d = 0; d < HD; d++) o[d] += p * Vs[s][d];
        }
        m = mn;
        __syncthreads();
    }
    float inv = 1.f / l;
    #pragma unroll
    for (int d = 0; d < HD; d++) {
        float v = o[d] * inv;
        __nv_bfloat16 hi = __float2bfloat16(v);
        size_t idx = (size_t)tok * CDIM + h * HD + d;
        g_attnh[idx] = hi;
        g_attnl[idx] = __float2bfloat16(v - __bfloat162float(hi));
    }
}

// ============================================================
// LN1 + residual: x1 = x + ln(proj); also emit x1 hi/lo bf16
// ============================================================
__global__ void k_ln1(const float* __restrict__ x,
                      const float* __restrict__ g, const float* __restrict__ bsh) {
    int t = blockIdx.x, tid = threadIdx.x;
    __shared__ float rs[256], rss[256];
    float s = 0.f, ss = 0.f;
    for (int c = tid; c < CDIM; c += 256) {
        float v = g_proj[(size_t)t * CDIM + c];
        s += v; ss += v * v;
    }
    rs[tid] = s; rss[tid] = ss;
    __syncthreads();
    for (int off = 128; off > 0; off >>= 1) {
        if (tid < off) { rs[tid] += rs[tid + off]; rss[tid] += rss[tid + off]; }
        __syncthreads();
    }
    float mean = rs[0] * (1.f / CDIM);
    float var = rss[0] * (1.f / CDIM) - mean * mean;
    float rstd = rsqrtf(var + EPS);
    for (int c = tid; c < CDIM; c += 256) {
        float v = (g_proj[(size_t)t * CDIM + c] - mean) * rstd * g[c] + bsh[c];
        float x1 = x[(size_t)t * CDIM + c] + v;
        g_x1[(size_t)t * CDIM + c] = x1;
        __nv_bfloat16 hi = __float2bfloat16(x1);
        g_x1h[(size_t)t * CDIM + c] = hi;
        g_x1l[(size_t)t * CDIM + c] = __float2bfloat16(x1 - __bfloat162float(hi));
    }
}

// ============================================================
// noisy top-2 router
// ============================================================
__global__ void k_router(const float* __restrict__ Wr, const float* __restrict__ br,
                         const float* __restrict__ Wn, const float* __restrict__ bn,
                         const float* __restrict__ noise) {
    int t = blockIdx.x, tid = threadIdx.x;
    float ar[NE], an[NE];
    #pragma unroll
    for (int e = 0; e < NE; e++) { ar[e] = 0.f; an[e] = 0.f; }
    for (int c = tid; c < CDIM; c += 128) {
        float xv = g_x1[(size_t)t * CDIM + c];
        const float4* wr4 = (const float4*)&Wr[c * NE];
        const float4* wn4 = (const float4*)&Wn[c * NE];
        float4 r0 = wr4[0], r1 = wr4[1];
        float4 n0 = wn4[0], n1 = wn4[1];
        ar[0] += xv * r0.x; ar[1] += xv * r0.y; ar[2] += xv * r0.z; ar[3] += xv * r0.w;
        ar[4] += xv * r1.x; ar[5] += xv * r1.y; ar[6] += xv * r1.z; ar[7] += xv * r1.w;
        an[0] += xv * n0.x; an[1] += xv * n0.y; an[2] += xv * n0.z; an[3] += xv * n0.w;
        an[4] += xv * n1.x; an[5] += xv * n1.y; an[6] += xv * n1.z; an[7] += xv * n1.w;
    }
    __shared__ float red[16 * 128];
    #pragma unroll
    for (int e = 0; e < NE; e++) {
        red[e * 128 + tid] = ar[e];
        red[(e + 8) * 128 + tid] = an[e];
    }
    __syncthreads();
    __shared__ float res[16];
    if (tid < 16) {
        float s = 0.f;
        for (int i = 0; i < 128; i++) s += red[tid * 128 + i];
        res[tid] = s;
    }
    __syncthreads();
    if (tid == 0) {
        float noisy[NE];
        #pragma unroll
        for (int e = 0; e < NE; e++) {
            float lg = res[e] + br[e];
            float nl = res[e + 8] + bn[e];
            float sp = (nl > 20.f) ? nl : log1pf(expf(nl));
            noisy[e] = lg + noise[t * NE + e] * sp;
        }
        int i0 = 0; float v0 = noisy[0];
        #pragma unroll
        for (int e = 1; e < NE; e++) if (noisy[e] > v0) { v0 = noisy[e]; i0 = e; }
        int i1 = -1; float v1 = -1e30f;
        #pragma unroll
        for (int e = 0; e < NE; e++)
            if (e != i0 && noisy[e] > v1) { v1 = noisy[e]; i1 = e; }
        float e1 = expf(v1 - v0);
        float denom = 1.f + e1;
        float gate0 = 1.f / denom, gate1 = e1 / denom;
        int s0 = atomicAdd(&g_counts[i0], 1);
        g_list[i0 * NTOK + s0] = t; g_gate[i0 * NTOK + s0] = gate0;
        g_slot[t * 2 + 0] = i0 * NTOK + s0;
        int s1 = atomicAdd(&g_counts[i1], 1);
        g_list[i1 * NTOK + s1] = t; g_gate[i1 * NTOK + s1] = gate1;
        g_slot[t * 2 + 1] = i1 * NTOK + s1;
    }
}

__global__ void k_prefix() {
    if (threadIdx.x == 0 && blockIdx.x == 0) {
        int s = 0;
        for (int e = 0; e < NE; e++) { g_base[e] = s; s += g_counts[e]; }
    }
}

// ============================================================
// combine 2 expert rows + LN2 + residual
// ============================================================
__global__ void k_out(const float* __restrict__ g, const float* __restrict__ bsh,
                      float* __restrict__ out) {
    int t = blockIdx.x, tid = threadIdx.x;
    __shared__ int srow[2];
    if (tid < 2) {
        int slot = g_slot[t * 2 + tid];
        int e = slot / NTOK, r = slot % NTOK;
        srow[tid] = g_base[e] + r;
    }
    __syncthreads();
    const float* eo0 = g_eo + (size_t)srow[0] * CDIM;
    const float* eo1 = g_eo + (size_t)srow[1] * CDIM;

    __shared__ float rs[256], rss[256];
    float s = 0.f, ss = 0.f;
    for (int c = tid; c < CDIM; c += 256) {
        float v = eo0[c] + eo1[c];
        s += v; ss += v * v;
    }
    rs[tid] = s; rss[tid] = ss;
    __syncthreads();
    for (int off = 128; off > 0; off >>= 1) {
        if (tid < off) { rs[tid] += rs[tid + off]; rss[tid] += rss[tid + off]; }
        __syncthreads();
    }
    float mean = rs[0] * (1.f / CDIM);
    float var = rss[0] * (1.f / CDIM) - mean * mean;
    float rstd = rsqrtf(var + EPS);
    for (int c = tid; c < CDIM; c += 256) {
        float v = ((eo0[c] + eo1[c]) - mean) * rstd * g[c] + bsh[c];
        out[(size_t)t * CDIM + c] = g_x1[(size_t)t * CDIM + c] + v;
    }
}

// ============================================================
extern "C" void kernel_launch(void* const* d_in, const int* in_sizes, int n_in,
                              void* d_out, int out_size) {
    const float* x     = (const float*)d_in[0];
    const float* Wq    = (const float*)d_in[1];
    const float* Wk    = (const float*)d_in[2];
    const float* Wv    = (const float*)d_in[3];
    const float* Wo    = (const float*)d_in[4];
    const float* bo    = (const float*)d_in[5];
    const float* ln1_g = (const float*)d_in[6];
    const float* ln1_b = (const float*)d_in[7];
    const float* Wr    = (const float*)d_in[8];
    const float* br    = (const float*)d_in[9];
    const float* Wn    = (const float*)d_in[10];
    const float* bn    = (const float*)d_in[11];
    const float* W1    = (const float*)d_in[12];
    const float* b1    = (const float*)d_in[13];
    const float* W2    = (const float*)d_in[14];
    const float* b2    = (const float*)d_in[15];
    const float* ln2_g = (const float*)d_in[16];
    const float* ln2_b = (const float*)d_in[17];
    const float* noise = (const float*)d_in[18];
    float* out = (float*)d_out;

    cudaFuncSetAttribute(k_gemm, cudaFuncAttributeMaxDynamicSharedMemorySize, SMEM_BYTES);

    k_zero<<<1, 32>>>();
    k_splitx<<<512, 256>>>(x);
    // weight split+transpose: src [z][K][N] -> [z][N][K]; grid (N/64, K/64, z)
    k_split_w<<<dim3(1, 16, 16), 256>>>(Wq, CDIM, HD, (long long)CDIM * HD, (long long)HD * CDIM, 0);
    k_split_w<<<dim3(1, 16, 16), 256>>>(Wk, CDIM, HD, (long long)CDIM * HD, (long long)HD * CDIM, 1);
    k_split_w<<<dim3(1, 16, 16), 256>>>(Wv, CDIM, HD, (long long)CDIM * HD, (long long)HD * CDIM, 2);
    k_split_w<<<dim3(16, 16, 1), 256>>>(Wo, CDIM, CDIM, 0LL, 0LL, 3);
    k_split_w<<<dim3(64, 16, 8), 256>>>(W1, CDIM, FF, (long long)CDIM * FF, (long long)FF * CDIM, 4);
    k_split_w<<<dim3(16, 64, 8), 256>>>(W2, FF, CDIM, (long long)FF * CDIM, (long long)CDIM * FF, 5);

    k_gemm<<<dim3(32, 24, 1), 256, SMEM_BYTES>>>(0, nullptr);     // qkv
    k_attn<<<dim3(TSEQ / 128, NB * NH), 128>>>();
    k_gemm<<<dim3(32, 8, 1), 256, SMEM_BYTES>>>(1, bo);           // out-proj
    k_ln1<<<NTOK, 256>>>(x, ln1_g, ln1_b);
    k_router<<<NTOK, 128>>>(Wr, br, Wn, bn, noise);
    k_prefix<<<1, 1>>>();
    k_gemm<<<dim3(32, 32, NE), 256, SMEM_BYTES>>>(2, b1);         // moe1 + gelu
    k_gemm<<<dim3(32, 8, NE), 256, SMEM_BYTES>>>(3, b2);          // moe2 + gate
    k_out<<<NTOK, 256>>>(ln2_g, ln2_b, out);
}

// round 12
// speedup vs baseline: 2.8778x; 1.3999x over previous
#include <cuda_runtime.h>
#include <cuda_bf16.h>
#include <math.h>
#include <stdint.h>

// ---- fixed problem shapes ----
#define NTOK 4096      // B*T
#define TSEQ 2048
#define NB   2
#define CDIM 1024
#define NH   16
#define HD   64
#define FF   4096
#define NE   8
#define EPS  1e-5f
#define SCALE 0.03125f // C^-0.5 = 1/32

// ============================================================
// scratch (device globals: allocation-free)
// ============================================================
__device__ __align__(128) float g_proj[NTOK * CDIM];
__device__ __align__(128) float g_x1[NTOK * CDIM];
__device__ __align__(128) float g_eo[2 * NTOK * CDIM];
__device__ int   g_counts[NE];
__device__ int   g_base[NE];
__device__ int   g_list[NE * NTOK];
__device__ float g_gate[NE * NTOK];
__device__ int   g_slot[NTOK * 2];

// bf16 hi/lo activation scratch (K-major rows)
__device__ __align__(128) __nv_bfloat16 g_xh[NTOK * CDIM];
__device__ __align__(128) __nv_bfloat16 g_xl[NTOK * CDIM];
__device__ __align__(128) __nv_bfloat16 g_attnh[NTOK * CDIM];
__device__ __align__(128) __nv_bfloat16 g_attnl[NTOK * CDIM];
__device__ __align__(128) __nv_bfloat16 g_x1h[NTOK * CDIM];
__device__ __align__(128) __nv_bfloat16 g_x1l[NTOK * CDIM];
__device__ __align__(128) __nv_bfloat16 g_hh[2 * NTOK * FF];
__device__ __align__(128) __nv_bfloat16 g_hl[2 * NTOK * FF];

// Q/K/V bf16 hi/lo, [b*NH+h][t][d]
__device__ __align__(128) __nv_bfloat16 g_qh[NB * NH * TSEQ * HD];
__device__ __align__(128) __nv_bfloat16 g_ql[NB * NH * TSEQ * HD];
__device__ __align__(128) __nv_bfloat16 g_kh[NB * NH * TSEQ * HD];
__device__ __align__(128) __nv_bfloat16 g_kl[NB * NH * TSEQ * HD];
__device__ __align__(128) __nv_bfloat16 g_vh[NB * NH * TSEQ * HD];
__device__ __align__(128) __nv_bfloat16 g_vl[NB * NH * TSEQ * HD];

// bf16 hi/lo transposed weights (B^T: [N rows][K cols], K-major)
__device__ __align__(128) __nv_bfloat16 g_Wqkvh[3 * CDIM * CDIM];
__device__ __align__(128) __nv_bfloat16 g_Wqkvl[3 * CDIM * CDIM];
__device__ __align__(128) __nv_bfloat16 g_Woh[CDIM * CDIM];
__device__ __align__(128) __nv_bfloat16 g_Wol[CDIM * CDIM];
__device__ __align__(128) __nv_bfloat16 g_W1h[NE * FF * CDIM];
__device__ __align__(128) __nv_bfloat16 g_W1l[NE * FF * CDIM];
__device__ __align__(128) __nv_bfloat16 g_W2h[NE * CDIM * FF];
__device__ __align__(128) __nv_bfloat16 g_W2l[NE * CDIM * FF];

__device__ __forceinline__ uint32_t pack2bf(float a, float b) {
    __nv_bfloat162 t;
    t.x = __float2bfloat16(a);
    t.y = __float2bfloat16(b);
    return *(uint32_t*)&t;
}

// ============================================================
// small kernels
// ============================================================
__global__ void k_zero() {
    if (threadIdx.x < NE) g_counts[threadIdx.x] = 0;
}

__global__ void k_splitx(const float* __restrict__ x) {
    int n4 = NTOK * CDIM / 4;
    for (int i = blockIdx.x * blockDim.x + threadIdx.x; i < n4;
         i += gridDim.x * blockDim.x) {
        float4 v = ((const float4*)x)[i];
        __nv_bfloat16 h0 = __float2bfloat16(v.x);
        __nv_bfloat16 h1 = __float2bfloat16(v.y);
        __nv_bfloat16 h2 = __float2bfloat16(v.z);
        __nv_bfloat16 h3 = __float2bfloat16(v.w);
        uint2 hi, lo;
        hi.x = pack2bf(v.x, v.y); hi.y = pack2bf(v.z, v.w);
        lo.x = pack2bf(v.x - __bfloat162float(h0), v.y - __bfloat162float(h1));
        lo.y = pack2bf(v.z - __bfloat162float(h2), v.w - __bfloat162float(h3));
        ((uint2*)g_xh)[i] = hi;
        ((uint2*)g_xl)[i] = lo;
    }
}

// transpose + split: src [z][K][N] fp32 -> dst [z][N][K] bf16 hi/lo
__global__ void __launch_bounds__(256)
k_split_w(const float* __restrict__ src, int K, int N,
          long long szs, long long dzs, int sel) {
    __nv_bfloat16 *dh, *dl;
    switch (sel) {
        case 0: dh = g_Wqkvh;                   dl = g_Wqkvl;                   break;
        case 1: dh = g_Wqkvh + CDIM * CDIM;     dl = g_Wqkvl + CDIM * CDIM;     break;
        case 2: dh = g_Wqkvh + 2 * CDIM * CDIM; dl = g_Wqkvl + 2 * CDIM * CDIM; break;
        case 3: dh = g_Woh;                     dl = g_Wol;                     break;
        case 4: dh = g_W1h;                     dl = g_W1l;                     break;
        default: dh = g_W2h;                    dl = g_W2l;                     break;
    }
    long long z = blockIdx.z;
    src += z * szs; dh += z * dzs; dl += z * dzs;

    __shared__ float t[64][68];
    int n0 = blockIdx.x * 64, k0 = blockIdx.y * 64;
    int tid = threadIdx.x;
    int tk = tid >> 4;
    int tn4 = (tid & 15) * 4;
    #pragma unroll
    for (int r = 0; r < 4; r++) {
        int k = r * 16 + tk;
        float4 v = *(const float4*)(src + (size_t)(k0 + k) * N + n0 + tn4);
        t[tn4 + 0][k] = v.x;
        t[tn4 + 1][k] = v.y;
        t[tn4 + 2][k] = v.z;
        t[tn4 + 3][k] = v.w;
    }
    __syncthreads();
    int sn = tid >> 2;
    int skg = (tid & 3) * 16;
    float v[16];
    #pragma unroll
    for (int i = 0; i < 16; i += 4) {
        float4 w = *(const float4*)&t[sn][skg + i];
        v[i] = w.x; v[i + 1] = w.y; v[i + 2] = w.z; v[i + 3] = w.w;
    }
    uint32_t hi[8], lo[8];
    #pragma unroll
    for (int j = 0; j < 8; j++) {
        float a = v[2 * j], b = v[2 * j + 1];
        __nv_bfloat16 ha = __float2bfloat16(a);
        __nv_bfloat16 hb = __float2bfloat16(b);
        hi[j] = pack2bf(a, b);
        lo[j] = pack2bf(a - __bfloat162float(ha), b - __bfloat162float(hb));
    }
    size_t off = (size_t)(n0 + sn) * K + k0 + skg;
    *(uint4*)(dh + off)     = make_uint4(hi[0], hi[1], hi[2], hi[3]);
    *(uint4*)(dh + off + 8) = make_uint4(hi[4], hi[5], hi[6], hi[7]);
    *(uint4*)(dl + off)     = make_uint4(lo[0], lo[1], lo[2], lo[3]);
    *(uint4*)(dl + off + 8) = make_uint4(lo[4], lo[5], lo[6], lo[7]);
}

// ============================================================
// mma/ldmatrix/cp.async primitives
// ============================================================
__device__ __forceinline__ void mma16816(float* c, const uint32_t* a, const uint32_t* b) {
    asm volatile(
        "mma.sync.aligned.m16n8k16.row.col.f32.bf16.bf16.f32 "
        "{%0,%1,%2,%3}, {%4,%5,%6,%7}, {%8,%9}, {%0,%1,%2,%3};"
        : "+f"(c[0]), "+f"(c[1]), "+f"(c[2]), "+f"(c[3])
        : "r"(a[0]), "r"(a[1]), "r"(a[2]), "r"(a[3]), "r"(b[0]), "r"(b[1]));
}
__device__ __forceinline__ void ldsm4(uint32_t* r, uint32_t saddr) {
    asm volatile("ldmatrix.sync.aligned.m8n8.x4.shared.b16 {%0,%1,%2,%3}, [%4];"
        : "=r"(r[0]), "=r"(r[1]), "=r"(r[2]), "=r"(r[3]) : "r"(saddr));
}
__device__ __forceinline__ void ldsm4t(uint32_t* r, uint32_t saddr) {
    asm volatile("ldmatrix.sync.aligned.m8n8.x4.trans.shared.b16 {%0,%1,%2,%3}, [%4];"
        : "=r"(r[0]), "=r"(r[1]), "=r"(r[2]), "=r"(r[3]) : "r"(saddr));
}
#define CPASYNC(dst, src) \
    asm volatile("cp.async.cg.shared.global [%0], [%1], 16;" :: "r"(dst), "l"(src))
#define CPCOMMIT() asm volatile("cp.async.commit_group;" ::: "memory")
#define CPWAIT1()  asm volatile("cp.async.wait_group 1;" ::: "memory")

// ============================================================
// unified bf16 split-GEMM (as R10/R11, passing)
// ============================================================
#define SMSTR 72
#define TILE_E (128 * SMSTR)
#define BUF_E (4 * TILE_E)
#define SMEM_BYTES (2 * BUF_E * 2)

__device__ __forceinline__ void stage_load(
    uint32_t sbase, int bufo,
    const __nv_bfloat16* __restrict__ Ah, const __nv_bfloat16* __restrict__ Al,
    const __nv_bfloat16* __restrict__ Bh, const __nv_bfloat16* __restrict__ Bl,
    const int* rows, int n0, int lda, int k0, int tid)
{
    #pragma unroll
    for (int i = 0; i < 4; i++) {
        int c = tid + i * 256;
        int r = c >> 3, col = (c & 7) * 8;
        uint32_t d = sbase + 2 * (bufo + r * SMSTR + col);
        size_t ao = (size_t)rows[r] * lda + k0 + col;
        size_t bo = (size_t)(n0 + r) * lda + k0 + col;
        CPASYNC(d,                Ah + ao);
        CPASYNC(d + 2 * TILE_E,   Al + ao);
        CPASYNC(d + 4 * TILE_E,   Bh + bo);
        CPASYNC(d + 6 * TILE_E,   Bl + bo);
    }
}

__global__ void __launch_bounds__(256, 1)
k_gemm(int mode, const float* __restrict__ bias) {
    extern __shared__ __align__(128) __nv_bfloat16 smem[];
    __shared__ int rows[128];

    int tid = threadIdx.x;
    int lane = tid & 31, wid = tid >> 5;
    int wm = (wid >> 2) * 64;
    int wn = (wid & 3) * 32;
    int qr = lane >> 2;
    int qc = (lane & 3) * 2;
    int e = blockIdx.z;
    int m0 = blockIdx.x * 128, n0 = blockIdx.y * 128;

    const __nv_bfloat16 *Ahp, *Alp, *Bhp, *Blp;
    int lda, K;
    int cnt = 0, base = 0;
    if (mode == 0) {
        Ahp = g_xh; Alp = g_xl; Bhp = g_Wqkvh; Blp = g_Wqkvl;
        lda = CDIM; K = CDIM;
    } else if (mode == 1) {
        Ahp = g_attnh; Alp = g_attnl; Bhp = g_Woh; Blp = g_Wol;
        lda = CDIM; K = CDIM;
    } else if (mode == 2) {
        cnt = g_counts[e]; base = g_base[e];
        if (m0 >= cnt) return;
        Ahp = g_x1h; Alp = g_x1l;
        Bhp = g_W1h + (size_t)e * FF * CDIM; Blp = g_W1l + (size_t)e * FF * CDIM;
        lda = CDIM; K = CDIM;
    } else {
        cnt = g_counts[e]; base = g_base[e];
        if (m0 >= cnt) return;
        Ahp = g_hh; Alp = g_hl;
        Bhp = g_W2h + (size_t)e * CDIM * FF; Blp = g_W2l + (size_t)e * CDIM * FF;
        lda = FF; K = FF;
    }

    if (tid < 128) {
        if (mode == 2) {
            int r = m0 + tid; if (r >= cnt) r = cnt - 1;
            rows[tid] = g_list[e * NTOK + r];
        } else if (mode == 3) {
            int r = m0 + tid; if (r >= cnt) r = cnt - 1;
            rows[tid] = base + r;
        } else {
            rows[tid] = m0 + tid;
        }
    }
    __syncthreads();

    float acc[4][4][4];
    #pragma unroll
    for (int im = 0; im < 4; im++)
        #pragma unroll
        for (int in_ = 0; in_ < 4; in_++)
            #pragma unroll
            for (int q = 0; q < 4; q++) acc[im][in_][q] = 0.f;

    uint32_t sbase;
    asm("{ .reg .u64 t; cvta.to.shared.u64 t, %1; cvt.u32.u64 %0, t; }"
        : "=r"(sbase) : "l"(smem));

    const int NST = K >> 6;
    int a_row = lane & 15, a_col = (lane >> 4) * 8;
    int b_row = (lane & 7) + ((lane >> 4) << 3);
    int b_col = ((lane >> 3) & 1) * 8;

    stage_load(sbase, 0, Ahp, Alp, Bhp, Blp, rows, n0, lda, 0, tid);
    CPCOMMIT();

    for (int kc = 0; kc < NST; kc++) {
        int cbuf = (kc & 1) * BUF_E;
        if (kc + 1 < NST)
            stage_load(sbase, ((kc + 1) & 1) * BUF_E, Ahp, Alp, Bhp, Blp,
                       rows, n0, lda, (kc + 1) << 6, tid);
        CPCOMMIT();
        CPWAIT1();
        __syncthreads();

        #pragma unroll
        for (int ks = 0; ks < 4; ks++) {
            int kb = ks * 16;
            uint32_t ah[4][4], al[4][4], bh[2][4], bl[2][4];
            #pragma unroll
            for (int im = 0; im < 4; im++) {
                uint32_t ad = sbase + 2 * (cbuf + (wm + im * 16 + a_row) * SMSTR + kb + a_col);
                ldsm4(ah[im], ad);
                ldsm4(al[im], ad + 2 * TILE_E);
            }
            #pragma unroll
            for (int ip = 0; ip < 2; ip++) {
                uint32_t bd = sbase + 2 * (cbuf + 2 * TILE_E + (wn + ip * 16 + b_row) * SMSTR + kb + b_col);
                ldsm4(bh[ip], bd);
                ldsm4(bl[ip], bd + 2 * TILE_E);
            }
            #pragma unroll
            for (int im = 0; im < 4; im++) {
                #pragma unroll
                for (int in_ = 0; in_ < 4; in_++) {
                    uint32_t* bhp = &bh[in_ >> 1][(in_ & 1) * 2];
                    uint32_t* blp = &bl[in_ >> 1][(in_ & 1) * 2];
                    mma16816(acc[im][in_], ah[im], bhp);
                    mma16816(acc[im][in_], ah[im], blp);
                    mma16816(acc[im][in_], al[im], bhp);
                }
            }
        }
        __syncthreads();
    }

    #pragma unroll
    for (int im = 0; im < 4; im++) {
        #pragma unroll
        for (int in_ = 0; in_ < 4; in_++) {
            #pragma unroll
            for (int half = 0; half < 2; half++) {
                int ml = wm + im * 16 + qr + half * 8;
                int nl = wn + in_ * 8 + qc;
                float v0 = acc[im][in_][half * 2 + 0];
                float v1 = acc[im][in_][half * 2 + 1];
                if (mode == 0) {
                    int tok = m0 + ml;
                    int col = n0 + nl;
                    int mat = col >> 10, rem = col & 1023;
                    int head = rem >> 6, d = rem & 63;
                    int bb = tok >> 11, t = tok & 2047;
                    size_t idx = ((size_t)(bb * NH + head) * TSEQ + t) * HD + d;
                    __nv_bfloat16 h0 = __float2bfloat16(v0);
                    __nv_bfloat16 h1 = __float2bfloat16(v1);
                    uint32_t hi = pack2bf(v0, v1);
                    uint32_t lo = pack2bf(v0 - __bfloat162float(h0),
                                          v1 - __bfloat162float(h1));
                    if (mat == 0)      { *(uint32_t*)&g_qh[idx] = hi; *(uint32_t*)&g_ql[idx] = lo; }
                    else if (mat == 1) { *(uint32_t*)&g_kh[idx] = hi; *(uint32_t*)&g_kl[idx] = lo; }
                    else               { *(uint32_t*)&g_vh[idx] = hi; *(uint32_t*)&g_vl[idx] = lo; }
                } else if (mode == 1) {
                    int tok = m0 + ml;
                    int col = n0 + nl;
                    *(float2*)&g_proj[(size_t)tok * CDIM + col] =
                        make_float2(v0 + bias[col], v1 + bias[col + 1]);
                } else if (mode == 2) {
                    int r = m0 + ml;
                    if (r < cnt) {
                        int col = n0 + nl;
                        float u0 = v0 + bias[(size_t)e * FF + col];
                        float u1 = v1 + bias[(size_t)e * FF + col + 1];
                        u0 = 0.5f * u0 * (1.0f + erff(u0 * 0.70710678118654752f));
                        u1 = 0.5f * u1 * (1.0f + erff(u1 * 0.70710678118654752f));
                        __nv_bfloat16 h0 = __float2bfloat16(u0);
                        __nv_bfloat16 h1 = __float2bfloat16(u1);
                        size_t o = (size_t)(base + r) * FF + col;
                        *(uint32_t*)&g_hh[o] = pack2bf(u0, u1);
                        *(uint32_t*)&g_hl[o] = pack2bf(u0 - __bfloat162float(h0),
                                                       u1 - __bfloat162float(h1));
                    }
                } else {
                    int r = m0 + ml;
                    if (r < cnt) {
                        int col = n0 + nl;
                        float gate = g_gate[e * NTOK + r];
                        *(float2*)&g_eo[(size_t)(base + r) * CDIM + col] =
                            make_float2((v0 + bias[(size_t)e * CDIM + col]) * gate,
                                        (v1 + bias[(size_t)e * CDIM + col + 1]) * gate);
                    }
                }
            }
        }
    }
}

// ============================================================
// tensor-core flash attention
// block: 128 queries (8 warps x 16 rows), 64-key tiles, HD=64
// ============================================================
#define AQ_E  (128 * 72)       // Q tile elems (hi or lo)
#define AKV_E (64 * 72)        // one kv tile
#define AST_E (4 * AKV_E)      // stage: Kh,Kl,Vh,Vl
#define ASM_BYTES ((2 * AQ_E + 2 * AST_E) * 2)

__device__ __forceinline__ void kv_stage(uint32_t sb, int stage, int bh, int kv0, int tid) {
    uint32_t base = 2 * AQ_E + stage * AST_E;
    const __nv_bfloat16* Kh = g_kh + (size_t)bh * TSEQ * HD;
    const __nv_bfloat16* Kl = g_kl + (size_t)bh * TSEQ * HD;
    const __nv_bfloat16* Vh = g_vh + (size_t)bh * TSEQ * HD;
    const __nv_bfloat16* Vl = g_vl + (size_t)bh * TSEQ * HD;
    #pragma unroll
    for (int i = 0; i < 2; i++) {
        int c = tid + i * 256;
        int r = c >> 3, col = (c & 7) * 8;
        size_t g = (size_t)(kv0 + r) * HD + col;
        uint32_t d = sb + 2 * (base + r * 72 + col);
        CPASYNC(d,              Kh + g);
        CPASYNC(d + 2 * AKV_E,  Kl + g);
        CPASYNC(d + 4 * AKV_E,  Vh + g);
        CPASYNC(d + 6 * AKV_E,  Vl + g);
    }
}

__global__ void __launch_bounds__(256, 1) k_attn2() {
    extern __shared__ __align__(128) __nv_bfloat16 smem_a[];
    int tid = threadIdx.x, lane = tid & 31, w = tid >> 5;
    int bh = blockIdx.y;
    int b = bh >> 4, h = bh & 15;
    int q0 = ((int)gridDim.x - 1 - (int)blockIdx.x) * 128;  // long blocks first

    const __nv_bfloat16* Qh = g_qh + (size_t)bh * TSEQ * HD;
    const __nv_bfloat16* Ql = g_ql + (size_t)bh * TSEQ * HD;

    uint32_t sb;
    asm("{ .reg .u64 t; cvta.to.shared.u64 t, %1; cvt.u32.u64 %0, t; }"
        : "=r"(sb) : "l"(smem_a));

    // Q tiles (hi+lo) via cp.async
    #pragma unroll
    for (int i = 0; i < 4; i++) {
        int c = tid + i * 256;
        int r = c >> 3, col = (c & 7) * 8;
        size_t g = (size_t)(q0 + r) * HD + col;
        CPASYNC(sb + 2 * (r * 72 + col),        Qh + g);
        CPASYNC(sb + 2 * (AQ_E + r * 72 + col), Ql + g);
    }
    kv_stage(sb, 0, bh, 0, tid);
    CPCOMMIT();

    int nkv = q0 / 64 + 2;

    float m0 = -1e30f, m1 = -1e30f, l0 = 0.f, l1 = 0.f;
    float oacc[8][4];
    #pragma unroll
    for (int nf = 0; nf < 8; nf++)
        #pragma unroll
        for (int q = 0; q < 4; q++) oacc[nf][q] = 0.f;

    int qr = lane >> 2, qc = (lane & 3) * 2;
    int r0g = q0 + w * 16 + qr;
    int a_row = lane & 15, a_col = (lane >> 4) * 8;
    int b_row = (lane & 7) + ((lane >> 4) << 3), b_col = ((lane >> 3) & 1) * 8;

    for (int kv = 0; kv < nkv; kv++) {
        int kv0 = kv * 64;
        if (kv + 1 < nkv) kv_stage(sb, (kv + 1) & 1, bh, (kv + 1) * 64, tid);
        CPCOMMIT();
        CPWAIT1();
        __syncthreads();
        uint32_t kvb = 2 * AQ_E + (kv & 1) * AST_E;

        float sacc[8][4];
        #pragma unroll
        for (int nf = 0; nf < 8; nf++)
            #pragma unroll
            for (int q = 0; q < 4; q++) sacc[nf][q] = 0.f;

        // S = Qh*Kh + Ql*Kh + Qh*Kl
        #pragma unroll
        for (int ks = 0; ks < 4; ks++) {
            int kb = ks * 16;
            uint32_t qf[4], qlf[4];
            uint32_t ad = sb + 2 * ((w * 16 + a_row) * 72 + kb + a_col);
            ldsm4(qf, ad);
            ldsm4(qlf, ad + 2 * AQ_E);
            uint32_t kh[4][4], kl[4][4];
            #pragma unroll
            for (int ip = 0; ip < 4; ip++) {
                uint32_t bd = sb + 2 * (kvb + (ip * 16 + b_row) * 72 + kb + b_col);
                ldsm4(kh[ip], bd);
                ldsm4(kl[ip], bd + 2 * AKV_E);
            }
            #pragma unroll
            for (int nf = 0; nf < 8; nf++) {
                uint32_t* bh_ = &kh[nf >> 1][(nf & 1) * 2];
                uint32_t* bl_ = &kl[nf >> 1][(nf & 1) * 2];
                mma16816(sacc[nf], qf, bh_);
                mma16816(sacc[nf], qf, bl_);
                mma16816(sacc[nf], qlf, bh_);
            }
        }

        // scale + causal mask
        bool needmask = (kv0 + 63) > (q0 + w * 16);
        #pragma unroll
        for (int nf = 0; nf < 8; nf++) {
            #pragma unroll
            for (int q = 0; q < 4; q++) {
                float s = sacc[nf][q] * SCALE;
                if (needmask) {
                    int key = kv0 + nf * 8 + qc + (q & 1);
                    int rowg = r0g + (q >> 1) * 8;
                    if (key > rowg) s = -1e30f;
                }
                sacc[nf][q] = s;
            }
        }

        // online softmax
        float rm0 = -1e30f, rm1 = -1e30f;
        #pragma unroll
        for (int nf = 0; nf < 8; nf++) {
            rm0 = fmaxf(rm0, fmaxf(sacc[nf][0], sacc[nf][1]));
            rm1 = fmaxf(rm1, fmaxf(sacc[nf][2], sacc[nf][3]));
        }
        rm0 = fmaxf(rm0, __shfl_xor_sync(0xffffffffu, rm0, 1));
        rm0 = fmaxf(rm0, __shfl_xor_sync(0xffffffffu, rm0, 2));
        rm1 = fmaxf(rm1, __shfl_xor_sync(0xffffffffu, rm1, 1));
        rm1 = fmaxf(rm1, __shfl_xor_sync(0xffffffffu, rm1, 2));
        float mn0 = fmaxf(m0, rm0), mn1 = fmaxf(m1, rm1);
        float f0 = __expf(m0 - mn0), f1 = __expf(m1 - mn1);
        float s0 = 0.f, s1 = 0.f;
        #pragma unroll
        for (int nf = 0; nf < 8; nf++) {
            float p0 = __expf(sacc[nf][0] - mn0);
            float p1 = __expf(sacc[nf][1] - mn0);
            float p2 = __expf(sacc[nf][2] - mn1);
            float p3 = __expf(sacc[nf][3] - mn1);
            sacc[nf][0] = p0; sacc[nf][1] = p1; sacc[nf][2] = p2; sacc[nf][3] = p3;
            s0 += p0 + p1; s1 += p2 + p3;
        }
        s0 += __shfl_xor_sync(0xffffffffu, s0, 1);
        s0 += __shfl_xor_sync(0xffffffffu, s0, 2);
        s1 += __shfl_xor_sync(0xffffffffu, s1, 1);
        s1 += __shfl_xor_sync(0xffffffffu, s1, 2);
        l0 = l0 * f0 + s0;
        l1 = l1 * f1 + s1;
        #pragma unroll
        for (int nf = 0; nf < 8; nf++) {
            oacc[nf][0] *= f0; oacc[nf][1] *= f0;
            oacc[nf][2] *= f1; oacc[nf][3] *= f1;
        }
        m0 = mn0; m1 = mn1;

        // P hi/lo A-fragments (accumulator layout == A layout)
        uint32_t pah[4][4], pal[4][4];
        #pragma unroll
        for (int j = 0; j < 4; j++) {
            float p00 = sacc[2 * j][0],     p01 = sacc[2 * j][1];
            float p02 = sacc[2 * j][2],     p03 = sacc[2 * j][3];
            float p10 = sacc[2 * j + 1][0], p11 = sacc[2 * j + 1][1];
            float p12 = sacc[2 * j + 1][2], p13 = sacc[2 * j + 1][3];
            pah[j][0] = pack2bf(p00, p01);
            pah[j][1] = pack2bf(p02, p03);
            pah[j][2] = pack2bf(p10, p11);
            pah[j][3] = pack2bf(p12, p13);
            pal[j][0] = pack2bf(p00 - __bfloat162float(__float2bfloat16(p00)),
                                p01 - __bfloat162float(__float2bfloat16(p01)));
            pal[j][1] = pack2bf(p02 - __bfloat162float(__float2bfloat16(p02)),
                                p03 - __bfloat162float(__float2bfloat16(p03)));
            pal[j][2] = pack2bf(p10 - __bfloat162float(__float2bfloat16(p10)),
                                p11 - __bfloat162float(__float2bfloat16(p11)));
            pal[j][3] = pack2bf(p12 - __bfloat162float(__float2bfloat16(p12)),
                                p13 - __bfloat162float(__float2bfloat16(p13)));
        }

        // O += Ph*Vh + Ph*Vl + Pl*Vh   (V frags via ldmatrix.trans)
        #pragma unroll
        for (int j = 0; j < 4; j++) {
            uint32_t vh[4][4], vl[4][4];
            #pragma unroll
            for (int ng = 0; ng < 4; ng++) {
                uint32_t va = sb + 2 * (kvb + 2 * AKV_E + (j * 16 + a_row) * 72 + ng * 16 + a_col);
                ldsm4t(vh[ng], va);
                ldsm4t(vl[ng], va + 2 * AKV_E);
            }
            #pragma unroll
            for (int nf = 0; nf < 8; nf++) {
                uint32_t* bvh = &vh[nf >> 1][(nf & 1) * 2];
                uint32_t* bvl = &vl[nf >> 1][(nf & 1) * 2];
                mma16816(oacc[nf], pah[j], bvh);
                mma16816(oacc[nf], pah[j], bvl);
                mma16816(oacc[nf], pal[j], bvh);
            }
        }
        __syncthreads();
    }

    // epilogue: normalize, write g_attnh/l (head-concat layout)
    float inv0 = 1.f / l0, inv1 = 1.f / l1;
    int tok0 = b * TSEQ + r0g;
    #pragma unroll
    for (int nf = 0; nf < 8; nf++) {
        int d = nf * 8 + qc;
        size_t o0 = (size_t)tok0 * CDIM + h * HD + d;
        float u0 = oacc[nf][0] * inv0, u1 = oacc[nf][1] * inv0;
        __nv_bfloat16 h0 = __float2bfloat16(u0);
        __nv_bfloat16 h1 = __float2bfloat16(u1);
        *(uint32_t*)&g_attnh[o0] = pack2bf(u0, u1);
        *(uint32_t*)&g_attnl[o0] = pack2bf(u0 - __bfloat162float(h0),
                                           u1 - __bfloat162float(h1));
        float u2 = oacc[nf][2] * inv1, u3 = oacc[nf][3] * inv1;
        __nv_bfloat16 h2 = __float2bfloat16(u2);
        __nv_bfloat16 h3 = __float2bfloat16(u3);
        size_t o1 = o0 + (size_t)8 * CDIM;
        *(uint32_t*)&g_attnh[o1] = pack2bf(u2, u3);
        *(uint32_t*)&g_attnl[o1] = pack2bf(u2 - __bfloat162float(h2),
                                           u3 - __bfloat162float(h3));
    }
}

// ============================================================
// LN1 + residual
// ============================================================
__global__ void k_ln1(const float* __restrict__ x,
                      const float* __restrict__ g, const float* __restrict__ bsh) {
    int t = blockIdx.x, tid = threadIdx.x;
    __shared__ float rs[256], rss[256];
    float s = 0.f, ss = 0.f;
    for (int c = tid; c < CDIM; c += 256) {
        float v = g_proj[(size_t)t * CDIM + c];
        s += v; ss += v * v;
    }
    rs[tid] = s; rss[tid] = ss;
    __syncthreads();
    for (int off = 128; off > 0; off >>= 1) {
        if (tid < off) { rs[tid] += rs[tid + off]; rss[tid] += rss[tid + off]; }
        __syncthreads();
    }
    float mean = rs[0] * (1.f / CDIM);
    float var = rss[0] * (1.f / CDIM) - mean * mean;
    float rstd = rsqrtf(var + EPS);
    for (int c = tid; c < CDIM; c += 256) {
        float v = (g_proj[(size_t)t * CDIM + c] - mean) * rstd * g[c] + bsh[c];
        float x1 = x[(size_t)t * CDIM + c] + v;
        g_x1[(size_t)t * CDIM + c] = x1;
        __nv_bfloat16 hi = __float2bfloat16(x1);
        g_x1h[(size_t)t * CDIM + c] = hi;
        g_x1l[(size_t)t * CDIM + c] = __float2bfloat16(x1 - __bfloat162float(hi));
    }
}

// ============================================================
// noisy top-2 router
// ============================================================
__global__ void k_router(const float* __restrict__ Wr, const float* __restrict__ br,
                         const float* __restrict__ Wn, const float* __restrict__ bn,
                         const float* __restrict__ noise) {
    int t = blockIdx.x, tid = threadIdx.x;
    float ar[NE], an[NE];
    #pragma unroll
    for (int e = 0; e < NE; e++) { ar[e] = 0.f; an[e] = 0.f; }
    for (int c = tid; c < CDIM; c += 128) {
        float xv = g_x1[(size_t)t * CDIM + c];
        const float4* wr4 = (const float4*)&Wr[c * NE];
        const float4* wn4 = (const float4*)&Wn[c * NE];
        float4 r0 = wr4[0], r1 = wr4[1];
        float4 n0 = wn4[0], n1 = wn4[1];
        ar[0] += xv * r0.x; ar[1] += xv * r0.y; ar[2] += xv * r0.z; ar[3] += xv * r0.w;
        ar[4] += xv * r1.x; ar[5] += xv * r1.y; ar[6] += xv * r1.z; ar[7] += xv * r1.w;
        an[0] += xv * n0.x; an[1] += xv * n0.y; an[2] += xv * n0.z; an[3] += xv * n0.w;
        an[4] += xv * n1.x; an[5] += xv * n1.y; an[6] += xv * n1.z; an[7] += xv * n1.w;
    }
    __shared__ float red[16 * 128];
    #pragma unroll
    for (int e = 0; e < NE; e++) {
        red[e * 128 + tid] = ar[e];
        red[(e + 8) * 128 + tid] = an[e];
    }
    __syncthreads();
    __shared__ float res[16];
    if (tid < 16) {
        float s = 0.f;
        for (int i = 0; i < 128; i++) s += red[tid * 128 + i];
        res[tid] = s;
    }
    __syncthreads();
    if (tid == 0) {
        float noisy[NE];
        #pragma unroll
        for (int e = 0; e < NE; e++) {
            float lg = res[e] + br[e];
            float nl = res[e + 8] + bn[e];
            float sp = (nl > 20.f) ? nl : log1pf(expf(nl));
            noisy[e] = lg + noise[t * NE + e] * sp;
        }
        int i0 = 0; float v0 = noisy[0];
        #pragma unroll
        for (int e = 1; e < NE; e++) if (noisy[e] > v0) { v0 = noisy[e]; i0 = e; }
        int i1 = -1; float v1 = -1e30f;
        #pragma unroll
        for (int e = 0; e < NE; e++)
            if (e != i0 && noisy[e] > v1) { v1 = noisy[e]; i1 = e; }
        float e1 = expf(v1 - v0);
        float denom = 1.f + e1;
        float gate0 = 1.f / denom, gate1 = e1 / denom;
        int s0 = atomicAdd(&g_counts[i0], 1);
        g_list[i0 * NTOK + s0] = t; g_gate[i0 * NTOK + s0] = gate0;
        g_slot[t * 2 + 0] = i0 * NTOK + s0;
        int s1 = atomicAdd(&g_counts[i1], 1);
        g_list[i1 * NTOK + s1] = t; g_gate[i1 * NTOK + s1] = gate1;
        g_slot[t * 2 + 1] = i1 * NTOK + s1;
    }
}

__global__ void k_prefix() {
    if (threadIdx.x == 0 && blockIdx.x == 0) {
        int s = 0;
        for (int e = 0; e < NE; e++) { g_base[e] = s; s += g_counts[e]; }
    }
}

// ============================================================
// combine 2 expert rows + LN2 + residual
// ============================================================
__global__ void k_out(const float* __restrict__ g, const float* __restrict__ bsh,
                      float* __restrict__ out) {
    int t = blockIdx.x, tid = threadIdx.x;
    __shared__ int srow[2];
    if (tid < 2) {
        int slot = g_slot[t * 2 + tid];
        int e = slot / NTOK, r = slot % NTOK;
        srow[tid] = g_base[e] + r;
    }
    __syncthreads();
    const float* eo0 = g_eo + (size_t)srow[0] * CDIM;
    const float* eo1 = g_eo + (size_t)srow[1] * CDIM;

    __shared__ float rs[256], rss[256];
    float s = 0.f, ss = 0.f;
    for (int c = tid; c < CDIM; c += 256) {
        float v = eo0[c] + eo1[c];
        s += v; ss += v * v;
    }
    rs[tid] = s; rss[tid] = ss;
    __syncthreads();
    for (int off = 128; off > 0; off >>= 1) {
        if (tid < off) { rs[tid] += rs[tid + off]; rss[tid] += rss[tid + off]; }
        __syncthreads();
    }
    float mean = rs[0] * (1.f / CDIM);
    float var = rss[0] * (1.f / CDIM) - mean * mean;
    float rstd = rsqrtf(var + EPS);
    for (int c = tid; c < CDIM; c += 256) {
        float v = ((eo0[c] + eo1[c]) - mean) * rstd * g[c] + bsh[c];
        out[(size_t)t * CDIM + c] = g_x1[(size_t)t * CDIM + c] + v;
    }
}

// ============================================================
extern "C" void kernel_launch(void* const* d_in, const int* in_sizes, int n_in,
                              void* d_out, int out_size) {
    const float* x     = (const float*)d_in[0];
    const float* Wq    = (const float*)d_in[1];
    const float* Wk    = (const float*)d_in[2];
    const float* Wv    = (const float*)d_in[3];
    const float* Wo    = (const float*)d_in[4];
    const float* bo    = (const float*)d_in[5];
    const float* ln1_g = (const float*)d_in[6];
    const float* ln1_b = (const float*)d_in[7];
    const float* Wr    = (const float*)d_in[8];
    const float* br    = (const float*)d_in[9];
    const float* Wn    = (const float*)d_in[10];
    const float* bn    = (const float*)d_in[11];
    const float* W1    = (const float*)d_in[12];
    const float* b1    = (const float*)d_in[13];
    const float* W2    = (const float*)d_in[14];
    const float* b2    = (const float*)d_in[15];
    const float* ln2_g = (const float*)d_in[16];
    const float* ln2_b = (const float*)d_in[17];
    const float* noise = (const float*)d_in[18];
    float* out = (float*)d_out;

    cudaFuncSetAttribute(k_gemm, cudaFuncAttributeMaxDynamicSharedMemorySize, SMEM_BYTES);
    cudaFuncSetAttribute(k_attn2, cudaFuncAttributeMaxDynamicSharedMemorySize, ASM_BYTES);

    k_zero<<<1, 32>>>();
    k_splitx<<<512, 256>>>(x);
    k_split_w<<<dim3(1, 16, 16), 256>>>(Wq, CDIM, HD, (long long)CDIM * HD, (long long)HD * CDIM, 0);
    k_split_w<<<dim3(1, 16, 16), 256>>>(Wk, CDIM, HD, (long long)CDIM * HD, (long long)HD * CDIM, 1);
    k_split_w<<<dim3(1, 16, 16), 256>>>(Wv, CDIM, HD, (long long)CDIM * HD, (long long)HD * CDIM, 2);
    k_split_w<<<dim3(16, 16, 1), 256>>>(Wo, CDIM, CDIM, 0LL, 0LL, 3);
    k_split_w<<<dim3(64, 16, 8), 256>>>(W1, CDIM, FF, (long long)CDIM * FF, (long long)FF * CDIM, 4);
    k_split_w<<<dim3(16, 64, 8), 256>>>(W2, FF, CDIM, (long long)FF * CDIM, (long long)CDIM * FF, 5);

    k_gemm<<<dim3(32, 24, 1), 256, SMEM_BYTES>>>(0, nullptr);     // qkv -> bf16 hi/lo QKV
    k_attn2<<<dim3(TSEQ / 128, NB * NH), 256, ASM_BYTES>>>();     // tensor-core flash attn
    k_gemm<<<dim3(32, 8, 1), 256, SMEM_BYTES>>>(1, bo);           // out-proj
    k_ln1<<<NTOK, 256>>>(x, ln1_g, ln1_b);
    k_router<<<NTOK, 128>>>(Wr, br, Wn, bn, noise);
    k_prefix<<<1, 1>>>();
    k_gemm<<<dim3(32, 32, NE), 256, SMEM_BYTES>>>(2, b1);         // moe1 + gelu
    k_gemm<<<dim3(32, 8, NE), 256, SMEM_BYTES>>>(3, b2);          // moe2 + gate
    k_out<<<NTOK, 256>>>(ln2_g, ln2_b, out);
}

// round 14
// speedup vs baseline: 2.9045x; 1.0093x over previous
#include <cuda_runtime.h>
#include <cuda_bf16.h>
#include <math.h>
#include <stdint.h>

// ---- fixed problem shapes ----
#define NTOK 4096      // B*T
#define TSEQ 2048
#define NB   2
#define CDIM 1024
#define NH   16
#define HD   64
#define FF   4096
#define NE   8
#define EPS  1e-5f
#define SCALE 0.03125f // C^-0.5 = 1/32

// ============================================================
// scratch (device globals: allocation-free)
// ============================================================
__device__ __align__(128) float g_proj[NTOK * CDIM];
__device__ __align__(128) float g_x1[NTOK * CDIM];
__device__ __align__(128) float g_eo[2 * NTOK * CDIM];
__device__ int   g_counts[NE];
__device__ int   g_base[NE];
__device__ int   g_list[NE * NTOK];
__device__ float g_gate[NE * NTOK];
__device__ int   g_slot[NTOK * 2];

// bf16 hi/lo activation scratch (K-major rows)
__device__ __align__(128) __nv_bfloat16 g_xh[NTOK * CDIM];
__device__ __align__(128) __nv_bfloat16 g_xl[NTOK * CDIM];
__device__ __align__(128) __nv_bfloat16 g_attnh[NTOK * CDIM];
__device__ __align__(128) __nv_bfloat16 g_attnl[NTOK * CDIM];
__device__ __align__(128) __nv_bfloat16 g_x1h[NTOK * CDIM];
__device__ __align__(128) __nv_bfloat16 g_x1l[NTOK * CDIM];
__device__ __align__(128) __nv_bfloat16 g_hh[2 * NTOK * FF];
__device__ __align__(128) __nv_bfloat16 g_hl[2 * NTOK * FF];

// Q/K/V bf16 hi/lo, [b*NH+h][t][d]
__device__ __align__(128) __nv_bfloat16 g_qh[NB * NH * TSEQ * HD];
__device__ __align__(128) __nv_bfloat16 g_ql[NB * NH * TSEQ * HD];
__device__ __align__(128) __nv_bfloat16 g_kh[NB * NH * TSEQ * HD];
__device__ __align__(128) __nv_bfloat16 g_kl[NB * NH * TSEQ * HD];
__device__ __align__(128) __nv_bfloat16 g_vh[NB * NH * TSEQ * HD];
__device__ __align__(128) __nv_bfloat16 g_vl[NB * NH * TSEQ * HD];

// bf16 hi/lo weights in NATURAL [K][N]-style layouts (no transpose):
// g_Wqkvh: [mat][head][C][HD]   (mat*2^20 + head*65536 + c*64 + d)
// g_Woh:   [C][C]
// g_W1h:   [e][C][FF]
// g_W2h:   [e][FF][C]
__device__ __align__(128) __nv_bfloat16 g_Wqkvh[3 * CDIM * CDIM];
__device__ __align__(128) __nv_bfloat16 g_Wqkvl[3 * CDIM * CDIM];
__device__ __align__(128) __nv_bfloat16 g_Woh[CDIM * CDIM];
__device__ __align__(128) __nv_bfloat16 g_Wol[CDIM * CDIM];
__device__ __align__(128) __nv_bfloat16 g_W1h[NE * CDIM * FF];
__device__ __align__(128) __nv_bfloat16 g_W1l[NE * CDIM * FF];
__device__ __align__(128) __nv_bfloat16 g_W2h[NE * FF * CDIM];
__device__ __align__(128) __nv_bfloat16 g_W2l[NE * FF * CDIM];

__device__ __forceinline__ uint32_t pack2bf(float a, float b) {
    __nv_bfloat162 t;
    t.x = __float2bfloat16(a);
    t.y = __float2bfloat16(b);
    return *(uint32_t*)&t;
}

// ============================================================
// small kernels
// ============================================================
__global__ void k_zero() {
    if (threadIdx.x < NE) g_counts[threadIdx.x] = 0;
}

__global__ void k_splitx(const float* __restrict__ x) {
    int n4 = NTOK * CDIM / 4;
    for (int i = blockIdx.x * blockDim.x + threadIdx.x; i < n4;
         i += gridDim.x * blockDim.x) {
        float4 v = ((const float4*)x)[i];
        __nv_bfloat16 h0 = __float2bfloat16(v.x);
        __nv_bfloat16 h1 = __float2bfloat16(v.y);
        __nv_bfloat16 h2 = __float2bfloat16(v.z);
        __nv_bfloat16 h3 = __float2bfloat16(v.w);
        uint2 hi, lo;
        hi.x = pack2bf(v.x, v.y); hi.y = pack2bf(v.z, v.w);
        lo.x = pack2bf(v.x - __bfloat162float(h0), v.y - __bfloat162float(h1));
        lo.y = pack2bf(v.z - __bfloat162float(h2), v.w - __bfloat162float(h3));
        ((uint2*)g_xh)[i] = hi;
        ((uint2*)g_xl)[i] = lo;
    }
}

// streaming fp32 -> bf16 hi/lo split, layout-preserving (no transpose)
__global__ void k_split_flat(const float* __restrict__ src, int sel, int n4) {
    __nv_bfloat16 *dh, *dl;
    switch (sel) {
        case 0: dh = g_Wqkvh;                 dl = g_Wqkvl;                 break;
        case 1: dh = g_Wqkvh + (1 << 20);     dl = g_Wqkvl + (1 << 20);     break;
        case 2: dh = g_Wqkvh + (2 << 20);     dl = g_Wqkvl + (2 << 20);     break;
        case 3: dh = g_Woh;                   dl = g_Wol;                   break;
        case 4: dh = g_W1h;                   dl = g_W1l;                   break;
        default: dh = g_W2h;                  dl = g_W2l;                   break;
    }
    for (int i = blockIdx.x * blockDim.x + threadIdx.x; i < n4;
         i += gridDim.x * blockDim.x) {
        float4 v = ((const float4*)src)[i];
        __nv_bfloat16 h0 = __float2bfloat16(v.x);
        __nv_bfloat16 h1 = __float2bfloat16(v.y);
        __nv_bfloat16 h2 = __float2bfloat16(v.z);
        __nv_bfloat16 h3 = __float2bfloat16(v.w);
        uint2 hi, lo;
        hi.x = pack2bf(v.x, v.y); hi.y = pack2bf(v.z, v.w);
        lo.x = pack2bf(v.x - __bfloat162float(h0), v.y - __bfloat162float(h1));
        lo.y = pack2bf(v.z - __bfloat162float(h2), v.w - __bfloat162float(h3));
        ((uint2*)dh)[i] = hi;
        ((uint2*)dl)[i] = lo;
    }
}

// ============================================================
// mma/ldmatrix/cp.async primitives
// ============================================================
__device__ __forceinline__ void mma16816(float* c, const uint32_t* a, const uint32_t* b) {
    asm volatile(
        "mma.sync.aligned.m16n8k16.row.col.f32.bf16.bf16.f32 "
        "{%0,%1,%2,%3}, {%4,%5,%6,%7}, {%8,%9}, {%0,%1,%2,%3};"
        : "+f"(c[0]), "+f"(c[1]), "+f"(c[2]), "+f"(c[3])
        : "r"(a[0]), "r"(a[1]), "r"(a[2]), "r"(a[3]), "r"(b[0]), "r"(b[1]));
}
__device__ __forceinline__ void ldsm4(uint32_t* r, uint32_t saddr) {
    asm volatile("ldmatrix.sync.aligned.m8n8.x4.shared.b16 {%0,%1,%2,%3}, [%4];"
        : "=r"(r[0]), "=r"(r[1]), "=r"(r[2]), "=r"(r[3]) : "r"(saddr));
}
__device__ __forceinline__ void ldsm4t(uint32_t* r, uint32_t saddr) {
    asm volatile("ldmatrix.sync.aligned.m8n8.x4.trans.shared.b16 {%0,%1,%2,%3}, [%4];"
        : "=r"(r[0]), "=r"(r[1]), "=r"(r[2]), "=r"(r[3]) : "r"(saddr));
}
#define CPASYNC(dst, src) \
    asm volatile("cp.async.cg.shared.global [%0], [%1], 16;" :: "r"(dst), "l"(src))
#define CPCOMMIT() asm volatile("cp.async.commit_group;" ::: "memory")
#define CPWAIT1()  asm volatile("cp.async.wait_group 1;" ::: "memory")

// ============================================================
// unified bf16 split-GEMM
// A: [128 m][64 k] per stage (gathered rows, hi+lo)
// B: [64 k][128 n] per stage (k-major natural weight layout, hi+lo)
//    fragments via ldmatrix.trans (proven by attention P*V path)
// ============================================================
#define ASTR 72
#define A_TILE_E (128 * ASTR)            // 9216
#define BSTR 136
#define B_TILE_E (64 * BSTR)             // 8704
#define GBUF_E (2 * A_TILE_E + 2 * B_TILE_E)   // 35840
#define SMEM_BYTES (2 * GBUF_E * 2)            // 143360

__device__ __forceinline__ void stage_load(
    uint32_t sbase, int bufo, int mode,
    const __nv_bfloat16* __restrict__ Ah, const __nv_bfloat16* __restrict__ Al,
    const __nv_bfloat16* __restrict__ Bh, const __nv_bfloat16* __restrict__ Bl,
    const int* rows, int n0, int lda, int ldbN, int k0, int tid)
{
    // A: 128 rows x 64 k
    #pragma unroll
    for (int i = 0; i < 4; i++) {
        int c = tid + i * 256;
        int r = c >> 3, col = (c & 7) * 8;
        uint32_t d = sbase + 2 * (bufo + r * ASTR + col);
        size_t ao = (size_t)rows[r] * lda + k0 + col;
        CPASYNC(d,                Ah + ao);
        CPASYNC(d + 2 * A_TILE_E, Al + ao);
    }
    // B: 64 k-rows x 128 n
    #pragma unroll
    for (int i = 0; i < 4; i++) {
        int c = tid + i * 256;
        int r = c >> 4, col = (c & 15) * 8;
        uint32_t d = sbase + 2 * (bufo + 2 * A_TILE_E + r * BSTR + col);
        size_t off;
        if (mode == 0) {
            int n = n0 + col;
            int mat = n >> 10, rem = n & 1023;
            int head = rem >> 6, dd = rem & 63;
            off = ((size_t)mat << 20) + (size_t)head * 65536 + (size_t)(k0 + r) * 64 + dd;
        } else {
            off = (size_t)(k0 + r) * ldbN + n0 + col;
        }
        CPASYNC(d,                Bh + off);
        CPASYNC(d + 2 * B_TILE_E, Bl + off);
    }
}

__global__ void __launch_bounds__(256, 1)
k_gemm(int mode, const float* __restrict__ bias) {
    extern __shared__ __align__(128) __nv_bfloat16 smem[];
    __shared__ int rows[128];

    int tid = threadIdx.x;
    int lane = tid & 31, wid = tid >> 5;
    int wm = (wid >> 2) * 64;
    int wn = (wid & 3) * 32;
    int qr = lane >> 2;
    int qc = (lane & 3) * 2;
    int e = blockIdx.z;
    int m0 = blockIdx.x * 128, n0 = blockIdx.y * 128;

    const __nv_bfloat16 *Ahp, *Alp, *Bhp, *Blp;
    int lda, ldbN, K;
    int cnt = 0, base = 0;
    if (mode == 0) {
        Ahp = g_xh; Alp = g_xl; Bhp = g_Wqkvh; Blp = g_Wqkvl;
        lda = CDIM; ldbN = 0; K = CDIM;
    } else if (mode == 1) {
        Ahp = g_attnh; Alp = g_attnl; Bhp = g_Woh; Blp = g_Wol;
        lda = CDIM; ldbN = CDIM; K = CDIM;
    } else if (mode == 2) {
        cnt = g_counts[e]; base = g_base[e];
        if (m0 >= cnt) return;
        Ahp = g_x1h; Alp = g_x1l;
        Bhp = g_W1h + (size_t)e * CDIM * FF; Blp = g_W1l + (size_t)e * CDIM * FF;
        lda = CDIM; ldbN = FF; K = CDIM;
    } else {
        cnt = g_counts[e]; base = g_base[e];
        if (m0 >= cnt) return;
        Ahp = g_hh; Alp = g_hl;
        Bhp = g_W2h + (size_t)e * FF * CDIM; Blp = g_W2l + (size_t)e * FF * CDIM;
        lda = FF; ldbN = CDIM; K = FF;
    }

    if (tid < 128) {
        if (mode == 2) {
            int r = m0 + tid; if (r >= cnt) r = cnt - 1;
            rows[tid] = g_list[e * NTOK + r];
        } else if (mode == 3) {
            int r = m0 + tid; if (r >= cnt) r = cnt - 1;
            rows[tid] = base + r;
        } else {
            rows[tid] = m0 + tid;
        }
    }
    __syncthreads();

    float acc[4][4][4];
    #pragma unroll
    for (int im = 0; im < 4; im++)
        #pragma unroll
        for (int in_ = 0; in_ < 4; in_++)
            #pragma unroll
            for (int q = 0; q < 4; q++) acc[im][in_][q] = 0.f;

    uint32_t sbase;
    asm("{ .reg .u64 t; cvta.to.shared.u64 t, %1; cvt.u32.u64 %0, t; }"
        : "=r"(sbase) : "l"(smem));

    const int NST = K >> 6;
    int a_row = lane & 15, a_col = (lane >> 4) * 8;

    stage_load(sbase, 0, mode, Ahp, Alp, Bhp, Blp, rows, n0, lda, ldbN, 0, tid);
    CPCOMMIT();

    for (int kc = 0; kc < NST; kc++) {
        int cbuf = (kc & 1) * GBUF_E;
        if (kc + 1 < NST)
            stage_load(sbase, ((kc + 1) & 1) * GBUF_E, mode, Ahp, Alp, Bhp, Blp,
                       rows, n0, lda, ldbN, (kc + 1) << 6, tid);
        CPCOMMIT();
        CPWAIT1();
        __syncthreads();

        #pragma unroll
        for (int ks = 0; ks < 4; ks++) {
            int kb = ks * 16;
            uint32_t ah[4][4], al[4][4], bh[2][4], bl[2][4];
            #pragma unroll
            for (int im = 0; im < 4; im++) {
                uint32_t ad = sbase + 2 * (cbuf + (wm + im * 16 + a_row) * ASTR + kb + a_col);
                ldsm4(ah[im], ad);
                ldsm4(al[im], ad + 2 * A_TILE_E);
            }
            #pragma unroll
            for (int ip = 0; ip < 2; ip++) {
                uint32_t bd = sbase + 2 * (cbuf + 2 * A_TILE_E +
                                           (kb + a_row) * BSTR + wn + ip * 16 + a_col);
                ldsm4t(bh[ip], bd);
                ldsm4t(bl[ip], bd + 2 * B_TILE_E);
            }
            #pragma unroll
            for (int im = 0; im < 4; im++) {
                #pragma unroll
                for (int in_ = 0; in_ < 4; in_++) {
                    uint32_t* bhp = &bh[in_ >> 1][(in_ & 1) * 2];
                    uint32_t* blp = &bl[in_ >> 1][(in_ & 1) * 2];
                    mma16816(acc[im][in_], ah[im], bhp);
                    mma16816(acc[im][in_], ah[im], blp);
                    mma16816(acc[im][in_], al[im], bhp);
                }
            }
        }
        __syncthreads();
    }

    #pragma unroll
    for (int im = 0; im < 4; im++) {
        #pragma unroll
        for (int in_ = 0; in_ < 4; in_++) {
            #pragma unroll
            for (int half = 0; half < 2; half++) {
                int ml = wm + im * 16 + qr + half * 8;
                int nl = wn + in_ * 8 + qc;
                float v0 = acc[im][in_][half * 2 + 0];
                float v1 = acc[im][in_][half * 2 + 1];
                if (mode == 0) {
                    int tok = m0 + ml;
                    int col = n0 + nl;
                    int mat = col >> 10, rem = col & 1023;
                    int head = rem >> 6, d = rem & 63;
                    int bb = tok >> 11, t = tok & 2047;
                    size_t idx = ((size_t)(bb * NH + head) * TSEQ + t) * HD + d;
                    __nv_bfloat16 h0 = __float2bfloat16(v0);
                    __nv_bfloat16 h1 = __float2bfloat16(v1);
                    uint32_t hi = pack2bf(v0, v1);
                    uint32_t lo = pack2bf(v0 - __bfloat162float(h0),
                                          v1 - __bfloat162float(h1));
                    if (mat == 0)      { *(uint32_t*)&g_qh[idx] = hi; *(uint32_t*)&g_ql[idx] = lo; }
                    else if (mat == 1) { *(uint32_t*)&g_kh[idx] = hi; *(uint32_t*)&g_kl[idx] = lo; }
                    else               { *(uint32_t*)&g_vh[idx] = hi; *(uint32_t*)&g_vl[idx] = lo; }
                } else if (mode == 1) {
                    int tok = m0 + ml;
                    int col = n0 + nl;
                    *(float2*)&g_proj[(size_t)tok * CDIM + col] =
                        make_float2(v0 + bias[col], v1 + bias[col + 1]);
                } else if (mode == 2) {
                    int r = m0 + ml;
                    if (r < cnt) {
                        int col = n0 + nl;
                        float u0 = v0 + bias[(size_t)e * FF + col];
                        float u1 = v1 + bias[(size_t)e * FF + col + 1];
                        u0 = 0.5f * u0 * (1.0f + erff(u0 * 0.70710678118654752f));
                        u1 = 0.5f * u1 * (1.0f + erff(u1 * 0.70710678118654752f));
                        __nv_bfloat16 h0 = __float2bfloat16(u0);
                        __nv_bfloat16 h1 = __float2bfloat16(u1);
                        size_t o = (size_t)(base + r) * FF + col;
                        *(uint32_t*)&g_hh[o] = pack2bf(u0, u1);
                        *(uint32_t*)&g_hl[o] = pack2bf(u0 - __bfloat162float(h0),
                                                       u1 - __bfloat162float(h1));
                    }
                } else {
                    int r = m0 + ml;
                    if (r < cnt) {
                        int col = n0 + nl;
                        float gate = g_gate[e * NTOK + r];
                        *(float2*)&g_eo[(size_t)(base + r) * CDIM + col] =
                            make_float2((v0 + bias[(size_t)e * CDIM + col]) * gate,
                                        (v1 + bias[(size_t)e * CDIM + col + 1]) * gate);
                    }
                }
            }
        }
    }
}

// ============================================================
// tensor-core flash attention (as R12, passing)
// ============================================================
#define AQ_E  (128 * 72)
#define AKV_E (64 * 72)
#define AST_E (4 * AKV_E)
#define ASM_BYTES ((2 * AQ_E + 2 * AST_E) * 2)

__device__ __forceinline__ void kv_stage(uint32_t sb, int stage, int bh, int kv0, int tid) {
    uint32_t base = 2 * AQ_E + stage * AST_E;
    const __nv_bfloat16* Kh = g_kh + (size_t)bh * TSEQ * HD;
    const __nv_bfloat16* Kl = g_kl + (size_t)bh * TSEQ * HD;
    const __nv_bfloat16* Vh = g_vh + (size_t)bh * TSEQ * HD;
    const __nv_bfloat16* Vl = g_vl + (size_t)bh * TSEQ * HD;
    #pragma unroll
    for (int i = 0; i < 2; i++) {
        int c = tid + i * 256;
        int r = c >> 3, col = (c & 7) * 8;
        size_t g = (size_t)(kv0 + r) * HD + col;
        uint32_t d = sb + 2 * (base + r * 72 + col);
        CPASYNC(d,              Kh + g);
        CPASYNC(d + 2 * AKV_E,  Kl + g);
        CPASYNC(d + 4 * AKV_E,  Vh + g);
        CPASYNC(d + 6 * AKV_E,  Vl + g);
    }
}

__global__ void __launch_bounds__(256, 1) k_attn2() {
    extern __shared__ __align__(128) __nv_bfloat16 smem_a[];
    int tid = threadIdx.x, lane = tid & 31, w = tid >> 5;
    int bh = blockIdx.y;
    int b = bh >> 4, h = bh & 15;
    int q0 = ((int)gridDim.x - 1 - (int)blockIdx.x) * 128;

    const __nv_bfloat16* Qh = g_qh + (size_t)bh * TSEQ * HD;
    const __nv_bfloat16* Ql = g_ql + (size_t)bh * TSEQ * HD;

    uint32_t sb;
    asm("{ .reg .u64 t; cvta.to.shared.u64 t, %1; cvt.u32.u64 %0, t; }"
        : "=r"(sb) : "l"(smem_a));

    #pragma unroll
    for (int i = 0; i < 4; i++) {
        int c = tid + i * 256;
        int r = c >> 3, col = (c & 7) * 8;
        size_t g = (size_t)(q0 + r) * HD + col;
        CPASYNC(sb + 2 * (r * 72 + col),        Qh + g);
        CPASYNC(sb + 2 * (AQ_E + r * 72 + col), Ql + g);
    }
    kv_stage(sb, 0, bh, 0, tid);
    CPCOMMIT();

    int nkv = q0 / 64 + 2;

    float m0 = -1e30f, m1 = -1e30f, l0 = 0.f, l1 = 0.f;
    float oacc[8][4];
    #pragma unroll
    for (int nf = 0; nf < 8; nf++)
        #pragma unroll
        for (int q = 0; q < 4; q++) oacc[nf][q] = 0.f;

    int qr = lane >> 2, qc = (lane & 3) * 2;
    int r0g = q0 + w * 16 + qr;
    int a_row = lane & 15, a_col = (lane >> 4) * 8;
    int b_row = (lane & 7) + ((lane >> 4) << 3), b_col = ((lane >> 3) & 1) * 8;

    for (int kv = 0; kv < nkv; kv++) {
        int kv0 = kv * 64;
        if (kv + 1 < nkv) kv_stage(sb, (kv + 1) & 1, bh, (kv + 1) * 64, tid);
        CPCOMMIT();
        CPWAIT1();
        __syncthreads();
        uint32_t kvb = 2 * AQ_E + (kv & 1) * AST_E;

        float sacc[8][4];
        #pragma unroll
        for (int nf = 0; nf < 8; nf++)
            #pragma unroll
            for (int q = 0; q < 4; q++) sacc[nf][q] = 0.f;

        #pragma unroll
        for (int ks = 0; ks < 4; ks++) {
            int kb = ks * 16;
            uint32_t qf[4], qlf[4];
            uint32_t ad = sb + 2 * ((w * 16 + a_row) * 72 + kb + a_col);
            ldsm4(qf, ad);
            ldsm4(qlf, ad + 2 * AQ_E);
            uint32_t kh[4][4], kl[4][4];
            #pragma unroll
            for (int ip = 0; ip < 4; ip++) {
                uint32_t bd = sb + 2 * (kvb + (ip * 16 + b_row) * 72 + kb + b_col);
                ldsm4(kh[ip], bd);
                ldsm4(kl[ip], bd + 2 * AKV_E);
            }
            #pragma unroll
            for (int nf = 0; nf < 8; nf++) {
                uint32_t* bh_ = &kh[nf >> 1][(nf & 1) * 2];
                uint32_t* bl_ = &kl[nf >> 1][(nf & 1) * 2];
                mma16816(sacc[nf], qf, bh_);
                mma16816(sacc[nf], qf, bl_);
                mma16816(sacc[nf], qlf, bh_);
            }
        }

        bool needmask = (kv0 + 63) > (q0 + w * 16);
        #pragma unroll
        for (int nf = 0; nf < 8; nf++) {
            #pragma unroll
            for (int q = 0; q < 4; q++) {
                float s = sacc[nf][q] * SCALE;
                if (needmask) {
                    int key = kv0 + nf * 8 + qc + (q & 1);
                    int rowg = r0g + (q >> 1) * 8;
                    if (key > rowg) s = -1e30f;
                }
                sacc[nf][q] = s;
            }
        }

        float rm0 = -1e30f, rm1 = -1e30f;
        #pragma unroll
        for (int nf = 0; nf < 8; nf++) {
            rm0 = fmaxf(rm0, fmaxf(sacc[nf][0], sacc[nf][1]));
            rm1 = fmaxf(rm1, fmaxf(sacc[nf][2], sacc[nf][3]));
        }
        rm0 = fmaxf(rm0, __shfl_xor_sync(0xffffffffu, rm0, 1));
        rm0 = fmaxf(rm0, __shfl_xor_sync(0xffffffffu, rm0, 2));
        rm1 = fmaxf(rm1, __shfl_xor_sync(0xffffffffu, rm1, 1));
        rm1 = fmaxf(rm1, __shfl_xor_sync(0xffffffffu, rm1, 2));
        float mn0 = fmaxf(m0, rm0), mn1 = fmaxf(m1, rm1);
        float f0 = __expf(m0 - mn0), f1 = __expf(m1 - mn1);
        float s0 = 0.f, s1 = 0.f;
        #pragma unroll
        for (int nf = 0; nf < 8; nf++) {
            float p0 = __expf(sacc[nf][0] - mn0);
            float p1 = __expf(sacc[nf][1] - mn0);
            float p2 = __expf(sacc[nf][2] - mn1);
            float p3 = __expf(sacc[nf][3] - mn1);
            sacc[nf][0] = p0; sacc[nf][1] = p1; sacc[nf][2] = p2; sacc[nf][3] = p3;
            s0 += p0 + p1; s1 += p2 + p3;
        }
        s0 += __shfl_xor_sync(0xffffffffu, s0, 1);
        s0 += __shfl_xor_sync(0xffffffffu, s0, 2);
        s1 += __shfl_xor_sync(0xffffffffu, s1, 1);
        s1 += __shfl_xor_sync(0xffffffffu, s1, 2);
        l0 = l0 * f0 + s0;
        l1 = l1 * f1 + s1;
        #pragma unroll
        for (int nf = 0; nf < 8; nf++) {
            oacc[nf][0] *= f0; oacc[nf][1] *= f0;
            oacc[nf][2] *= f1; oacc[nf][3] *= f1;
        }
        m0 = mn0; m1 = mn1;

        uint32_t pah[4][4], pal[4][4];
        #pragma unroll
        for (int j = 0; j < 4; j++) {
            float p00 = sacc[2 * j][0],     p01 = sacc[2 * j][1];
            float p02 = sacc[2 * j][2],     p03 = sacc[2 * j][3];
            float p10 = sacc[2 * j + 1][0], p11 = sacc[2 * j + 1][1];
            float p12 = sacc[2 * j + 1][2], p13 = sacc[2 * j + 1][3];
            pah[j][0] = pack2bf(p00, p01);
            pah[j][1] = pack2bf(p02, p03);
            pah[j][2] = pack2bf(p10, p11);
            pah[j][3] = pack2bf(p12, p13);
            pal[j][0] = pack2bf(p00 - __bfloat162float(__float2bfloat16(p00)),
                                p01 - __bfloat162float(__float2bfloat16(p01)));
            pal[j][1] = pack2bf(p02 - __bfloat162float(__float2bfloat16(p02)),
                                p03 - __bfloat162float(__float2bfloat16(p03)));
            pal[j][2] = pack2bf(p10 - __bfloat162float(__float2bfloat16(p10)),
                                p11 - __bfloat162float(__float2bfloat16(p11)));
            pal[j][3] = pack2bf(p12 - __bfloat162float(__float2bfloat16(p12)),
                                p13 - __bfloat162float(__float2bfloat16(p13)));
        }

        #pragma unroll
        for (int j = 0; j < 4; j++) {
            uint32_t vh[4][4], vl[4][4];
            #pragma unroll
            for (int ng = 0; ng < 4; ng++) {
                uint32_t va = sb + 2 * (kvb + 2 * AKV_E + (j * 16 + a_row) * 72 + ng * 16 + a_col);
                ldsm4t(vh[ng], va);
                ldsm4t(vl[ng], va + 2 * AKV_E);
            }
            #pragma unroll
            for (int nf = 0; nf < 8; nf++) {
                uint32_t* bvh = &vh[nf >> 1][(nf & 1) * 2];
                uint32_t* bvl = &vl[nf >> 1][(nf & 1) * 2];
                mma16816(oacc[nf], pah[j], bvh);
                mma16816(oacc[nf], pah[j], bvl);
                mma16816(oacc[nf], pal[j], bvh);
            }
        }
        __syncthreads();
    }

    float inv0 = 1.f / l0, inv1 = 1.f / l1;
    int tok0 = b * TSEQ + r0g;
    #pragma unroll
    for (int nf = 0; nf < 8; nf++) {
        int d = nf * 8 + qc;
        size_t o0 = (size_t)tok0 * CDIM + h * HD + d;
        float u0 = oacc[nf][0] * inv0, u1 = oacc[nf][1] * inv0;
        __nv_bfloat16 h0 = __float2bfloat16(u0);
        __nv_bfloat16 h1 = __float2bfloat16(u1);
        *(uint32_t*)&g_attnh[o0] = pack2bf(u0, u1);
        *(uint32_t*)&g_attnl[o0] = pack2bf(u0 - __bfloat162float(h0),
                                           u1 - __bfloat162float(h1));
        float u2 = oacc[nf][2] * inv1, u3 = oacc[nf][3] * inv1;
        __nv_bfloat16 h2 = __float2bfloat16(u2);
        __nv_bfloat16 h3 = __float2bfloat16(u3);
        size_t o1 = o0 + (size_t)8 * CDIM;
        *(uint32_t*)&g_attnh[o1] = pack2bf(u2, u3);
        *(uint32_t*)&g_attnl[o1] = pack2bf(u2 - __bfloat162float(h2),
                                           u3 - __bfloat162float(h3));
    }
}

// ============================================================
// LN1 + residual
// ============================================================
__global__ void k_ln1(const float* __restrict__ x,
                      const float* __restrict__ g, const float* __restrict__ bsh) {
    int t = blockIdx.x, tid = threadIdx.x;
    __shared__ float rs[256], rss[256];
    float s = 0.f, ss = 0.f;
    for (int c = tid; c < CDIM; c += 256) {
        float v = g_proj[(size_t)t * CDIM + c];
        s += v; ss += v * v;
    }
    rs[tid] = s; rss[tid] = ss;
    __syncthreads();
    for (int off = 128; off > 0; off >>= 1) {
        if (tid < off) { rs[tid] += rs[tid + off]; rss[tid] += rss[tid + off]; }
        __syncthreads();
    }
    float mean = rs[0] * (1.f / CDIM);
    float var = rss[0] * (1.f / CDIM) - mean * mean;
    float rstd = rsqrtf(var + EPS);
    for (int c = tid; c < CDIM; c += 256) {
        float v = (g_proj[(size_t)t * CDIM + c] - mean) * rstd * g[c] + bsh[c];
        float x1 = x[(size_t)t * CDIM + c] + v;
        g_x1[(size_t)t * CDIM + c] = x1;
        __nv_bfloat16 hi = __float2bfloat16(x1);
        g_x1h[(size_t)t * CDIM + c] = hi;
        g_x1l[(size_t)t * CDIM + c] = __float2bfloat16(x1 - __bfloat162float(hi));
    }
}

// ============================================================
// noisy top-2 router
// ============================================================
__global__ void k_router(const float* __restrict__ Wr, const float* __restrict__ br,
                         const float* __restrict__ Wn, const float* __restrict__ bn,
                         const float* __restrict__ noise) {
    int t = blockIdx.x, tid = threadIdx.x;
    float ar[NE], an[NE];
    #pragma unroll
    for (int e = 0; e < NE; e++) { ar[e] = 0.f; an[e] = 0.f; }
    for (int c = tid; c < CDIM; c += 128) {
        float xv = g_x1[(size_t)t * CDIM + c];
        const float4* wr4 = (const float4*)&Wr[c * NE];
        const float4* wn4 = (const float4*)&Wn[c * NE];
        float4 r0 = wr4[0], r1 = wr4[1];
        float4 n0 = wn4[0], n1 = wn4[1];
        ar[0] += xv * r0.x; ar[1] += xv * r0.y; ar[2] += xv * r0.z; ar[3] += xv * r0.w;
        ar[4] += xv * r1.x; ar[5] += xv * r1.y; ar[6] += xv * r1.z; ar[7] += xv * r1.w;
        an[0] += xv * n0.x; an[1] += xv * n0.y; an[2] += xv * n0.z; an[3] += xv * n0.w;
        an[4] += xv * n1.x; an[5] += xv * n1.y; an[6] += xv * n1.z; an[7] += xv * n1.w;
    }
    __shared__ float red[16 * 128];
    #pragma unroll
    for (int e = 0; e < NE; e++) {
        red[e * 128 + tid] = ar[e];
        red[(e + 8) * 128 + tid] = an[e];
    }
    __syncthreads();
    __shared__ float res[16];
    if (tid < 16) {
        float s = 0.f;
        for (int i = 0; i < 128; i++) s += red[tid * 128 + i];
        res[tid] = s;
    }
    __syncthreads();
    if (tid == 0) {
        float noisy[NE];
        #pragma unroll
        for (int e = 0; e < NE; e++) {
            float lg = res[e] + br[e];
            float nl = res[e + 8] + bn[e];
            float sp = (nl > 20.f) ? nl : log1pf(expf(nl));
            noisy[e] = lg + noise[t * NE + e] * sp;
        }
        int i0 = 0; float v0 = noisy[0];
        #pragma unroll
        for (int e = 1; e < NE; e++) if (noisy[e] > v0) { v0 = noisy[e]; i0 = e; }
        int i1 = -1; float v1 = -1e30f;
        #pragma unroll
        for (int e = 0; e < NE; e++)
            if (e != i0 && noisy[e] > v1) { v1 = noisy[e]; i1 = e; }
        float e1 = expf(v1 - v0);
        float denom = 1.f + e1;
        float gate0 = 1.f / denom, gate1 = e1 / denom;
        int s0 = atomicAdd(&g_counts[i0], 1);
        g_list[i0 * NTOK + s0] = t; g_gate[i0 * NTOK + s0] = gate0;
        g_slot[t * 2 + 0] = i0 * NTOK + s0;
        int s1 = atomicAdd(&g_counts[i1], 1);
        g_list[i1 * NTOK + s1] = t; g_gate[i1 * NTOK + s1] = gate1;
        g_slot[t * 2 + 1] = i1 * NTOK + s1;
    }
}

__global__ void k_prefix() {
    if (threadIdx.x == 0 && blockIdx.x == 0) {
        int s = 0;
        for (int e = 0; e < NE; e++) { g_base[e] = s; s += g_counts[e]; }
    }
}

// ============================================================
// combine 2 expert rows + LN2 + residual
// ============================================================
__global__ void k_out(const float* __restrict__ g, const float* __restrict__ bsh,
                      float* __restrict__ out) {
    int t = blockIdx.x, tid = threadIdx.x;
    __shared__ int srow[2];
    if (tid < 2) {
        int slot = g_slot[t * 2 + tid];
        int e = slot / NTOK, r = slot % NTOK;
        srow[tid] = g_base[e] + r;
    }
    __syncthreads();
    const float* eo0 = g_eo + (size_t)srow[0] * CDIM;
    const float* eo1 = g_eo + (size_t)srow[1] * CDIM;

    __shared__ float rs[256], rss[256];
    float s = 0.f, ss = 0.f;
    for (int c = tid; c < CDIM; c += 256) {
        float v = eo0[c] + eo1[c];
        s += v; ss += v * v;
    }
    rs[tid] = s; rss[tid] = ss;
    __syncthreads();
    for (int off = 128; off > 0; off >>= 1) {
        if (tid < off) { rs[tid] += rs[tid + off]; rss[tid] += rss[tid + off]; }
        __syncthreads();
    }
    float mean = rs[0] * (1.f / CDIM);
    float var = rss[0] * (1.f / CDIM) - mean * mean;
    float rstd = rsqrtf(var + EPS);
    for (int c = tid; c < CDIM; c += 256) {
        float v = ((eo0[c] + eo1[c]) - mean) * rstd * g[c] + bsh[c];
        out[(size_t)t * CDIM + c] = g_x1[(size_t)t * CDIM + c] + v;
    }
}

// ============================================================
extern "C" void kernel_launch(void* const* d_in, const int* in_sizes, int n_in,
                              void* d_out, int out_size) {
    const float* x     = (const float*)d_in[0];
    const float* Wq    = (const float*)d_in[1];
    const float* Wk    = (const float*)d_in[2];
    const float* Wv    = (const float*)d_in[3];
    const float* Wo    = (const float*)d_in[4];
    const float* bo    = (const float*)d_in[5];
    const float* ln1_g = (const float*)d_in[6];
    const float* ln1_b = (const float*)d_in[7];
    const float* Wr    = (const float*)d_in[8];
    const float* br    = (const float*)d_in[9];
    const float* Wn    = (const float*)d_in[10];
    const float* bn    = (const float*)d_in[11];
    const float* W1    = (const float*)d_in[12];
    const float* b1    = (const float*)d_in[13];
    const float* W2    = (const float*)d_in[14];
    const float* b2    = (const float*)d_in[15];
    const float* ln2_g = (const float*)d_in[16];
    const float* ln2_b = (const float*)d_in[17];
    const float* noise = (const float*)d_in[18];
    float* out = (float*)d_out;

    cudaFuncSetAttribute(k_gemm, cudaFuncAttributeMaxDynamicSharedMemorySize, SMEM_BYTES);
    cudaFuncSetAttribute(k_attn2, cudaFuncAttributeMaxDynamicSharedMemorySize, ASM_BYTES);

    k_zero<<<1, 32>>>();
    k_splitx<<<512, 256>>>(x);
    k_split_flat<<<256, 256>>>(Wq, 0, (1 << 20) / 4);
    k_split_flat<<<256, 256>>>(Wk, 1, (1 << 20) / 4);
    k_split_flat<<<256, 256>>>(Wv, 2, (1 << 20) / 4);
    k_split_flat<<<256, 256>>>(Wo, 3, (1 << 20) / 4);
    k_split_flat<<<1024, 256>>>(W1, 4, (NE * CDIM * FF) / 4);
    k_split_flat<<<1024, 256>>>(W2, 5, (NE * FF * CDIM) / 4);

    k_gemm<<<dim3(32, 24, 1), 256, SMEM_BYTES>>>(0, nullptr);     // qkv
    k_attn2<<<dim3(TSEQ / 128, NB * NH), 256, ASM_BYTES>>>();     // flash attn
    k_gemm<<<dim3(32, 8, 1), 256, SMEM_BYTES>>>(1, bo);           // out-proj
    k_ln1<<<NTOK, 256>>>(x, ln1_g, ln1_b);
    k_router<<<NTOK, 128>>>(Wr, br, Wn, bn, noise);
    k_prefix<<<1, 1>>>();
    k_gemm<<<dim3(32, 32, NE), 256, SMEM_BYTES>>>(2, b1);         // moe1 + gelu
    k_gemm<<<dim3(32, 8, NE), 256, SMEM_BYTES>>>(3, b2);          // moe2 + gate
    k_out<<<NTOK, 256>>>(ln2_g, ln2_b, out);
}

// round 16
// speedup vs baseline: 3.0010x; 1.0332x over previous
#include <cuda_runtime.h>
#include <cuda_bf16.h>
#include <math.h>
#include <stdint.h>

// ---- fixed problem shapes ----
#define NTOK 4096      // B*T
#define TSEQ 2048
#define NB   2
#define CDIM 1024
#define NH   16
#define HD   64
#define FF   4096
#define NE   8
#define EPS  1e-5f
#define SCALE 0.03125f // C^-0.5 = 1/32

// ============================================================
// scratch (device globals: allocation-free)
// ============================================================
__device__ __align__(128) float g_proj[NTOK * CDIM];
__device__ __align__(128) float g_x1[NTOK * CDIM];
__device__ __align__(128) float g_eo[2 * NTOK * CDIM];
__device__ int   g_counts[NE];
__device__ int   g_base[NE];
__device__ int   g_list[NE * NTOK];
__device__ float g_gate[NE * NTOK];
__device__ int   g_slot[NTOK * 2];

// bf16 hi/lo activation scratch (K-major rows)
__device__ __align__(128) __nv_bfloat16 g_xh[NTOK * CDIM];
__device__ __align__(128) __nv_bfloat16 g_xl[NTOK * CDIM];
__device__ __align__(128) __nv_bfloat16 g_attnh[NTOK * CDIM];
__device__ __align__(128) __nv_bfloat16 g_attnl[NTOK * CDIM];
__device__ __align__(128) __nv_bfloat16 g_x1h[NTOK * CDIM];
__device__ __align__(128) __nv_bfloat16 g_x1l[NTOK * CDIM];
__device__ __align__(128) __nv_bfloat16 g_hh[2 * NTOK * FF];
__device__ __align__(128) __nv_bfloat16 g_hl[2 * NTOK * FF];

// Q/K/V bf16 hi/lo, [b*NH+h][t][d]
__device__ __align__(128) __nv_bfloat16 g_qh[NB * NH * TSEQ * HD];
__device__ __align__(128) __nv_bfloat16 g_ql[NB * NH * TSEQ * HD];
__device__ __align__(128) __nv_bfloat16 g_kh[NB * NH * TSEQ * HD];
__device__ __align__(128) __nv_bfloat16 g_kl[NB * NH * TSEQ * HD];
__device__ __align__(128) __nv_bfloat16 g_vh[NB * NH * TSEQ * HD];
__device__ __align__(128) __nv_bfloat16 g_vl[NB * NH * TSEQ * HD];

// bf16 hi/lo weights in NATURAL [K][N]-style layouts (no transpose):
// g_Wqkvh: [mat][head][C][HD]   (mat*2^20 + head*65536 + c*64 + d)
// g_Woh:   [C][C]
// g_W1h:   [e][C][FF]
// g_W2h:   [e][FF][C]
__device__ __align__(128) __nv_bfloat16 g_Wqkvh[3 * CDIM * CDIM];
__device__ __align__(128) __nv_bfloat16 g_Wqkvl[3 * CDIM * CDIM];
__device__ __align__(128) __nv_bfloat16 g_Woh[CDIM * CDIM];
__device__ __align__(128) __nv_bfloat16 g_Wol[CDIM * CDIM];
__device__ __align__(128) __nv_bfloat16 g_W1h[NE * CDIM * FF];
__device__ __align__(128) __nv_bfloat16 g_W1l[NE * CDIM * FF];
__device__ __align__(128) __nv_bfloat16 g_W2h[NE * FF * CDIM];
__device__ __align__(128) __nv_bfloat16 g_W2l[NE * FF * CDIM];

__device__ __forceinline__ uint32_t pack2bf(float a, float b) {
    __nv_bfloat162 t;
    t.x = __float2bfloat16(a);
    t.y = __float2bfloat16(b);
    return *(uint32_t*)&t;
}

// ============================================================
// small kernels
// ============================================================
__global__ void k_zero() {
    if (threadIdx.x < NE) g_counts[threadIdx.x] = 0;
}

__global__ void k_splitx(const float* __restrict__ x) {
    int n4 = NTOK * CDIM / 4;
    for (int i = blockIdx.x * blockDim.x + threadIdx.x; i < n4;
         i += gridDim.x * blockDim.x) {
        float4 v = ((const float4*)x)[i];
        __nv_bfloat16 h0 = __float2bfloat16(v.x);
        __nv_bfloat16 h1 = __float2bfloat16(v.y);
        __nv_bfloat16 h2 = __float2bfloat16(v.z);
        __nv_bfloat16 h3 = __float2bfloat16(v.w);
        uint2 hi, lo;
        hi.x = pack2bf(v.x, v.y); hi.y = pack2bf(v.z, v.w);
        lo.x = pack2bf(v.x - __bfloat162float(h0), v.y - __bfloat162float(h1));
        lo.y = pack2bf(v.z - __bfloat162float(h2), v.w - __bfloat162float(h3));
        ((uint2*)g_xh)[i] = hi;
        ((uint2*)g_xl)[i] = lo;
    }
}

// streaming fp32 -> bf16 hi/lo split, layout-preserving (no transpose)
__global__ void k_split_flat(const float* __restrict__ src, int sel, int n4) {
    __nv_bfloat16 *dh, *dl;
    switch (sel) {
        case 0: dh = g_Wqkvh;                 dl = g_Wqkvl;                 break;
        case 1: dh = g_Wqkvh + (1 << 20);     dl = g_Wqkvl + (1 << 20);     break;
        case 2: dh = g_Wqkvh + (2 << 20);     dl = g_Wqkvl + (2 << 20);     break;
        case 3: dh = g_Woh;                   dl = g_Wol;                   break;
        case 4: dh = g_W1h;                   dl = g_W1l;                   break;
        default: dh = g_W2h;                  dl = g_W2l;                   break;
    }
    int stride = gridDim.x * blockDim.x;
    #pragma unroll 4
    for (int i = blockIdx.x * blockDim.x + threadIdx.x; i < n4; i += stride) {
        float4 v = ((const float4*)src)[i];
        __nv_bfloat16 h0 = __float2bfloat16(v.x);
        __nv_bfloat16 h1 = __float2bfloat16(v.y);
        __nv_bfloat16 h2 = __float2bfloat16(v.z);
        __nv_bfloat16 h3 = __float2bfloat16(v.w);
        uint2 hi, lo;
        hi.x = pack2bf(v.x, v.y); hi.y = pack2bf(v.z, v.w);
        lo.x = pack2bf(v.x - __bfloat162float(h0), v.y - __bfloat162float(h1));
        lo.y = pack2bf(v.z - __bfloat162float(h2), v.w - __bfloat162float(h3));
        ((uint2*)dh)[i] = hi;
        ((uint2*)dl)[i] = lo;
    }
}

// ============================================================
// mma/ldmatrix/cp.async primitives
// ============================================================
__device__ __forceinline__ void mma16816(float* c, const uint32_t* a, const uint32_t* b) {
    asm volatile(
        "mma.sync.aligned.m16n8k16.row.col.f32.bf16.bf16.f32 "
        "{%0,%1,%2,%3}, {%4,%5,%6,%7}, {%8,%9}, {%0,%1,%2,%3};"
        : "+f"(c[0]), "+f"(c[1]), "+f"(c[2]), "+f"(c[3])
        : "r"(a[0]), "r"(a[1]), "r"(a[2]), "r"(a[3]), "r"(b[0]), "r"(b[1]));
}
__device__ __forceinline__ void ldsm4(uint32_t* r, uint32_t saddr) {
    asm volatile("ldmatrix.sync.aligned.m8n8.x4.shared.b16 {%0,%1,%2,%3}, [%4];"
        : "=r"(r[0]), "=r"(r[1]), "=r"(r[2]), "=r"(r[3]) : "r"(saddr));
}
__device__ __forceinline__ void ldsm4t(uint32_t* r, uint32_t saddr) {
    asm volatile("ldmatrix.sync.aligned.m8n8.x4.trans.shared.b16 {%0,%1,%2,%3}, [%4];"
        : "=r"(r[0]), "=r"(r[1]), "=r"(r[2]), "=r"(r[3]) : "r"(saddr));
}
#define CPASYNC(dst, src) \
    asm volatile("cp.async.cg.shared.global [%0], [%1], 16;" :: "r"(dst), "l"(src))
#define CPCOMMIT() asm volatile("cp.async.commit_group;" ::: "memory")
#define CPWAIT1()  asm volatile("cp.async.wait_group 1;" ::: "memory")

// ============================================================
// unified bf16 split-GEMM, block tile 128m x 256n, BK=64
// A: [128 m][64 k] hi+lo; B: [64 k][256 n] hi+lo (natural layout, ldsm4t)
// 8 warps 2x4, warp tile 64x64
// ============================================================
#define ASTR 72
#define A_TILE_E (128 * ASTR)                  // 9216
#define BSTR 264
#define B_TILE_E (64 * BSTR)                   // 16896
#define GBUF_E (2 * A_TILE_E + 2 * B_TILE_E)   // 52224
#define SMEM_BYTES (2 * GBUF_E * 2)            // 208896

__device__ __forceinline__ void stage_load(
    uint32_t sbase, int bufo, int mode,
    const __nv_bfloat16* __restrict__ Ah, const __nv_bfloat16* __restrict__ Al,
    const __nv_bfloat16* __restrict__ Bh, const __nv_bfloat16* __restrict__ Bl,
    const int* rows, int n0, int lda, int ldbN, int k0, int tid)
{
    // A: 128 rows x 64 k
    #pragma unroll
    for (int i = 0; i < 4; i++) {
        int c = tid + i * 256;
        int r = c >> 3, col = (c & 7) * 8;
        uint32_t d = sbase + 2 * (bufo + r * ASTR + col);
        size_t ao = (size_t)rows[r] * lda + k0 + col;
        CPASYNC(d,                Ah + ao);
        CPASYNC(d + 2 * A_TILE_E, Al + ao);
    }
    // B: 64 k-rows x 256 n
    #pragma unroll
    for (int i = 0; i < 8; i++) {
        int c = tid + i * 256;
        int r = c >> 5, col = (c & 31) * 8;
        uint32_t d = sbase + 2 * (bufo + 2 * A_TILE_E + r * BSTR + col);
        size_t off;
        if (mode == 0) {
            int n = n0 + col;
            int mat = n >> 10, rem = n & 1023;
            int head = rem >> 6, dd = rem & 63;
            off = ((size_t)mat << 20) + (size_t)head * 65536 + (size_t)(k0 + r) * 64 + dd;
        } else {
            off = (size_t)(k0 + r) * ldbN + n0 + col;
        }
        CPASYNC(d,                Bh + off);
        CPASYNC(d + 2 * B_TILE_E, Bl + off);
    }
}

__global__ void __launch_bounds__(256, 1)
k_gemm(int mode, const float* __restrict__ bias) {
    extern __shared__ __align__(128) __nv_bfloat16 smem[];
    __shared__ int rows[128];

    int tid = threadIdx.x;
    int lane = tid & 31, wid = tid >> 5;
    int wm = (wid >> 2) * 64;       // warp m offset
    int wn = (wid & 3) * 64;        // warp n offset (64-wide now)
    int qr = lane >> 2;
    int qc = (lane & 3) * 2;
    int e = blockIdx.z;
    int m0 = blockIdx.x * 128, n0 = blockIdx.y * 256;

    const __nv_bfloat16 *Ahp, *Alp, *Bhp, *Blp;
    int lda, ldbN, K;
    int cnt = 0, base = 0;
    if (mode == 0) {
        Ahp = g_xh; Alp = g_xl; Bhp = g_Wqkvh; Blp = g_Wqkvl;
        lda = CDIM; ldbN = 0; K = CDIM;
    } else if (mode == 1) {
        Ahp = g_attnh; Alp = g_attnl; Bhp = g_Woh; Blp = g_Wol;
        lda = CDIM; ldbN = CDIM; K = CDIM;
    } else if (mode == 2) {
        cnt = g_counts[e]; base = g_base[e];
        if (m0 >= cnt) return;
        Ahp = g_x1h; Alp = g_x1l;
        Bhp = g_W1h + (size_t)e * CDIM * FF; Blp = g_W1l + (size_t)e * CDIM * FF;
        lda = CDIM; ldbN = FF; K = CDIM;
    } else {
        cnt = g_counts[e]; base = g_base[e];
        if (m0 >= cnt) return;
        Ahp = g_hh; Alp = g_hl;
        Bhp = g_W2h + (size_t)e * FF * CDIM; Blp = g_W2l + (size_t)e * FF * CDIM;
        lda = FF; ldbN = CDIM; K = FF;
    }

    if (tid < 128) {
        if (mode == 2) {
            int r = m0 + tid; if (r >= cnt) r = cnt - 1;
            rows[tid] = g_list[e * NTOK + r];
        } else if (mode == 3) {
            int r = m0 + tid; if (r >= cnt) r = cnt - 1;
            rows[tid] = base + r;
        } else {
            rows[tid] = m0 + tid;
        }
    }
    __syncthreads();

    float acc[4][8][4];
    #pragma unroll
    for (int im = 0; im < 4; im++)
        #pragma unroll
        for (int in_ = 0; in_ < 8; in_++)
            #pragma unroll
            for (int q = 0; q < 4; q++) acc[im][in_][q] = 0.f;

    uint32_t sbase;
    asm("{ .reg .u64 t; cvta.to.shared.u64 t, %1; cvt.u32.u64 %0, t; }"
        : "=r"(sbase) : "l"(smem));

    const int NST = K >> 6;
    int a_row = lane & 15, a_col = (lane >> 4) * 8;

    stage_load(sbase, 0, mode, Ahp, Alp, Bhp, Blp, rows, n0, lda, ldbN, 0, tid);
    CPCOMMIT();

    for (int kc = 0; kc < NST; kc++) {
        int cbuf = (kc & 1) * GBUF_E;
        if (kc + 1 < NST)
            stage_load(sbase, ((kc + 1) & 1) * GBUF_E, mode, Ahp, Alp, Bhp, Blp,
                       rows, n0, lda, ldbN, (kc + 1) << 6, tid);
        CPCOMMIT();
        CPWAIT1();
        __syncthreads();

        #pragma unroll
        for (int ks = 0; ks < 4; ks++) {
            int kb = ks * 16;
            uint32_t ah[4][4], al[4][4];
            #pragma unroll
            for (int im = 0; im < 4; im++) {
                uint32_t ad = sbase + 2 * (cbuf + (wm + im * 16 + a_row) * ASTR + kb + a_col);
                ldsm4(ah[im], ad);
                ldsm4(al[im], ad + 2 * A_TILE_E);
            }
            #pragma unroll
            for (int bhalf = 0; bhalf < 2; bhalf++) {
                uint32_t bh[2][4], bl[2][4];
                #pragma unroll
                for (int ip = 0; ip < 2; ip++) {
                    uint32_t bd = sbase + 2 * (cbuf + 2 * A_TILE_E + (kb + a_row) * BSTR +
                                               wn + bhalf * 32 + ip * 16 + a_col);
                    ldsm4t(bh[ip], bd);
                    ldsm4t(bl[ip], bd + 2 * B_TILE_E);
                }
                #pragma unroll
                for (int im = 0; im < 4; im++) {
                    #pragma unroll
                    for (int j = 0; j < 4; j++) {
                        int in_ = bhalf * 4 + j;
                        uint32_t* bhp = &bh[j >> 1][(j & 1) * 2];
                        uint32_t* blp = &bl[j >> 1][(j & 1) * 2];
                        mma16816(acc[im][in_], ah[im], bhp);
                        mma16816(acc[im][in_], ah[im], blp);
                        mma16816(acc[im][in_], al[im], bhp);
                    }
                }
            }
        }
        __syncthreads();
    }

    #pragma unroll
    for (int im = 0; im < 4; im++) {
        #pragma unroll
        for (int in_ = 0; in_ < 8; in_++) {
            #pragma unroll
            for (int half = 0; half < 2; half++) {
                int ml = wm + im * 16 + qr + half * 8;
                int nl = wn + in_ * 8 + qc;
                float v0 = acc[im][in_][half * 2 + 0];
                float v1 = acc[im][in_][half * 2 + 1];
                if (mode == 0) {
                    int tok = m0 + ml;
                    int col = n0 + nl;
                    int mat = col >> 10, rem = col & 1023;
                    int head = rem >> 6, d = rem & 63;
                    int bb = tok >> 11, t = tok & 2047;
                    size_t idx = ((size_t)(bb * NH + head) * TSEQ + t) * HD + d;
                    __nv_bfloat16 h0 = __float2bfloat16(v0);
                    __nv_bfloat16 h1 = __float2bfloat16(v1);
                    uint32_t hi = pack2bf(v0, v1);
                    uint32_t lo = pack2bf(v0 - __bfloat162float(h0),
                                          v1 - __bfloat162float(h1));
                    if (mat == 0)      { *(uint32_t*)&g_qh[idx] = hi; *(uint32_t*)&g_ql[idx] = lo; }
                    else if (mat == 1) { *(uint32_t*)&g_kh[idx] = hi; *(uint32_t*)&g_kl[idx] = lo; }
                    else               { *(uint32_t*)&g_vh[idx] = hi; *(uint32_t*)&g_vl[idx] = lo; }
                } else if (mode == 1) {
                    int tok = m0 + ml;
                    int col = n0 + nl;
                    *(float2*)&g_proj[(size_t)tok * CDIM + col] =
                        make_float2(v0 + bias[col], v1 + bias[col + 1]);
                } else if (mode == 2) {
                    int r = m0 + ml;
                    if (r < cnt) {
                        int col = n0 + nl;
                        float u0 = v0 + bias[(size_t)e * FF + col];
                        float u1 = v1 + bias[(size_t)e * FF + col + 1];
                        u0 = 0.5f * u0 * (1.0f + erff(u0 * 0.70710678118654752f));
                        u1 = 0.5f * u1 * (1.0f + erff(u1 * 0.70710678118654752f));
                        __nv_bfloat16 h0 = __float2bfloat16(u0);
                        __nv_bfloat16 h1 = __float2bfloat16(u1);
                        size_t o = (size_t)(base + r) * FF + col;
                        *(uint32_t*)&g_hh[o] = pack2bf(u0, u1);
                        *(uint32_t*)&g_hl[o] = pack2bf(u0 - __bfloat162float(h0),
                                                       u1 - __bfloat162float(h1));
                    }
                } else {
                    int r = m0 + ml;
                    if (r < cnt) {
                        int col = n0 + nl;
                        float gate = g_gate[e * NTOK + r];
                        *(float2*)&g_eo[(size_t)(base + r) * CDIM + col] =
                            make_float2((v0 + bias[(size_t)e * CDIM + col]) * gate,
                                        (v1 + bias[(size_t)e * CDIM + col + 1]) * gate);
                    }
                }
            }
        }
    }
}

// ============================================================
// tensor-core flash attention (as R12, passing)
// ============================================================
#define AQ_E  (128 * 72)
#define AKV_E (64 * 72)
#define AST_E (4 * AKV_E)
#define ASM_BYTES ((2 * AQ_E + 2 * AST_E) * 2)

__device__ __forceinline__ void kv_stage(uint32_t sb, int stage, int bh, int kv0, int tid) {
    uint32_t base = 2 * AQ_E + stage * AST_E;
    const __nv_bfloat16* Kh = g_kh + (size_t)bh * TSEQ * HD;
    const __nv_bfloat16* Kl = g_kl + (size_t)bh * TSEQ * HD;
    const __nv_bfloat16* Vh = g_vh + (size_t)bh * TSEQ * HD;
    const __nv_bfloat16* Vl = g_vl + (size_t)bh * TSEQ * HD;
    #pragma unroll
    for (int i = 0; i < 2; i++) {
        int c = tid + i * 256;
        int r = c >> 3, col = (c & 7) * 8;
        size_t g = (size_t)(kv0 + r) * HD + col;
        uint32_t d = sb + 2 * (base + r * 72 + col);
        CPASYNC(d,              Kh + g);
        CPASYNC(d + 2 * AKV_E,  Kl + g);
        CPASYNC(d + 4 * AKV_E,  Vh + g);
        CPASYNC(d + 6 * AKV_E,  Vl + g);
    }
}

__global__ void __launch_bounds__(256, 1) k_attn2() {
    extern __shared__ __align__(128) __nv_bfloat16 smem_a[];
    int tid = threadIdx.x, lane = tid & 31, w = tid >> 5;
    int bh = blockIdx.y;
    int b = bh >> 4, h = bh & 15;
    int q0 = ((int)gridDim.x - 1 - (int)blockIdx.x) * 128;

    const __nv_bfloat16* Qh = g_qh + (size_t)bh * TSEQ * HD;
    const __nv_bfloat16* Ql = g_ql + (size_t)bh * TSEQ * HD;

    uint32_t sb;
    asm("{ .reg .u64 t; cvta.to.shared.u64 t, %1; cvt.u32.u64 %0, t; }"
        : "=r"(sb) : "l"(smem_a));

    #pragma unroll
    for (int i = 0; i < 4; i++) {
        int c = tid + i * 256;
        int r = c >> 3, col = (c & 7) * 8;
        size_t g = (size_t)(q0 + r) * HD + col;
        CPASYNC(sb + 2 * (r * 72 + col),        Qh + g);
        CPASYNC(sb + 2 * (AQ_E + r * 72 + col), Ql + g);
    }
    kv_stage(sb, 0, bh, 0, tid);
    CPCOMMIT();

    int nkv = q0 / 64 + 2;

    float m0 = -1e30f, m1 = -1e30f, l0 = 0.f, l1 = 0.f;
    float oacc[8][4];
    #pragma unroll
    for (int nf = 0; nf < 8; nf++)
        #pragma unroll
        for (int q = 0; q < 4; q++) oacc[nf][q] = 0.f;

    int qr = lane >> 2, qc = (lane & 3) * 2;
    int r0g = q0 + w * 16 + qr;
    int a_row = lane & 15, a_col = (lane >> 4) * 8;
    int b_row = (lane & 7) + ((lane >> 4) << 3), b_col = ((lane >> 3) & 1) * 8;

    for (int kv = 0; kv < nkv; kv++) {
        int kv0 = kv * 64;
        if (kv + 1 < nkv) kv_stage(sb, (kv + 1) & 1, bh, (kv + 1) * 64, tid);
        CPCOMMIT();
        CPWAIT1();
        __syncthreads();
        uint32_t kvb = 2 * AQ_E + (kv & 1) * AST_E;

        float sacc[8][4];
        #pragma unroll
        for (int nf = 0; nf < 8; nf++)
            #pragma unroll
            for (int q = 0; q < 4; q++) sacc[nf][q] = 0.f;

        #pragma unroll
        for (int ks = 0; ks < 4; ks++) {
            int kb = ks * 16;
            uint32_t qf[4], qlf[4];
            uint32_t ad = sb + 2 * ((w * 16 + a_row) * 72 + kb + a_col);
            ldsm4(qf, ad);
            ldsm4(qlf, ad + 2 * AQ_E);
            uint32_t kh[4][4], kl[4][4];
            #pragma unroll
            for (int ip = 0; ip < 4; ip++) {
                uint32_t bd = sb + 2 * (kvb + (ip * 16 + b_row) * 72 + kb + b_col);
                ldsm4(kh[ip], bd);
                ldsm4(kl[ip], bd + 2 * AKV_E);
            }
            #pragma unroll
            for (int nf = 0; nf < 8; nf++) {
                uint32_t* bh_ = &kh[nf >> 1][(nf & 1) * 2];
                uint32_t* bl_ = &kl[nf >> 1][(nf & 1) * 2];
                mma16816(sacc[nf], qf, bh_);
                mma16816(sacc[nf], qf, bl_);
                mma16816(sacc[nf], qlf, bh_);
            }
        }

        bool needmask = (kv0 + 63) > (q0 + w * 16);
        #pragma unroll
        for (int nf = 0; nf < 8; nf++) {
            #pragma unroll
            for (int q = 0; q < 4; q++) {
                float s = sacc[nf][q] * SCALE;
                if (needmask) {
                    int key = kv0 + nf * 8 + qc + (q & 1);
                    int rowg = r0g + (q >> 1) * 8;
                    if (key > rowg) s = -1e30f;
                }
                sacc[nf][q] = s;
            }
        }

        float rm0 = -1e30f, rm1 = -1e30f;
        #pragma unroll
        for (int nf = 0; nf < 8; nf++) {
            rm0 = fmaxf(rm0, fmaxf(sacc[nf][0], sacc[nf][1]));
            rm1 = fmaxf(rm1, fmaxf(sacc[nf][2], sacc[nf][3]));
        }
        rm0 = fmaxf(rm0, __shfl_xor_sync(0xffffffffu, rm0, 1));
        rm0 = fmaxf(rm0, __shfl_xor_sync(0xffffffffu, rm0, 2));
        rm1 = fmaxf(rm1, __shfl_xor_sync(0xffffffffu, rm1, 1));
        rm1 = fmaxf(rm1, __shfl_xor_sync(0xffffffffu, rm1, 2));
        float mn0 = fmaxf(m0, rm0), mn1 = fmaxf(m1, rm1);
        float f0 = __expf(m0 - mn0), f1 = __expf(m1 - mn1);
        float s0 = 0.f, s1 = 0.f;
        #pragma unroll
        for (int nf = 0; nf < 8; nf++) {
            float p0 = __expf(sacc[nf][0] - mn0);
            float p1 = __expf(sacc[nf][1] - mn0);
            float p2 = __expf(sacc[nf][2] - mn1);
            float p3 = __expf(sacc[nf][3] - mn1);
            sacc[nf][0] = p0; sacc[nf][1] = p1; sacc[nf][2] = p2; sacc[nf][3] = p3;
            s0 += p0 + p1; s1 += p2 + p3;
        }
        s0 += __shfl_xor_sync(0xffffffffu, s0, 1);
        s0 += __shfl_xor_sync(0xffffffffu, s0, 2);
        s1 += __shfl_xor_sync(0xffffffffu, s1, 1);
        s1 += __shfl_xor_sync(0xffffffffu, s1, 2);
        l0 = l0 * f0 + s0;
        l1 = l1 * f1 + s1;
        #pragma unroll
        for (int nf = 0; nf < 8; nf++) {
            oacc[nf][0] *= f0; oacc[nf][1] *= f0;
            oacc[nf][2] *= f1; oacc[nf][3] *= f1;
        }
        m0 = mn0; m1 = mn1;

        uint32_t pah[4][4], pal[4][4];
        #pragma unroll
        for (int j = 0; j < 4; j++) {
            float p00 = sacc[2 * j][0],     p01 = sacc[2 * j][1];
            float p02 = sacc[2 * j][2],     p03 = sacc[2 * j][3];
            float p10 = sacc[2 * j + 1][0], p11 = sacc[2 * j + 1][1];
            float p12 = sacc[2 * j + 1][2], p13 = sacc[2 * j + 1][3];
            pah[j][0] = pack2bf(p00, p01);
            pah[j][1] = pack2bf(p02, p03);
            pah[j][2] = pack2bf(p10, p11);
            pah[j][3] = pack2bf(p12, p13);
            pal[j][0] = pack2bf(p00 - __bfloat162float(__float2bfloat16(p00)),
                                p01 - __bfloat162float(__float2bfloat16(p01)));
            pal[j][1] = pack2bf(p02 - __bfloat162float(__float2bfloat16(p02)),
                                p03 - __bfloat162float(__float2bfloat16(p03)));
            pal[j][2] = pack2bf(p10 - __bfloat162float(__float2bfloat16(p10)),
                                p11 - __bfloat162float(__float2bfloat16(p11)));
            pal[j][3] = pack2bf(p12 - __bfloat162float(__float2bfloat16(p12)),
                                p13 - __bfloat162float(__float2bfloat16(p13)));
        }

        #pragma unroll
        for (int j = 0; j < 4; j++) {
            uint32_t vh[4][4], vl[4][4];
            #pragma unroll
            for (int ng = 0; ng < 4; ng++) {
                uint32_t va = sb + 2 * (kvb + 2 * AKV_E + (j * 16 + a_row) * 72 + ng * 16 + a_col);
                ldsm4t(vh[ng], va);
                ldsm4t(vl[ng], va + 2 * AKV_E);
            }
            #pragma unroll
            for (int nf = 0; nf < 8; nf++) {
                uint32_t* bvh = &vh[nf >> 1][(nf & 1) * 2];
                uint32_t* bvl = &vl[nf >> 1][(nf & 1) * 2];
                mma16816(oacc[nf], pah[j], bvh);
                mma16816(oacc[nf], pah[j], bvl);
                mma16816(oacc[nf], pal[j], bvh);
            }
        }
        __syncthreads();
    }

    float inv0 = 1.f / l0, inv1 = 1.f / l1;
    int tok0 = b * TSEQ + r0g;
    #pragma unroll
    for (int nf = 0; nf < 8; nf++) {
        int d = nf * 8 + qc;
        size_t o0 = (size_t)tok0 * CDIM + h * HD + d;
        float u0 = oacc[nf][0] * inv0, u1 = oacc[nf][1] * inv0;
        __nv_bfloat16 h0 = __float2bfloat16(u0);
        __nv_bfloat16 h1 = __float2bfloat16(u1);
        *(uint32_t*)&g_attnh[o0] = pack2bf(u0, u1);
        *(uint32_t*)&g_attnl[o0] = pack2bf(u0 - __bfloat162float(h0),
                                           u1 - __bfloat162float(h1));
        float u2 = oacc[nf][2] * inv1, u3 = oacc[nf][3] * inv1;
        __nv_bfloat16 h2 = __float2bfloat16(u2);
        __nv_bfloat16 h3 = __float2bfloat16(u3);
        size_t o1 = o0 + (size_t)8 * CDIM;
        *(uint32_t*)&g_attnh[o1] = pack2bf(u2, u3);
        *(uint32_t*)&g_attnl[o1] = pack2bf(u2 - __bfloat162float(h2),
                                           u3 - __bfloat162float(h3));
    }
}

// ============================================================
// LN1 + residual
// ============================================================
__global__ void k_ln1(const float* __restrict__ x,
                      const float* __restrict__ g, const float* __restrict__ bsh) {
    int t = blockIdx.x, tid = threadIdx.x;
    __shared__ float rs[256], rss[256];
    float s = 0.f, ss = 0.f;
    for (int c = tid; c < CDIM; c += 256) {
        float v = g_proj[(size_t)t * CDIM + c];
        s += v; ss += v * v;
    }
    rs[tid] = s; rss[tid] = ss;
    __syncthreads();
    for (int off = 128; off > 0; off >>= 1) {
        if (tid < off) { rs[tid] += rs[tid + off]; rss[tid] += rss[tid + off]; }
        __syncthreads();
    }
    float mean = rs[0] * (1.f / CDIM);
    float var = rss[0] * (1.f / CDIM) - mean * mean;
    float rstd = rsqrtf(var + EPS);
    for (int c = tid; c < CDIM; c += 256) {
        float v = (g_proj[(size_t)t * CDIM + c] - mean) * rstd * g[c] + bsh[c];
        float x1 = x[(size_t)t * CDIM + c] + v;
        g_x1[(size_t)t * CDIM + c] = x1;
        __nv_bfloat16 hi = __float2bfloat16(x1);
        g_x1h[(size_t)t * CDIM + c] = hi;
        g_x1l[(size_t)t * CDIM + c] = __float2bfloat16(x1 - __bfloat162float(hi));
    }
}

// ============================================================
// noisy top-2 router
// ============================================================
__global__ void k_router(const float* __restrict__ Wr, const float* __restrict__ br,
                         const float* __restrict__ Wn, const float* __restrict__ bn,
                         const float* __restrict__ noise) {
    int t = blockIdx.x, tid = threadIdx.x;
    float ar[NE], an[NE];
    #pragma unroll
    for (int e = 0; e < NE; e++) { ar[e] = 0.f; an[e] = 0.f; }
    for (int c = tid; c < CDIM; c += 128) {
        float xv = g_x1[(size_t)t * CDIM + c];
        const float4* wr4 = (const float4*)&Wr[c * NE];
        const float4* wn4 = (const float4*)&Wn[c * NE];
        float4 r0 = wr4[0], r1 = wr4[1];
        float4 n0 = wn4[0], n1 = wn4[1];
        ar[0] += xv * r0.x; ar[1] += xv * r0.y; ar[2] += xv * r0.z; ar[3] += xv * r0.w;
        ar[4] += xv * r1.x; ar[5] += xv * r1.y; ar[6] += xv * r1.z; ar[7] += xv * r1.w;
        an[0] += xv * n0.x; an[1] += xv * n0.y; an[2] += xv * n0.z; an[3] += xv * n0.w;
        an[4] += xv * n1.x; an[5] += xv * n1.y; an[6] += xv * n1.z; an[7] += xv * n1.w;
    }
    __shared__ float red[16 * 128];
    #pragma unroll
    for (int e = 0; e < NE; e++) {
        red[e * 128 + tid] = ar[e];
        red[(e + 8) * 128 + tid] = an[e];
    }
    __syncthreads();
    __shared__ float res[16];
    if (tid < 16) {
        float s = 0.f;
        for (int i = 0; i < 128; i++) s += red[tid * 128 + i];
        res[tid] = s;
    }
    __syncthreads();
    if (tid == 0) {
        float noisy[NE];
        #pragma unroll
        for (int e = 0; e < NE; e++) {
            float lg = res[e] + br[e];
            float nl = res[e + 8] + bn[e];
            float sp = (nl > 20.f) ? nl : log1pf(expf(nl));
            noisy[e] = lg + noise[t * NE + e] * sp;
        }
        int i0 = 0; float v0 = noisy[0];
        #pragma unroll
        for (int e = 1; e < NE; e++) if (noisy[e] > v0) { v0 = noisy[e]; i0 = e; }
        int i1 = -1; float v1 = -1e30f;
        #pragma unroll
        for (int e = 0; e < NE; e++)
            if (e != i0 && noisy[e] > v1) { v1 = noisy[e]; i1 = e; }
        float e1 = expf(v1 - v0);
        float denom = 1.f + e1;
        float gate0 = 1.f / denom, gate1 = e1 / denom;
        int s0 = atomicAdd(&g_counts[i0], 1);
        g_list[i0 * NTOK + s0] = t; g_gate[i0 * NTOK + s0] = gate0;
        g_slot[t * 2 + 0] = i0 * NTOK + s0;
        int s1 = atomicAdd(&g_counts[i1], 1);
        g_list[i1 * NTOK + s1] = t; g_gate[i1 * NTOK + s1] = gate1;
        g_slot[t * 2 + 1] = i1 * NTOK + s1;
    }
}

__global__ void k_prefix() {
    if (threadIdx.x == 0 && blockIdx.x == 0) {
        int s = 0;
        for (int e = 0; e < NE; e++) { g_base[e] = s; s += g_counts[e]; }
    }
}

// ============================================================
// combine 2 expert rows + LN2 + residual
// ============================================================
__global__ void k_out(const float* __restrict__ g, const float* __restrict__ bsh,
                      float* __restrict__ out) {
    int t = blockIdx.x, tid = threadIdx.x;
    __shared__ int srow[2];
    if (tid < 2) {
        int slot = g_slot[t * 2 + tid];
        int e = slot / NTOK, r = slot % NTOK;
        srow[tid] = g_base[e] + r;
    }
    __syncthreads();
    const float* eo0 = g_eo + (size_t)srow[0] * CDIM;
    const float* eo1 = g_eo + (size_t)srow[1] * CDIM;

    __shared__ float rs[256], rss[256];
    float s = 0.f, ss = 0.f;
    for (int c = tid; c < CDIM; c += 256) {
        float v = eo0[c] + eo1[c];
        s += v; ss += v * v;
    }
    rs[tid] = s; rss[tid] = ss;
    __syncthreads();
    for (int off = 128; off > 0; off >>= 1) {
        if (tid < off) { rs[tid] += rs[tid + off]; rss[tid] += rss[tid + off]; }
        __syncthreads();
    }
    float mean = rs[0] * (1.f / CDIM);
    float var = rss[0] * (1.f / CDIM) - mean * mean;
    float rstd = rsqrtf(var + EPS);
    for (int c = tid; c < CDIM; c += 256) {
        float v = ((eo0[c] + eo1[c]) - mean) * rstd * g[c] + bsh[c];
        out[(size_t)t * CDIM + c] = g_x1[(size_t)t * CDIM + c] + v;
    }
}

// ============================================================
extern "C" void kernel_launch(void* const* d_in, const int* in_sizes, int n_in,
                              void* d_out, int out_size) {
    const float* x     = (const float*)d_in[0];
    const float* Wq    = (const float*)d_in[1];
    const float* Wk    = (const float*)d_in[2];
    const float* Wv    = (const float*)d_in[3];
    const float* Wo    = (const float*)d_in[4];
    const float* bo    = (const float*)d_in[5];
    const float* ln1_g = (const float*)d_in[6];
    const float* ln1_b = (const float*)d_in[7];
    const float* Wr    = (const float*)d_in[8];
    const float* br    = (const float*)d_in[9];
    const float* Wn    = (const float*)d_in[10];
    const float* bn    = (const float*)d_in[11];
    const float* W1    = (const float*)d_in[12];
    const float* b1    = (const float*)d_in[13];
    const float* W2    = (const float*)d_in[14];
    const float* b2    = (const float*)d_in[15];
    const float* ln2_g = (const float*)d_in[16];
    const float* ln2_b = (const float*)d_in[17];
    const float* noise = (const float*)d_in[18];
    float* out = (float*)d_out;

    cudaFuncSetAttribute(k_gemm, cudaFuncAttributeMaxDynamicSharedMemorySize, SMEM_BYTES);
    cudaFuncSetAttribute(k_attn2, cudaFuncAttributeMaxDynamicSharedMemorySize, ASM_BYTES);

    k_zero<<<1, 32>>>();
    k_splitx<<<512, 256>>>(x);
    k_split_flat<<<256, 256>>>(Wq, 0, (1 << 20) / 4);
    k_split_flat<<<256, 256>>>(Wk, 1, (1 << 20) / 4);
    k_split_flat<<<256, 256>>>(Wv, 2, (1 << 20) / 4);
    k_split_flat<<<256, 256>>>(Wo, 3, (1 << 20) / 4);
    k_split_flat<<<2048, 256>>>(W1, 4, (NE * CDIM * FF) / 4);
    k_split_flat<<<2048, 256>>>(W2, 5, (NE * FF * CDIM) / 4);

    k_gemm<<<dim3(32, 12, 1), 256, SMEM_BYTES>>>(0, nullptr);     // qkv
    k_attn2<<<dim3(TSEQ / 128, NB * NH), 256, ASM_BYTES>>>();     // flash attn
    k_gemm<<<dim3(32, 4, 1), 256, SMEM_BYTES>>>(1, bo);           // out-proj
    k_ln1<<<NTOK, 256>>>(x, ln1_g, ln1_b);
    k_router<<<NTOK, 128>>>(Wr, br, Wn, bn, noise);
    k_prefix<<<1, 1>>>();
    k_gemm<<<dim3(32, 16, NE), 256, SMEM_BYTES>>>(2, b1);         // moe1 + gelu
    k_gemm<<<dim3(32, 4, NE), 256, SMEM_BYTES>>>(3, b2);          // moe2 + gate
    k_out<<<NTOK, 256>>>(ln2_g, ln2_b, out);
}